// round 3
// baseline (speedup 1.0000x reference)
#include <cuda_runtime.h>
#include <cstdint>
#include <cstddef>

#define PI_F 3.14159265358979323846f
#define FFT_M 32768
typedef unsigned long long ull;

// ---- static scratch ----
__device__ float  g_h1[64u*64u*8192u];
__device__ float  g_h2[64u*128u*4096u];
__device__ float  g_h3[64u*256u*2048u];
__device__ float2 g_fftA[128u*32768u];
__device__ float2 g_fftB[128u*32768u];
__device__ float2 g_tw[32768];
__device__ float  g_spec[64u*8448u];
__device__ float  g_spectrum[64u*256u];
__device__ float  g_timevec[64u*256u];
__device__ float  g_freqvec[64u*128u];

// ---- packed f32x2 helpers ----
__device__ __forceinline__ ull fma2(ull a, ull b, ull c) {
    ull d; asm("fma.rn.f32x2 %0, %1, %2, %3;" : "=l"(d) : "l"(a), "l"(b), "l"(c)); return d;
}
__device__ __forceinline__ ull pack2(float lo, float hi) {
    ull r; asm("mov.b64 %0, {%1, %2};" : "=l"(r) : "f"(lo), "f"(hi)); return r;
}
__device__ __forceinline__ void unpack2(ull v, float& lo, float& hi) {
    asm("mov.b64 {%0, %1}, %2;" : "=f"(lo), "=f"(hi) : "l"(v));
}

// =============== conv1: 1->64, k=7, +BN+relu+pool2 ===============
__global__ void conv1_kernel(const float* __restrict__ x, const float* __restrict__ w,
                             const float* __restrict__ cb, const float* __restrict__ g,
                             const float* __restrict__ be, const float* __restrict__ m,
                             const float* __restrict__ v)
{
    __shared__ float sx[519];
    int tid = threadIdx.x;                    // 256
    int pb  = blockIdx.x * 256;
    int c   = blockIdx.y;
    int b   = blockIdx.z;
    const float* xb = x + (size_t)b * 16384;
    for (int idx = tid; idx < 519; idx += 256) {
        int t = 2*pb - 3 + idx;
        sx[idx] = (t >= 0 && t < 16384) ? xb[t] : 0.f;
    }
    float wv[7];
    #pragma unroll
    for (int j = 0; j < 7; j++) wv[j] = __ldg(w + c*7 + j);
    float sc = g[c] * rsqrtf(v[c] + 1e-5f);
    float sh = be[c] - m[c]*sc + cb[c]*sc;
    __syncthreads();
    float y0 = 0.f, y1 = 0.f;
    #pragma unroll
    for (int j = 0; j < 7; j++) {
        y0 = fmaf(wv[j], sx[2*tid + j],     y0);
        y1 = fmaf(wv[j], sx[2*tid + 1 + j], y1);
    }
    float r = fmaxf(fmaxf(y0*sc + sh, y1*sc + sh), 0.f);
    g_h1[((size_t)b*64 + c)*8192 + pb + tid] = r;
}

// =============== conv blocks 2/3 with packed f32x2 FMA ===============
// Input tile staged channel-pair interleaved: sIn2[cp*36+u] = (in[2cp][t], in[2cp+1][t]).
// Each thread = one output channel; acc2[q] lanes hold even/odd-channel partials.
template<int CIN, int COUT, int LIN, int WHICH>
__global__ void __launch_bounds__(COUT)
convblock_kernel(const float* __restrict__ w, const float* __restrict__ cb,
                 const float* __restrict__ g, const float* __restrict__ be,
                 const float* __restrict__ m, const float* __restrict__ v)
{
    const float* in = WHICH ? g_h2 : g_h1;
    float* out      = WHICH ? g_h3 : g_h2;
    const int LOUT = LIN / 2;
    const int CP = CIN / 2;
    __shared__ __align__(16) float2 sIn2[CP*36];
    int o  = threadIdx.x;
    int b  = blockIdx.y;
    int pb = blockIdx.x * 16;                 // 16 pooled (32 conv) outputs / block
    int ib = 2*pb - 2;
    const float* inb = in + (size_t)b * CIN * LIN;
    for (int idx = o; idx < CP*36; idx += COUT) {
        int cp = idx / 36, u = idx - cp*36;
        int t = ib + u;
        float e0 = 0.f, e1 = 0.f;
        if (t >= 0 && t < LIN) {
            e0 = inb[(size_t)(2*cp)*LIN + t];
            e1 = inb[(size_t)(2*cp+1)*LIN + t];
        }
        sIn2[idx] = make_float2(e0, e1);
    }
    __syncthreads();

    ull acc2[32];
    #pragma unroll
    for (int q = 0; q < 32; q++) acc2[q] = 0ull;

    for (int cp = 0; cp < CP; cp++) {
        const float* wp = w + ((size_t)o*CIN + 2*cp)*5;
        ull w2[5];
        #pragma unroll
        for (int j = 0; j < 5; j++) w2[j] = pack2(__ldg(wp + j), __ldg(wp + 5 + j));
        const ulonglong2* r2 = (const ulonglong2*)(sIn2 + cp*36);
        ull win[8];
        { ulonglong2 t0 = r2[0], t1 = r2[1];
          win[0]=t0.x; win[1]=t0.y; win[2]=t1.x; win[3]=t1.y; }
        #pragma unroll
        for (int t = 0; t < 8; t++) {
            ulonglong2 t0 = r2[2*t+2], t1 = r2[2*t+3];
            win[4]=t0.x; win[5]=t0.y; win[6]=t1.x; win[7]=t1.y;
            #pragma unroll
            for (int q = 0; q < 4; q++)
                #pragma unroll
                for (int j = 0; j < 5; j++)
                    acc2[4*t + q] = fma2(w2[j], win[q + j], acc2[4*t + q]);
            win[0]=win[4]; win[1]=win[5]; win[2]=win[6]; win[3]=win[7];
        }
    }
    float sc = g[o] * rsqrtf(v[o] + 1e-5f);
    float sh = be[o] - m[o]*sc + cb[o]*sc;
    float r[16];
    #pragma unroll
    for (int p = 0; p < 16; p++) {
        float l0, h0, l1, h1;
        unpack2(acc2[2*p],   l0, h0);
        unpack2(acc2[2*p+1], l1, h1);
        float a0 = fmaxf((l0 + h0)*sc + sh, 0.f);
        float a1 = fmaxf((l1 + h1)*sc + sh, 0.f);
        r[p] = fmaxf(a0, a1);
    }
    float4* op = (float4*)(out + ((size_t)b*COUT + o)*LOUT + pb);
    #pragma unroll
    for (int p = 0; p < 4; p++)
        op[p] = make_float4(r[4*p], r[4*p+1], r[4*p+2], r[4*p+3]);
}

// =============== masked global average over time ===============
__global__ void timepool_kernel(const int* __restrict__ lengths)
{
    int c = blockIdx.x, b = blockIdx.y, tid = threadIdx.x; // 128
    int plen = lengths[b] >> 3; if (plen < 1) plen = 1;
    const float* p = g_h3 + ((size_t)b*256 + c)*2048;
    float s = 0.f;
    for (int t = tid; t < plen; t += 128) s += p[t];
    __shared__ float red[4];
    #pragma unroll
    for (int off = 16; off; off >>= 1) s += __shfl_down_sync(0xffffffffu, s, off);
    if ((tid & 31) == 0) red[tid >> 5] = s;
    __syncthreads();
    if (tid == 0) g_timevec[b*256 + c] = (red[0]+red[1]+red[2]+red[3]) / (float)plen;
}

// =============== FFT: Bluestein, M=32768, radix-4 Stockham ===============
__global__ void fft_twiddle_kernel()
{
    int p = blockIdx.x*blockDim.x + threadIdx.x;  // 0..16383
    int off = 0;
    #pragma unroll
    for (int st = 0; st < 15; st++) {
        int n = FFT_M >> st, mm = n >> 1;
        if (p < mm) {
            float sv, cv; sincosf(-2.f*PI_F*(float)p/(float)n, &sv, &cv);
            g_tw[off + p] = make_float2(cv, sv);
        }
        off += mm;
    }
}

__global__ void fft_build_kernel(const float* __restrict__ x, const int* __restrict__ lengths)
{
    int n = blockIdx.x*blockDim.x + threadIdx.x;  // 0..32767
    int i = blockIdx.y;
    int L = lengths[i];
    int mm = (n <= FFT_M - n) ? n : FFT_M - n;
    float2 a  = make_float2(0.f, 0.f);
    float2 bb = make_float2(0.f, 0.f);
    if (mm < L) {
        unsigned r = ((unsigned)mm * (unsigned)mm) % (unsigned)(2*L);
        float sv, cv; sincosf(PI_F * (float)r / (float)L, &sv, &cv);
        bb = make_float2(cv, sv);                 // chirp b[n]=e^{+i pi n^2/L}
        if (n < L) {
            float xv = x[(size_t)i*16384 + n];
            a = make_float2(xv*cv, -xv*sv);       // x[n]*conj(b[n])
        }
    }
    g_fftA[(size_t)i*FFT_M + n]      = a;
    g_fftA[(size_t)(64+i)*FFT_M + n] = bb;
}

// radix-4 Stockham stage: sShift = 2*stage, twOff = 32768 - (FFT_M >> (2*stage)).
__global__ void fft4_stage_kernel(int sel, int sShift, int twOff)
{
    const float2* __restrict__ src = sel ? g_fftB : g_fftA;
    float2* __restrict__ dst       = sel ? g_fftA : g_fftB;
    int i = blockIdx.x*blockDim.x + threadIdx.x;  // 0..8191
    size_t base = (size_t)blockIdx.y * FFT_M;
    int p = i >> sShift;
    int s = 1 << sShift;
    float2 a = src[base + i];
    float2 b = src[base + i + 8192];
    float2 c = src[base + i + 16384];
    float2 d = src[base + i + 24576];
    float2 w1 = g_tw[twOff + p];
    float2 w2 = g_tw[twOff + 2*p];
    float2 w3 = make_float2(w1.x*w2.x - w1.y*w2.y, w1.x*w2.y + w1.y*w2.x);
    float2 apc = make_float2(a.x + c.x, a.y + c.y);
    float2 amc = make_float2(a.x - c.x, a.y - c.y);
    float2 bpd = make_float2(b.x + d.x, b.y + d.y);
    float2 tbd = make_float2(b.x - d.x, b.y - d.y);
    float2 bmd = make_float2(tbd.y, -tbd.x);      // (b-d)*(-i), forward
    float2 y0 = make_float2(apc.x + bpd.x, apc.y + bpd.y);
    float2 u1 = make_float2(amc.x + bmd.x, amc.y + bmd.y);
    float2 u2 = make_float2(apc.x - bpd.x, apc.y - bpd.y);
    float2 u3 = make_float2(amc.x - bmd.x, amc.y - bmd.y);
    int j = i + 3*p*s;
    dst[base + j]       = y0;
    dst[base + j + s]   = make_float2(fmaf(u1.x,w1.x,-u1.y*w1.y), fmaf(u1.x,w1.y, u1.y*w1.x));
    dst[base + j + 2*s] = make_float2(fmaf(u2.x,w2.x,-u2.y*w2.y), fmaf(u2.x,w2.y, u2.y*w2.x));
    dst[base + j + 3*s] = make_float2(fmaf(u3.x,w3.x,-u3.y*w3.y), fmaf(u3.x,w3.y, u3.y*w3.x));
}

// final radix-2 stage (n=2, s=16384): p==0, twiddle = 1
__global__ void fft2_final_kernel(int sel)
{
    const float2* __restrict__ src = sel ? g_fftB : g_fftA;
    float2* __restrict__ dst       = sel ? g_fftA : g_fftB;
    int i = blockIdx.x*blockDim.x + threadIdx.x;  // 0..16383
    size_t base = (size_t)blockIdx.y * FFT_M;
    float2 a = src[base + i];
    float2 b = src[base + i + 16384];
    dst[base + i]         = make_float2(a.x + b.x, a.y + b.y);
    dst[base + i + 16384] = make_float2(a.x - b.x, a.y - b.y);
}

__global__ void fft_pointwise_kernel()   // C = conj(Ahat*Bhat), A-buffer -> B-buffer
{
    int n = blockIdx.x*blockDim.x + threadIdx.x;
    int i = blockIdx.y;
    float2 A = g_fftA[(size_t)i*FFT_M + n];
    float2 B = g_fftA[(size_t)(64+i)*FFT_M + n];
    g_fftB[(size_t)i*FFT_M + n] =
        make_float2(A.x*B.x - A.y*B.y, -(A.x*B.y + A.y*B.x));
}

__global__ void fft_finalize_kernel(const int* __restrict__ lengths)
{
    int k = blockIdx.x*blockDim.x + threadIdx.x;
    int i = blockIdx.y;
    int K = lengths[i]/2 + 1;
    if (k < K) {
        float2 c = g_fftB[(size_t)i*FFT_M + k];
        g_spec[(size_t)i*8448 + k] = log1pf(sqrtf(c.x*c.x + c.y*c.y) * (1.0f/32768.0f));
    }
}

__global__ void apool_kernel(const int* __restrict__ lengths)
{
    int i = blockIdx.x, j = threadIdx.x;          // 256 bins
    int K = lengths[i]/2 + 1;
    int s0 = (j*K) >> 8;
    int e0 = ((j+1)*K + 255) >> 8;
    const float* sp = g_spec + (size_t)i*8448;
    float s = 0.f;
    for (int t = s0; t < e0; t++) s += sp[t];
    g_spectrum[i*256 + j] = s / (float)(e0 - s0);
}

// =============== small GEMMs ===============
__global__ void freqlin_kernel(const float* __restrict__ fw, const float* __restrict__ fb)
{
    int i = blockIdx.x, h = threadIdx.x;          // 128
    __shared__ float sp[256];
    for (int f = h; f < 256; f += 128) sp[f] = g_spectrum[i*256 + f];
    __syncthreads();
    float acc = fb[h];
    const float* wr = fw + (size_t)h*256;
    for (int f = 0; f < 256; f++) acc = fmaf(sp[f], wr[f], acc);
    g_freqvec[i*128 + h] = fmaxf(acc, 0.f);
}

__global__ void head_kernel(const float* __restrict__ w0, const float* __restrict__ b0,
                            const float* __restrict__ w1, const float* __restrict__ b1,
                            float* __restrict__ out)
{
    int b = blockIdx.x, tid = threadIdx.x;        // 128
    __shared__ float fused[384];
    __shared__ float hid[128];
    for (int j = tid; j < 384; j += 128)
        fused[j] = (j < 256) ? g_timevec[b*256 + j] : g_freqvec[b*128 + (j - 256)];
    __syncthreads();
    float acc = b0[tid];
    const float* wr = w0 + (size_t)tid*384;
    for (int j = 0; j < 384; j++) acc = fmaf(fused[j], wr[j], acc);
    hid[tid] = fmaxf(acc, 0.f);
    __syncthreads();
    int wid = tid >> 5, lane = tid & 31;
    float s = 0.f;
    for (int t = lane; t < 128; t += 32) s += hid[t] * w1[wid*128 + t];
    #pragma unroll
    for (int off = 16; off; off >>= 1) s += __shfl_down_sync(0xffffffffu, s, off);
    if (lane == 0) out[b*4 + wid] = s + b1[wid];
}

// =============== launch ===============
extern "C" void kernel_launch(void* const* d_in, const int* in_sizes, int n_in,
                              void* d_out, int out_size)
{
    const float* x   = (const float*)d_in[0];
    const int*   len = (const int*)  d_in[1];
    const float *cw0 = (const float*)d_in[2],  *cb0 = (const float*)d_in[3];
    const float *g0  = (const float*)d_in[4],  *be0 = (const float*)d_in[5];
    const float *m0  = (const float*)d_in[6],  *v0  = (const float*)d_in[7];
    const float *cw1 = (const float*)d_in[8],  *cb1 = (const float*)d_in[9];
    const float *g1  = (const float*)d_in[10], *be1 = (const float*)d_in[11];
    const float *m1  = (const float*)d_in[12], *v1  = (const float*)d_in[13];
    const float *cw2 = (const float*)d_in[14], *cb2 = (const float*)d_in[15];
    const float *g2  = (const float*)d_in[16], *be2 = (const float*)d_in[17];
    const float *m2  = (const float*)d_in[18], *v2  = (const float*)d_in[19];
    const float *fw  = (const float*)d_in[20], *fb  = (const float*)d_in[21];
    const float *hw0 = (const float*)d_in[22], *hb0 = (const float*)d_in[23];
    const float *hw1 = (const float*)d_in[24], *hb1 = (const float*)d_in[25];
    float* out = (float*)d_out;

    // time branch
    conv1_kernel<<<dim3(32,64,64), 256>>>(x, cw0, cb0, g0, be0, m0, v0);
    convblock_kernel<64,128,8192,0><<<dim3(256,64), 128>>>(cw1, cb1, g1, be1, m1, v1);
    convblock_kernel<128,256,4096,1><<<dim3(128,64), 256>>>(cw2, cb2, g2, be2, m2, v2);
    timepool_kernel<<<dim3(256,64), 128>>>(len);

    // frequency branch
    fft_twiddle_kernel<<<64, 256>>>();
    fft_build_kernel<<<dim3(128,64), 256>>>(x, len);
    // forward FFT: 7 radix-4 stages + final radix-2 (batch 128). Ends in g_fftA.
    int sel = 0;
    for (int st = 0; st < 7; st++) {
        int n = FFT_M >> (2*st);
        fft4_stage_kernel<<<dim3(32,128), 256>>>(sel, 2*st, 32768 - n);
        sel ^= 1;
    }
    fft2_final_kernel<<<dim3(64,128), 256>>>(sel);   // sel=1: B->A
    fft_pointwise_kernel<<<dim3(128,64), 256>>>();   // A -> B (conj product)
    // inverse (forward-of-conjugate): starts reading g_fftB (sel=1). Ends in g_fftB.
    sel = 1;
    for (int st = 0; st < 7; st++) {
        int n = FFT_M >> (2*st);
        fft4_stage_kernel<<<dim3(32,64), 256>>>(sel, 2*st, 32768 - n);
        sel ^= 1;
    }
    fft2_final_kernel<<<dim3(64,64), 256>>>(sel);    // sel=0: A->B
    fft_finalize_kernel<<<dim3(33,64), 256>>>(len);
    apool_kernel<<<64, 256>>>(len);
    freqlin_kernel<<<64, 128>>>(fw, fb);

    // fuse + head
    head_kernel<<<64, 128>>>(hw0, hb0, hw1, hb1, out);
}

// round 6
// speedup vs baseline: 2.1727x; 2.1727x over previous
#include <cuda_runtime.h>
#include <cuda_bf16.h>
#include <cstdint>
#include <cstddef>

#define PI_F 3.14159265358979323846f
#define FFT_M 32768

// ---- static scratch ----
__device__ float  g_h1[64u*64u*8192u];
__device__ float  g_h2[64u*128u*4096u];
__device__ float  g_h3[64u*256u*2048u];
__device__ float2 g_fftA[128u*32768u];
__device__ float2 g_fftB[128u*32768u];
__device__ float2 g_tw[32768];
__device__ float  g_spec[64u*8448u];
__device__ float  g_spectrum[64u*256u];
__device__ float  g_timevec[64u*256u];
__device__ float  g_freqvec[64u*128u];
// prepped split-bf16 weights: [mt][chunk][split][m=128][k=48]
__device__ __nv_bfloat16 g_wA2[1u*8u*2u*128u*48u];
__device__ __nv_bfloat16 g_wA3[2u*16u*2u*128u*48u];

// ---- mma helpers ----
__device__ __forceinline__ uint32_t smem_u32(const void* p) {
    uint32_t a; asm("{ .reg .u64 t; cvta.to.shared.u64 t, %1; cvt.u32.u64 %0, t; }" : "=r"(a) : "l"(p));
    return a;
}
__device__ __forceinline__ void mma16816(float* c, const uint32_t* a, uint32_t b0, uint32_t b1) {
    asm volatile("mma.sync.aligned.m16n8k16.row.col.f32.bf16.bf16.f32 "
        "{%0,%1,%2,%3}, {%4,%5,%6,%7}, {%8,%9}, {%0,%1,%2,%3};"
        : "+f"(c[0]), "+f"(c[1]), "+f"(c[2]), "+f"(c[3])
        : "r"(a[0]), "r"(a[1]), "r"(a[2]), "r"(a[3]), "r"(b0), "r"(b1));
}
__device__ __forceinline__ void ldmA(uint32_t* a, uint32_t addr) {
    asm volatile("ldmatrix.sync.aligned.m8n8.x4.shared.b16 {%0,%1,%2,%3}, [%4];"
        : "=r"(a[0]), "=r"(a[1]), "=r"(a[2]), "=r"(a[3]) : "r"(addr));
}

// ---- weight prep: fp32 [COUT][CIN][5] -> [mt][ch][split][m 128][k 48] bf16, j=5 zeroed ----
template<int CIN, int MT>
__global__ void prep_w_kernel(const float* __restrict__ w, __nv_bfloat16* __restrict__ dst)
{
    const int NCH = CIN / 8;
    int total = MT * NCH * 2 * 128 * 48;
    int idx = blockIdx.x * 256 + threadIdx.x;
    if (idx >= total) return;
    int kl = idx % 48;
    int m  = (idx / 48) % 128;
    int s  = (idx / (48 * 128)) % 2;
    int ch = (idx / (48 * 128 * 2)) % NCH;
    int mt = idx / (48 * 128 * 2 * NCH);
    int cl = kl / 6, j = kl - 6 * cl;
    float wv = 0.f;
    if (j < 5) wv = w[(((size_t)(mt * 128 + m)) * CIN + ch * 8 + cl) * 5 + j];
    __nv_bfloat16 hi = __float2bfloat16(wv);
    dst[idx] = s ? __float2bfloat16(wv - __bfloat162float(hi)) : hi;
}

// ---- conv blocks 2/3 via mma.sync bf16 (3-pass split), +BN+relu+maxpool2 fused ----
// CTA tile: M=128 out-ch x N=128 conv positions (-> 64 pooled). 8 warps (4 M x 2 N).
template<int CIN, int COUT, int LIN, int WHICH>
__global__ void __launch_bounds__(256)
convmma_kernel(const float* __restrict__ cb, const float* __restrict__ g,
               const float* __restrict__ be, const float* __restrict__ bm,
               const float* __restrict__ bv)
{
    const int NCH  = CIN / 8;                    // 8-channel chunks
    const int LOUT = LIN / 2;
    const float* in = WHICH ? g_h2 : g_h1;
    float* out      = WHICH ? g_h3 : g_h2;
    const __nv_bfloat16* wA = WHICH ? g_wA3 : g_wA2;

    __shared__ __align__(16) __nv_bfloat16 sA[2 * 128 * 48];       // [split][m][k48]
    __shared__ __align__(16) __nv_bfloat16 sB[2 * 2 * 8 * 136];    // [split][parity][c8][136]

    int tid = threadIdx.x, wid = tid >> 5, lane = tid & 31;
    int pt = blockIdx.x, mt = blockIdx.y, b = blockIdx.z;
    int warp_m = wid & 3, warp_n = wid >> 2;
    int lrow = lane >> 2;                         // 0..7
    int tb = pt * 128 - 2;
    const float* inb = in + (size_t)b * CIN * LIN;
    uint32_t sA_addr = smem_u32(sA);

    float acc[2][8][4];
    #pragma unroll
    for (int i = 0; i < 2; i++)
        #pragma unroll
        for (int n = 0; n < 8; n++)
            #pragma unroll
            for (int q = 0; q < 4; q++) acc[i][n][q] = 0.f;

    for (int ch = 0; ch < NCH; ch++) {
        __syncthreads();
        // stage A chunk (both splits contiguous): 24576 B = 1536 uint4
        {
            const uint4* asrc = (const uint4*)(wA + (size_t)(mt * NCH + ch) * 2 * 128 * 48);
            uint4* adst = (uint4*)sA;
            #pragma unroll 6
            for (int i = tid; i < 1536; i += 256) adst[i] = asrc[i];
        }
        // stage B chunk: 8 channels x 136 positions, split + dual parity copies
        for (int i = tid; i < 8 * 136; i += 256) {
            int c = i / 136, u = i - c * 136;
            int t = tb + u;
            float v = (t >= 0 && t < LIN) ? inb[(size_t)(ch * 8 + c) * LIN + t] : 0.f;
            __nv_bfloat16 hi = __float2bfloat16(v);
            __nv_bfloat16 lo = __float2bfloat16(v - __bfloat162float(hi));
            sB[(0 * 2 + 0) * 8 * 136 + c * 136 + u] = hi;       // even, hi
            sB[(1 * 2 + 0) * 8 * 136 + c * 136 + u] = lo;       // even, lo
            if (u > 0) {
                sB[(0 * 2 + 1) * 8 * 136 + c * 136 + u - 1] = hi;   // odd (shift-1), hi
                sB[(1 * 2 + 1) * 8 * 136 + c * 136 + u - 1] = lo;   // odd, lo
            }
        }
        if (tid < 16) {   // zero last elem of odd copies
            int s = tid >> 3, c = tid & 7;
            sB[(s * 2 + 1) * 8 * 136 + c * 136 + 135] = __float2bfloat16(0.f);
        }
        __syncthreads();

        #pragma unroll
        for (int pass = 0; pass < 3; pass++) {     // hi*hi, hi*lo, lo*hi
            int sa  = (pass == 2) ? 1 : 0;
            int sbs = (pass == 1) ? 1 : 0;
            uint32_t Abase = sA_addr + (uint32_t)(sa * 128 * 48 * 2);
            #pragma unroll
            for (int ks = 0; ks < 3; ks++) {
                uint32_t a0[4], a1[4];
                uint32_t aoff = (uint32_t)(((warp_m * 32 + (lane & 7) + ((lane >> 3) & 1) * 8) * 48
                                           + (lane >> 4) * 8 + ks * 16) * 2);
                ldmA(a0, Abase + aoff);
                ldmA(a1, Abase + aoff + 16 * 48 * 2);

                int k0 = ks * 16 + (lane & 3) * 2;
                int c0 = k0 / 6, j0 = k0 - 6 * c0;
                int k1 = k0 + 8;
                int c1 = k1 / 6, j1 = k1 - 6 * c1;
                int t0 = warp_n * 64 + lrow + j0;
                int t1 = warp_n * 64 + lrow + j1;
                const uint32_t* Bw = (const uint32_t*)sB;
                const uint32_t* p0 = Bw + ((sbs * 2 + (t0 & 1)) * 8 + c0) * 68 + (t0 >> 1);
                const uint32_t* p1 = Bw + ((sbs * 2 + (t1 & 1)) * 8 + c1) * 68 + (t1 >> 1);
                #pragma unroll
                for (int nt = 0; nt < 8; nt++) {
                    uint32_t b0 = p0[nt * 4];
                    uint32_t b1 = p1[nt * 4];
                    mma16816(acc[0][nt], a0, b0, b1);
                    mma16816(acc[1][nt], a1, b0, b1);
                }
            }
        }
    }

    // epilogue: BN + relu + maxpool2 (c0/c1 and c2/c3 are adjacent conv positions)
    int pcol = warp_n * 32 + (lane & 3);
    #pragma unroll
    for (int mtile = 0; mtile < 2; mtile++) {
        #pragma unroll
        for (int h = 0; h < 2; h++) {
            int mg = mt * 128 + warp_m * 32 + mtile * 16 + h * 8 + lrow;
            float scv = g[mg] * rsqrtf(bv[mg] + 1e-5f);
            float shv = be[mg] - bm[mg] * scv + cb[mg] * scv;
            float* orow = out + ((size_t)b * COUT + mg) * LOUT + pt * 64;
            #pragma unroll
            for (int nt = 0; nt < 8; nt++) {
                float v0 = acc[mtile][nt][2 * h]     * scv + shv;
                float v1 = acc[mtile][nt][2 * h + 1] * scv + shv;
                orow[pcol + nt * 4] = fmaxf(fmaxf(v0, v1), 0.f);
            }
        }
    }
}

// =============== conv1: 1->64, k=7, +BN+relu+pool2 (scalar) ===============
__global__ void conv1_kernel(const float* __restrict__ x, const float* __restrict__ w,
                             const float* __restrict__ cb, const float* __restrict__ g,
                             const float* __restrict__ be, const float* __restrict__ m,
                             const float* __restrict__ v)
{
    __shared__ float sx[519];
    int tid = threadIdx.x;
    int pb  = blockIdx.x * 256;
    int c   = blockIdx.y;
    int b   = blockIdx.z;
    const float* xb = x + (size_t)b * 16384;
    for (int idx = tid; idx < 519; idx += 256) {
        int t = 2*pb - 3 + idx;
        sx[idx] = (t >= 0 && t < 16384) ? xb[t] : 0.f;
    }
    float wv[7];
    #pragma unroll
    for (int j = 0; j < 7; j++) wv[j] = __ldg(w + c*7 + j);
    float sc = g[c] * rsqrtf(v[c] + 1e-5f);
    float sh = be[c] - m[c]*sc + cb[c]*sc;
    __syncthreads();
    float y0 = 0.f, y1 = 0.f;
    #pragma unroll
    for (int j = 0; j < 7; j++) {
        y0 = fmaf(wv[j], sx[2*tid + j],     y0);
        y1 = fmaf(wv[j], sx[2*tid + 1 + j], y1);
    }
    float r = fmaxf(fmaxf(y0*sc + sh, y1*sc + sh), 0.f);
    g_h1[((size_t)b*64 + c)*8192 + pb + tid] = r;
}

// =============== masked global average over time ===============
__global__ void timepool_kernel(const int* __restrict__ lengths)
{
    int c = blockIdx.x, b = blockIdx.y, tid = threadIdx.x;
    int plen = lengths[b] >> 3; if (plen < 1) plen = 1;
    const float* p = g_h3 + ((size_t)b*256 + c)*2048;
    float s = 0.f;
    for (int t = tid; t < plen; t += 128) s += p[t];
    __shared__ float red[4];
    #pragma unroll
    for (int off = 16; off; off >>= 1) s += __shfl_down_sync(0xffffffffu, s, off);
    if ((tid & 31) == 0) red[tid >> 5] = s;
    __syncthreads();
    if (tid == 0) g_timevec[b*256 + c] = (red[0]+red[1]+red[2]+red[3]) / (float)plen;
}

// =============== FFT: Bluestein, M=32768, radix-4 Stockham ===============
__global__ void fft_twiddle_kernel()
{
    int p = blockIdx.x*blockDim.x + threadIdx.x;
    int off = 0;
    #pragma unroll
    for (int st = 0; st < 15; st++) {
        int n = FFT_M >> st, mm = n >> 1;
        if (p < mm) {
            float sv, cv; sincosf(-2.f*PI_F*(float)p/(float)n, &sv, &cv);
            g_tw[off + p] = make_float2(cv, sv);
        }
        off += mm;
    }
}

__global__ void fft_build_kernel(const float* __restrict__ x, const int* __restrict__ lengths)
{
    int n = blockIdx.x*blockDim.x + threadIdx.x;
    int i = blockIdx.y;
    int L = lengths[i];
    int mm = (n <= FFT_M - n) ? n : FFT_M - n;
    float2 a  = make_float2(0.f, 0.f);
    float2 bb = make_float2(0.f, 0.f);
    if (mm < L) {
        unsigned r = ((unsigned)mm * (unsigned)mm) % (unsigned)(2*L);
        float sv, cv; sincosf(PI_F * (float)r / (float)L, &sv, &cv);
        bb = make_float2(cv, sv);
        if (n < L) {
            float xv = x[(size_t)i*16384 + n];
            a = make_float2(xv*cv, -xv*sv);
        }
    }
    g_fftA[(size_t)i*FFT_M + n]      = a;
    g_fftA[(size_t)(64+i)*FFT_M + n] = bb;
}

__global__ void fft4_stage_kernel(int sel, int sShift, int twOff)
{
    const float2* __restrict__ src = sel ? g_fftB : g_fftA;
    float2* __restrict__ dst       = sel ? g_fftA : g_fftB;
    int i = blockIdx.x*blockDim.x + threadIdx.x;
    size_t base = (size_t)blockIdx.y * FFT_M;
    int p = i >> sShift;
    int s = 1 << sShift;
    float2 a = src[base + i];
    float2 b = src[base + i + 8192];
    float2 c = src[base + i + 16384];
    float2 d = src[base + i + 24576];
    float2 w1 = g_tw[twOff + p];
    float2 w2 = g_tw[twOff + 2*p];
    float2 w3 = make_float2(w1.x*w2.x - w1.y*w2.y, w1.x*w2.y + w1.y*w2.x);
    float2 apc = make_float2(a.x + c.x, a.y + c.y);
    float2 amc = make_float2(a.x - c.x, a.y - c.y);
    float2 bpd = make_float2(b.x + d.x, b.y + d.y);
    float2 tbd = make_float2(b.x - d.x, b.y - d.y);
    float2 bmd = make_float2(tbd.y, -tbd.x);
    float2 y0 = make_float2(apc.x + bpd.x, apc.y + bpd.y);
    float2 u1 = make_float2(amc.x + bmd.x, amc.y + bmd.y);
    float2 u2 = make_float2(apc.x - bpd.x, apc.y - bpd.y);
    float2 u3 = make_float2(amc.x - bmd.x, amc.y - bmd.y);
    int j = i + 3*p*s;
    dst[base + j]       = y0;
    dst[base + j + s]   = make_float2(fmaf(u1.x,w1.x,-u1.y*w1.y), fmaf(u1.x,w1.y, u1.y*w1.x));
    dst[base + j + 2*s] = make_float2(fmaf(u2.x,w2.x,-u2.y*w2.y), fmaf(u2.x,w2.y, u2.y*w2.x));
    dst[base + j + 3*s] = make_float2(fmaf(u3.x,w3.x,-u3.y*w3.y), fmaf(u3.x,w3.y, u3.y*w3.x));
}

__global__ void fft2_final_kernel(int sel)
{
    const float2* __restrict__ src = sel ? g_fftB : g_fftA;
    float2* __restrict__ dst       = sel ? g_fftA : g_fftB;
    int i = blockIdx.x*blockDim.x + threadIdx.x;
    size_t base = (size_t)blockIdx.y * FFT_M;
    float2 a = src[base + i];
    float2 b = src[base + i + 16384];
    dst[base + i]         = make_float2(a.x + b.x, a.y + b.y);
    dst[base + i + 16384] = make_float2(a.x - b.x, a.y - b.y);
}

__global__ void fft_pointwise_kernel()
{
    int n = blockIdx.x*blockDim.x + threadIdx.x;
    int i = blockIdx.y;
    float2 A = g_fftA[(size_t)i*FFT_M + n];
    float2 B = g_fftA[(size_t)(64+i)*FFT_M + n];
    g_fftB[(size_t)i*FFT_M + n] =
        make_float2(A.x*B.x - A.y*B.y, -(A.x*B.y + A.y*B.x));
}

__global__ void fft_finalize_kernel(const int* __restrict__ lengths)
{
    int k = blockIdx.x*blockDim.x + threadIdx.x;
    int i = blockIdx.y;
    int K = lengths[i]/2 + 1;
    if (k < K) {
        float2 c = g_fftB[(size_t)i*FFT_M + k];
        g_spec[(size_t)i*8448 + k] = log1pf(sqrtf(c.x*c.x + c.y*c.y) * (1.0f/32768.0f));
    }
}

__global__ void apool_kernel(const int* __restrict__ lengths)
{
    int i = blockIdx.x, j = threadIdx.x;
    int K = lengths[i]/2 + 1;
    int s0 = (j*K) >> 8;
    int e0 = ((j+1)*K + 255) >> 8;
    const float* sp = g_spec + (size_t)i*8448;
    float s = 0.f;
    for (int t = s0; t < e0; t++) s += sp[t];
    g_spectrum[i*256 + j] = s / (float)(e0 - s0);
}

// =============== small GEMMs ===============
__global__ void freqlin_kernel(const float* __restrict__ fw, const float* __restrict__ fb)
{
    int i = blockIdx.x, h = threadIdx.x;
    __shared__ float sp[256];
    for (int f = h; f < 256; f += 128) sp[f] = g_spectrum[i*256 + f];
    __syncthreads();
    float acc = fb[h];
    const float* wr = fw + (size_t)h*256;
    for (int f = 0; f < 256; f++) acc = fmaf(sp[f], wr[f], acc);
    g_freqvec[i*128 + h] = fmaxf(acc, 0.f);
}

__global__ void head_kernel(const float* __restrict__ w0, const float* __restrict__ b0,
                            const float* __restrict__ w1, const float* __restrict__ b1,
                            float* __restrict__ out)
{
    int b = blockIdx.x, tid = threadIdx.x;
    __shared__ float fused[384];
    __shared__ float hid[128];
    for (int j = tid; j < 384; j += 128)
        fused[j] = (j < 256) ? g_timevec[b*256 + j] : g_freqvec[b*128 + (j - 256)];
    __syncthreads();
    float acc = b0[tid];
    const float* wr = w0 + (size_t)tid*384;
    for (int j = 0; j < 384; j++) acc = fmaf(fused[j], wr[j], acc);
    hid[tid] = fmaxf(acc, 0.f);
    __syncthreads();
    int wid = tid >> 5, lane = tid & 31;
    float s = 0.f;
    for (int t = lane; t < 128; t += 32) s += hid[t] * w1[wid*128 + t];
    #pragma unroll
    for (int off = 16; off; off >>= 1) s += __shfl_down_sync(0xffffffffu, s, off);
    if (lane == 0) out[b*4 + wid] = s + b1[wid];
}

// =============== launch ===============
extern "C" void kernel_launch(void* const* d_in, const int* in_sizes, int n_in,
                              void* d_out, int out_size)
{
    const float* x   = (const float*)d_in[0];
    const int*   len = (const int*)  d_in[1];
    const float *cw0 = (const float*)d_in[2],  *cb0 = (const float*)d_in[3];
    const float *g0  = (const float*)d_in[4],  *be0 = (const float*)d_in[5];
    const float *m0  = (const float*)d_in[6],  *v0  = (const float*)d_in[7];
    const float *cw1 = (const float*)d_in[8],  *cb1 = (const float*)d_in[9];
    const float *g1  = (const float*)d_in[10], *be1 = (const float*)d_in[11];
    const float *m1  = (const float*)d_in[12], *v1  = (const float*)d_in[13];
    const float *cw2 = (const float*)d_in[14], *cb2 = (const float*)d_in[15];
    const float *g2  = (const float*)d_in[16], *be2 = (const float*)d_in[17];
    const float *m2  = (const float*)d_in[18], *v2  = (const float*)d_in[19];
    const float *fw  = (const float*)d_in[20], *fb  = (const float*)d_in[21];
    const float *hw0 = (const float*)d_in[22], *hb0 = (const float*)d_in[23];
    const float *hw1 = (const float*)d_in[24], *hb1 = (const float*)d_in[25];
    float* out = (float*)d_out;

    __nv_bfloat16 *wa2, *wa3;
    cudaGetSymbolAddress((void**)&wa2, g_wA2);
    cudaGetSymbolAddress((void**)&wa3, g_wA3);
    prep_w_kernel<64, 1><<<(1*8*2*128*48  + 255)/256, 256>>>(cw1, wa2);
    prep_w_kernel<128,2><<<(2*16*2*128*48 + 255)/256, 256>>>(cw2, wa3);

    // time branch
    conv1_kernel<<<dim3(32,64,64), 256>>>(x, cw0, cb0, g0, be0, m0, v0);
    convmma_kernel<64,128,8192,0><<<dim3(64,1,64), 256>>>(cb1, g1, be1, m1, v1);
    convmma_kernel<128,256,4096,1><<<dim3(32,2,64), 256>>>(cb2, g2, be2, m2, v2);
    timepool_kernel<<<dim3(256,64), 128>>>(len);

    // frequency branch
    fft_twiddle_kernel<<<64, 256>>>();
    fft_build_kernel<<<dim3(128,64), 256>>>(x, len);
    int sel = 0;
    for (int st = 0; st < 7; st++) {
        int n = FFT_M >> (2*st);
        fft4_stage_kernel<<<dim3(32,128), 256>>>(sel, 2*st, 32768 - n);
        sel ^= 1;
    }
    fft2_final_kernel<<<dim3(64,128), 256>>>(sel);
    fft_pointwise_kernel<<<dim3(128,64), 256>>>();
    sel = 1;
    for (int st = 0; st < 7; st++) {
        int n = FFT_M >> (2*st);
        fft4_stage_kernel<<<dim3(32,64), 256>>>(sel, 2*st, 32768 - n);
        sel ^= 1;
    }
    fft2_final_kernel<<<dim3(64,64), 256>>>(sel);
    fft_finalize_kernel<<<dim3(33,64), 256>>>(len);
    apool_kernel<<<64, 256>>>(len);
    freqlin_kernel<<<64, 128>>>(fw, fb);

    head_kernel<<<64, 128>>>(hw0, hb0, hw1, hb1, out);
}

// round 7
// speedup vs baseline: 3.8225x; 1.7593x over previous
#include <cuda_runtime.h>
#include <cuda_fp16.h>
#include <cstdint>
#include <cstddef>

#define PI_F 3.14159265358979323846f
#define FFT_M 32768

// ---- static scratch ----
__device__ float  g_h1[64u*64u*8192u];
__device__ float  g_h2[64u*128u*4096u];
__device__ float  g_h3[64u*256u*2048u];
__device__ float2 g_fftA[128u*32768u];
__device__ float2 g_fftB[128u*32768u];
__device__ float2 g_tw[32768];
__device__ float  g_spec[64u*8448u];
__device__ float  g_spectrum[64u*256u];
__device__ float  g_timevec[64u*256u];
__device__ float  g_freqvec[64u*128u];
// prepped fp16 weights (hi only): [mt][chunk][m=128][k=48]
__device__ __half g_wA2[1u*8u*128u*48u];
__device__ __half g_wA3[2u*16u*128u*48u];

// ---- helpers ----
__device__ __forceinline__ uint32_t smem_u32(const void* p) {
    uint32_t a; asm("{ .reg .u64 t; cvta.to.shared.u64 t, %1; cvt.u32.u64 %0, t; }" : "=r"(a) : "l"(p));
    return a;
}
__device__ __forceinline__ void mma16816(float* c, const uint32_t* a, uint32_t b0, uint32_t b1) {
    asm volatile("mma.sync.aligned.m16n8k16.row.col.f32.f16.f16.f32 "
        "{%0,%1,%2,%3}, {%4,%5,%6,%7}, {%8,%9}, {%0,%1,%2,%3};"
        : "+f"(c[0]), "+f"(c[1]), "+f"(c[2]), "+f"(c[3])
        : "r"(a[0]), "r"(a[1]), "r"(a[2]), "r"(a[3]), "r"(b0), "r"(b1));
}
__device__ __forceinline__ void ldmA(uint32_t* a, uint32_t addr) {
    asm volatile("ldmatrix.sync.aligned.m8n8.x4.shared.b16 {%0,%1,%2,%3}, [%4];"
        : "=r"(a[0]), "=r"(a[1]), "=r"(a[2]), "=r"(a[3]) : "r"(addr));
}
#define CP_ASYNC16(dst, src) asm volatile("cp.async.cg.shared.global [%0], [%1], 16;" :: "r"(dst), "l"(src))
#define CP_ASYNC4Z(dst, src, sz) asm volatile("cp.async.ca.shared.global [%0], [%1], 4, %2;" :: "r"(dst), "l"(src), "r"(sz))
#define CP_COMMIT() asm volatile("cp.async.commit_group;")
#define CP_WAIT0()  asm volatile("cp.async.wait_group 0;" ::: "memory")

// ---- weight prep: fp32 [COUT][CIN][5] -> [mt][ch][m 128][k 48] fp16, tap j=5 zeroed ----
template<int CIN, int MT>
__global__ void prep_w_kernel(const float* __restrict__ w, __half* __restrict__ dst)
{
    const int NCH = CIN / 8;
    int total = MT * NCH * 128 * 48;
    int idx = blockIdx.x * 256 + threadIdx.x;
    if (idx >= total) return;
    int kl = idx % 48;
    int m  = (idx / 48) % 128;
    int ch = (idx / (48 * 128)) % NCH;
    int mt = idx / (48 * 128 * NCH);
    int cl = kl / 6, j = kl - 6 * cl;
    float wv = (j < 5) ? w[(((size_t)(mt * 128 + m)) * CIN + ch * 8 + cl) * 5 + j] : 0.f;
    dst[idx] = __float2half_rn(wv);
}

// ---- conv blocks 2/3: fp16 mma, 2-pass B-split, cp.async double-buffered pipeline ----
// CTA: M=128 out-ch x N=128 conv positions (->64 pooled). 16 warps (4 M x 4 N).
// smem (dynamic): A[2]@0 (12288 ea), Braw[2]@24576 (4352 ea), sB[2]@33280 (8704 ea) = 50688 B
template<int CIN, int COUT, int LIN, int WHICH>
__global__ void __launch_bounds__(512)
convmma_kernel(const float* __restrict__ cb, const float* __restrict__ g,
               const float* __restrict__ be, const float* __restrict__ bm,
               const float* __restrict__ bv)
{
    const int NCH  = CIN / 8;
    const int LOUT = LIN / 2;
    const float* in = WHICH ? g_h2 : g_h1;
    float* out      = WHICH ? g_h3 : g_h2;
    const __half* wA = WHICH ? g_wA3 : g_wA2;

    extern __shared__ __align__(16) char smem[];
    uint32_t sbase = smem_u32(smem);
    int tid = threadIdx.x, wid = tid >> 5, lane = tid & 31;
    int pt = blockIdx.x, mt = blockIdx.y, b = blockIdx.z;
    int warp_m = wid & 3, warp_n = wid >> 2;          // 4 x 4
    int lrow = lane >> 2;
    int tb = pt * 128 - 2;
    const float* inb = in + (size_t)b * CIN * LIN;

    // per-thread invariant index math
    uint32_t aoffb = (uint32_t)(((warp_m * 32 + (lane & 7) + ((lane >> 3) & 1) * 8) * 48
                                + (lane >> 4) * 8) * 2);
    int b0idx[3], b1idx[3];
    #pragma unroll
    for (int ks = 0; ks < 3; ks++) {
        int k0 = ks * 16 + (lane & 3) * 2;
        int c0 = k0 / 6, j0 = k0 - 6 * c0;
        int k1 = k0 + 8;
        int c1 = k1 / 6, j1 = k1 - 6 * c1;
        int t0 = warp_n * 32 + lrow + j0;
        int t1 = warp_n * 32 + lrow + j1;
        b0idx[ks] = ((t0 & 1) * 8 + c0) * 68 + (t0 >> 1);
        b1idx[ks] = ((t1 & 1) * 8 + c1) * 68 + (t1 >> 1);
    }

    float acc[2][4][4];
    #pragma unroll
    for (int i = 0; i < 2; i++)
        #pragma unroll
        for (int n = 0; n < 4; n++)
            #pragma unroll
            for (int q = 0; q < 4; q++) acc[i][n][q] = 0.f;

    // zero the never-written tail of the odd-parity B copies (both buffers)
    if (tid < 32) {
        int buf = tid >> 4, sp = (tid >> 3) & 1, c = tid & 7;
        __half* p = (__half*)(smem + 33280 + buf * 8704);
        p[((sp * 2 + 1) * 8 + c) * 136 + 135] = __float2half(0.f);
    }

    // ---- staging helpers (inline) ----
    #define STAGE_A(CH) do {                                                            \
        const uint4* _as = (const uint4*)(wA + (size_t)(mt * NCH + (CH)) * 128 * 48);   \
        uint32_t _ad = sbase + (((CH) & 1) ? 12288u : 0u);                              \
        for (int _i = tid; _i < 768; _i += 512) CP_ASYNC16(_ad + _i * 16, _as + _i);    \
    } while (0)
    #define STAGE_B(CH) do {                                                            \
        uint32_t _bd = sbase + 24576u + ((CH) & 1) * 4352u;                             \
        const float* _bb = inb + (size_t)(CH) * 8 * LIN;                                \
        for (int _i = tid; _i < 1088; _i += 512) {                                      \
            int _c = _i / 136, _u = _i - _c * 136;                                      \
            int _t = tb + _u;                                                           \
            int _ok = (_t >= 0 && _t < LIN);                                            \
            const float* _sp = _bb + (size_t)_c * LIN + (_ok ? _t : 0);                 \
            CP_ASYNC4Z(_bd + _i * 4, _sp, _ok ? 4 : 0);                                 \
        }                                                                               \
    } while (0)

    STAGE_A(0); STAGE_B(0); CP_COMMIT();
    CP_WAIT0();
    __syncthreads();

    for (int ch = 0; ch < NCH; ch++) {
        int cur = ch & 1;
        // convert raw floats -> fp16 hi/lo with dual parity copies
        {
            const float* braw = (const float*)(smem + 24576 + cur * 4352);
            __half* sBh = (__half*)(smem + 33280 + cur * 8704);
            for (int i = tid; i < 1088; i += 512) {
                int c = i / 136, u = i - c * 136;
                float v = braw[i];
                __half hi = __float2half_rn(v);
                __half lo = __float2half_rn(v - __half2float(hi));
                sBh[(0 * 8 + c) * 136 + u] = hi;              // split0, even
                sBh[(2 * 8 + c) * 136 + u] = lo;              // split1, even
                if (u) {
                    sBh[(1 * 8 + c) * 136 + u - 1] = hi;      // split0, odd
                    sBh[(3 * 8 + c) * 136 + u - 1] = lo;      // split1, odd
                }
            }
        }
        __syncthreads();
        if (ch + 1 < NCH) { STAGE_A(ch + 1); STAGE_B(ch + 1); CP_COMMIT(); }

        // compute on buffers [cur]
        {
            uint32_t Aaddr = sbase + (cur ? 12288u : 0u) + aoffb;
            uint32_t afr[3][2][4];
            #pragma unroll
            for (int ks = 0; ks < 3; ks++) {
                ldmA(afr[ks][0], Aaddr + ks * 32);
                ldmA(afr[ks][1], Aaddr + ks * 32 + 1536);
            }
            const uint32_t* Bw = (const uint32_t*)(smem + 33280 + cur * 8704);
            #pragma unroll
            for (int pass = 0; pass < 2; pass++) {
                const uint32_t* Bp = Bw + pass * 1088;
                #pragma unroll
                for (int ks = 0; ks < 3; ks++) {
                    const uint32_t* p0 = Bp + b0idx[ks];
                    const uint32_t* p1 = Bp + b1idx[ks];
                    #pragma unroll
                    for (int nt = 0; nt < 4; nt++) {
                        uint32_t bb0 = p0[nt * 4];
                        uint32_t bb1 = p1[nt * 4];
                        mma16816(acc[0][nt], afr[ks][0], bb0, bb1);
                        mma16816(acc[1][nt], afr[ks][1], bb0, bb1);
                    }
                }
            }
        }
        if (ch + 1 < NCH) CP_WAIT0();
        __syncthreads();
    }
    #undef STAGE_A
    #undef STAGE_B

    // epilogue: BN + relu + maxpool2 (c0/c1, c2/c3 are adjacent conv positions)
    int pcol = warp_n * 16 + (lane & 3);
    #pragma unroll
    for (int mtile = 0; mtile < 2; mtile++) {
        #pragma unroll
        for (int h = 0; h < 2; h++) {
            int mg = mt * 128 + warp_m * 32 + mtile * 16 + h * 8 + lrow;
            float scv = g[mg] * rsqrtf(bv[mg] + 1e-5f);
            float shv = be[mg] - bm[mg] * scv + cb[mg] * scv;
            float* orow = out + ((size_t)b * COUT + mg) * LOUT + pt * 64;
            #pragma unroll
            for (int nt = 0; nt < 4; nt++) {
                float v0 = acc[mtile][nt][2 * h]     * scv + shv;
                float v1 = acc[mtile][nt][2 * h + 1] * scv + shv;
                orow[pcol + nt * 4] = fmaxf(fmaxf(v0, v1), 0.f);
            }
        }
    }
}

// =============== conv1: 1->64, k=7, +BN+relu+pool2 (8 channels per thread) ===============
__global__ void conv1_kernel(const float* __restrict__ x, const float* __restrict__ w,
                             const float* __restrict__ cb, const float* __restrict__ g,
                             const float* __restrict__ be, const float* __restrict__ m,
                             const float* __restrict__ v)
{
    __shared__ float sx[519];
    __shared__ float swv[56];
    __shared__ float sbn[16];
    int tid = threadIdx.x;                 // 256
    int pb  = blockIdx.x * 256;
    int c8  = blockIdx.y * 8;
    int b   = blockIdx.z;
    const float* xb = x + (size_t)b * 16384;
    for (int idx = tid; idx < 519; idx += 256) {
        int t = 2*pb - 3 + idx;
        sx[idx] = (t >= 0 && t < 16384) ? xb[t] : 0.f;
    }
    if (tid < 56) swv[tid] = w[c8*7 + tid];
    if (tid < 8) {
        int c = c8 + tid;
        float sc = g[c] * rsqrtf(v[c] + 1e-5f);
        sbn[tid] = sc;
        sbn[8 + tid] = be[c] - m[c]*sc + cb[c]*sc;
    }
    __syncthreads();
    float xv[8];
    #pragma unroll
    for (int j = 0; j < 8; j++) xv[j] = sx[2*tid + j];
    #pragma unroll
    for (int c = 0; c < 8; c++) {
        float y0 = 0.f, y1 = 0.f;
        #pragma unroll
        for (int j = 0; j < 7; j++) {
            float wc = swv[c*7 + j];
            y0 = fmaf(wc, xv[j],   y0);
            y1 = fmaf(wc, xv[j+1], y1);
        }
        float sc = sbn[c], sh = sbn[8 + c];
        g_h1[((size_t)(b*64 + c8 + c))*8192 + pb + tid] =
            fmaxf(fmaxf(y0*sc + sh, y1*sc + sh), 0.f);
    }
}

// =============== masked global average over time ===============
__global__ void timepool_kernel(const int* __restrict__ lengths)
{
    int c = blockIdx.x, b = blockIdx.y, tid = threadIdx.x;
    int plen = lengths[b] >> 3; if (plen < 1) plen = 1;
    const float* p = g_h3 + ((size_t)b*256 + c)*2048;
    float s = 0.f;
    for (int t = tid; t < plen; t += 128) s += p[t];
    __shared__ float red[4];
    #pragma unroll
    for (int off = 16; off; off >>= 1) s += __shfl_down_sync(0xffffffffu, s, off);
    if ((tid & 31) == 0) red[tid >> 5] = s;
    __syncthreads();
    if (tid == 0) g_timevec[b*256 + c] = (red[0]+red[1]+red[2]+red[3]) / (float)plen;
}

// =============== FFT: Bluestein, M=32768, radix-4 Stockham ===============
__global__ void fft_twiddle_kernel()
{
    int p = blockIdx.x*blockDim.x + threadIdx.x;
    int off = 0;
    #pragma unroll
    for (int st = 0; st < 15; st++) {
        int n = FFT_M >> st, mm = n >> 1;
        if (p < mm) {
            float sv, cv; sincosf(-2.f*PI_F*(float)p/(float)n, &sv, &cv);
            g_tw[off + p] = make_float2(cv, sv);
        }
        off += mm;
    }
}

__global__ void fft_build_kernel(const float* __restrict__ x, const int* __restrict__ lengths)
{
    int n = blockIdx.x*blockDim.x + threadIdx.x;
    int i = blockIdx.y;
    int L = lengths[i];
    int mm = (n <= FFT_M - n) ? n : FFT_M - n;
    float2 a  = make_float2(0.f, 0.f);
    float2 bb = make_float2(0.f, 0.f);
    if (mm < L) {
        unsigned r = ((unsigned)mm * (unsigned)mm) % (unsigned)(2*L);
        float sv, cv; sincosf(PI_F * (float)r / (float)L, &sv, &cv);
        bb = make_float2(cv, sv);
        if (n < L) {
            float xv = x[(size_t)i*16384 + n];
            a = make_float2(xv*cv, -xv*sv);
        }
    }
    g_fftA[(size_t)i*FFT_M + n]      = a;
    g_fftA[(size_t)(64+i)*FFT_M + n] = bb;
}

__global__ void fft4_stage_kernel(int sel, int sShift, int twOff)
{
    const float2* __restrict__ src = sel ? g_fftB : g_fftA;
    float2* __restrict__ dst       = sel ? g_fftA : g_fftB;
    int i = blockIdx.x*blockDim.x + threadIdx.x;
    size_t base = (size_t)blockIdx.y * FFT_M;
    int p = i >> sShift;
    int s = 1 << sShift;
    float2 a = src[base + i];
    float2 b = src[base + i + 8192];
    float2 c = src[base + i + 16384];
    float2 d = src[base + i + 24576];
    float2 w1 = g_tw[twOff + p];
    float2 w2 = g_tw[twOff + 2*p];
    float2 w3 = make_float2(w1.x*w2.x - w1.y*w2.y, w1.x*w2.y + w1.y*w2.x);
    float2 apc = make_float2(a.x + c.x, a.y + c.y);
    float2 amc = make_float2(a.x - c.x, a.y - c.y);
    float2 bpd = make_float2(b.x + d.x, b.y + d.y);
    float2 tbd = make_float2(b.x - d.x, b.y - d.y);
    float2 bmd = make_float2(tbd.y, -tbd.x);
    float2 y0 = make_float2(apc.x + bpd.x, apc.y + bpd.y);
    float2 u1 = make_float2(amc.x + bmd.x, amc.y + bmd.y);
    float2 u2 = make_float2(apc.x - bpd.x, apc.y - bpd.y);
    float2 u3 = make_float2(amc.x - bmd.x, amc.y - bmd.y);
    int j = i + 3*p*s;
    dst[base + j]       = y0;
    dst[base + j + s]   = make_float2(fmaf(u1.x,w1.x,-u1.y*w1.y), fmaf(u1.x,w1.y, u1.y*w1.x));
    dst[base + j + 2*s] = make_float2(fmaf(u2.x,w2.x,-u2.y*w2.y), fmaf(u2.x,w2.y, u2.y*w2.x));
    dst[base + j + 3*s] = make_float2(fmaf(u3.x,w3.x,-u3.y*w3.y), fmaf(u3.x,w3.y, u3.y*w3.x));
}

__global__ void fft2_final_kernel(int sel)
{
    const float2* __restrict__ src = sel ? g_fftB : g_fftA;
    float2* __restrict__ dst       = sel ? g_fftA : g_fftB;
    int i = blockIdx.x*blockDim.x + threadIdx.x;
    size_t base = (size_t)blockIdx.y * FFT_M;
    float2 a = src[base + i];
    float2 b = src[base + i + 16384];
    dst[base + i]         = make_float2(a.x + b.x, a.y + b.y);
    dst[base + i + 16384] = make_float2(a.x - b.x, a.y - b.y);
}

__global__ void fft_pointwise_kernel()
{
    int n = blockIdx.x*blockDim.x + threadIdx.x;
    int i = blockIdx.y;
    float2 A = g_fftA[(size_t)i*FFT_M + n];
    float2 B = g_fftA[(size_t)(64+i)*FFT_M + n];
    g_fftB[(size_t)i*FFT_M + n] =
        make_float2(A.x*B.x - A.y*B.y, -(A.x*B.y + A.y*B.x));
}

__global__ void fft_finalize_kernel(const int* __restrict__ lengths)
{
    int k = blockIdx.x*blockDim.x + threadIdx.x;
    int i = blockIdx.y;
    int K = lengths[i]/2 + 1;
    if (k < K) {
        float2 c = g_fftB[(size_t)i*FFT_M + k];
        g_spec[(size_t)i*8448 + k] = log1pf(sqrtf(c.x*c.x + c.y*c.y) * (1.0f/32768.0f));
    }
}

__global__ void apool_kernel(const int* __restrict__ lengths)
{
    int i = blockIdx.x, j = threadIdx.x;
    int K = lengths[i]/2 + 1;
    int s0 = (j*K) >> 8;
    int e0 = ((j+1)*K + 255) >> 8;
    const float* sp = g_spec + (size_t)i*8448;
    float s = 0.f;
    for (int t = s0; t < e0; t++) s += sp[t];
    g_spectrum[i*256 + j] = s / (float)(e0 - s0);
}

// =============== small GEMMs ===============
__global__ void freqlin_kernel(const float* __restrict__ fw, const float* __restrict__ fb)
{
    int i = blockIdx.x, h = threadIdx.x;
    __shared__ float sp[256];
    for (int f = h; f < 256; f += 128) sp[f] = g_spectrum[i*256 + f];
    __syncthreads();
    float acc = fb[h];
    const float* wr = fw + (size_t)h*256;
    for (int f = 0; f < 256; f++) acc = fmaf(sp[f], wr[f], acc);
    g_freqvec[i*128 + h] = fmaxf(acc, 0.f);
}

__global__ void head_kernel(const float* __restrict__ w0, const float* __restrict__ b0,
                            const float* __restrict__ w1, const float* __restrict__ b1,
                            float* __restrict__ out)
{
    int b = blockIdx.x, tid = threadIdx.x;
    __shared__ float fused[384];
    __shared__ float hid[128];
    for (int j = tid; j < 384; j += 128)
        fused[j] = (j < 256) ? g_timevec[b*256 + j] : g_freqvec[b*128 + (j - 256)];
    __syncthreads();
    float acc = b0[tid];
    const float* wr = w0 + (size_t)tid*384;
    for (int j = 0; j < 384; j++) acc = fmaf(fused[j], wr[j], acc);
    hid[tid] = fmaxf(acc, 0.f);
    __syncthreads();
    int wid = tid >> 5, lane = tid & 31;
    float s = 0.f;
    for (int t = lane; t < 128; t += 32) s += hid[t] * w1[wid*128 + t];
    #pragma unroll
    for (int off = 16; off; off >>= 1) s += __shfl_down_sync(0xffffffffu, s, off);
    if (lane == 0) out[b*4 + wid] = s + b1[wid];
}

// =============== launch ===============
extern "C" void kernel_launch(void* const* d_in, const int* in_sizes, int n_in,
                              void* d_out, int out_size)
{
    const float* x   = (const float*)d_in[0];
    const int*   len = (const int*)  d_in[1];
    const float *cw0 = (const float*)d_in[2],  *cb0 = (const float*)d_in[3];
    const float *g0  = (const float*)d_in[4],  *be0 = (const float*)d_in[5];
    const float *m0  = (const float*)d_in[6],  *v0  = (const float*)d_in[7];
    const float *cw1 = (const float*)d_in[8],  *cb1 = (const float*)d_in[9];
    const float *g1  = (const float*)d_in[10], *be1 = (const float*)d_in[11];
    const float *m1  = (const float*)d_in[12], *v1  = (const float*)d_in[13];
    const float *cw2 = (const float*)d_in[14], *cb2 = (const float*)d_in[15];
    const float *g2  = (const float*)d_in[16], *be2 = (const float*)d_in[17];
    const float *m2  = (const float*)d_in[18], *v2  = (const float*)d_in[19];
    const float *fw  = (const float*)d_in[20], *fb  = (const float*)d_in[21];
    const float *hw0 = (const float*)d_in[22], *hb0 = (const float*)d_in[23];
    const float *hw1 = (const float*)d_in[24], *hb1 = (const float*)d_in[25];
    float* out = (float*)d_out;

    const int SMEM_CONV = 50688;
    cudaFuncSetAttribute(convmma_kernel<64,128,8192,0>, cudaFuncAttributeMaxDynamicSharedMemorySize, SMEM_CONV);
    cudaFuncSetAttribute(convmma_kernel<128,256,4096,1>, cudaFuncAttributeMaxDynamicSharedMemorySize, SMEM_CONV);

    __half *wa2, *wa3;
    cudaGetSymbolAddress((void**)&wa2, g_wA2);
    cudaGetSymbolAddress((void**)&wa3, g_wA3);
    prep_w_kernel<64, 1><<<(1*8*128*48  + 255)/256, 256>>>(cw1, wa2);
    prep_w_kernel<128,2><<<(2*16*128*48 + 255)/256, 256>>>(cw2, wa3);

    // time branch
    conv1_kernel<<<dim3(32,8,64), 256>>>(x, cw0, cb0, g0, be0, m0, v0);
    convmma_kernel<64,128,8192,0><<<dim3(64,1,64), 512, SMEM_CONV>>>(cb1, g1, be1, m1, v1);
    convmma_kernel<128,256,4096,1><<<dim3(32,2,64), 512, SMEM_CONV>>>(cb2, g2, be2, m2, v2);
    timepool_kernel<<<dim3(256,64), 128>>>(len);

    // frequency branch
    fft_twiddle_kernel<<<64, 256>>>();
    fft_build_kernel<<<dim3(128,64), 256>>>(x, len);
    int sel = 0;
    for (int st = 0; st < 7; st++) {
        int n = FFT_M >> (2*st);
        fft4_stage_kernel<<<dim3(32,128), 256>>>(sel, 2*st, 32768 - n);
        sel ^= 1;
    }
    fft2_final_kernel<<<dim3(64,128), 256>>>(sel);
    fft_pointwise_kernel<<<dim3(128,64), 256>>>();
    sel = 1;
    for (int st = 0; st < 7; st++) {
        int n = FFT_M >> (2*st);
        fft4_stage_kernel<<<dim3(32,64), 256>>>(sel, 2*st, 32768 - n);
        sel ^= 1;
    }
    fft2_final_kernel<<<dim3(64,64), 256>>>(sel);
    fft_finalize_kernel<<<dim3(33,64), 256>>>(len);
    apool_kernel<<<64, 256>>>(len);
    freqlin_kernel<<<64, 128>>>(fw, fb);

    head_kernel<<<64, 128>>>(hw0, hb0, hw1, hb1, out);
}

// round 8
// speedup vs baseline: 5.3320x; 1.3949x over previous
#include <cuda_runtime.h>
#include <cuda_fp16.h>
#include <cstdint>
#include <cstddef>

#define PI_F 3.14159265358979323846f
#define FFT_M 32768

// ---- static scratch ----
__device__ float  g_h1[64u*64u*8192u];
__device__ float  g_h2[64u*128u*4096u];
__device__ float  g_h3[64u*256u*2048u];
__device__ float2 g_fftA[128u*32768u];
__device__ float2 g_fftB[128u*32768u];
__device__ float2 g_tw[32768];
__device__ float  g_spec[64u*8448u];
__device__ float  g_spectrum[64u*256u];
__device__ float  g_timevec[64u*256u];
__device__ float  g_freqvec[64u*128u];
// prepped fp16 weights (hi only): [mt][chunk][m=128][k=48]
__device__ __half g_wA2[1u*8u*128u*48u];
__device__ __half g_wA3[2u*16u*128u*48u];

// ---- helpers ----
__device__ __forceinline__ uint32_t smem_u32(const void* p) {
    uint32_t a; asm("{ .reg .u64 t; cvta.to.shared.u64 t, %1; cvt.u32.u64 %0, t; }" : "=r"(a) : "l"(p));
    return a;
}
__device__ __forceinline__ void mma16816(float* c, const uint32_t* a, uint32_t b0, uint32_t b1) {
    asm volatile("mma.sync.aligned.m16n8k16.row.col.f32.f16.f16.f32 "
        "{%0,%1,%2,%3}, {%4,%5,%6,%7}, {%8,%9}, {%0,%1,%2,%3};"
        : "+f"(c[0]), "+f"(c[1]), "+f"(c[2]), "+f"(c[3])
        : "r"(a[0]), "r"(a[1]), "r"(a[2]), "r"(a[3]), "r"(b0), "r"(b1));
}
__device__ __forceinline__ void ldmA(uint32_t* a, uint32_t addr) {
    asm volatile("ldmatrix.sync.aligned.m8n8.x4.shared.b16 {%0,%1,%2,%3}, [%4];"
        : "=r"(a[0]), "=r"(a[1]), "=r"(a[2]), "=r"(a[3]) : "r"(addr));
}
#define CP_ASYNC16(dst, src) asm volatile("cp.async.cg.shared.global [%0], [%1], 16;" :: "r"(dst), "l"(src))
#define CP_ASYNC4Z(dst, src, sz) asm volatile("cp.async.ca.shared.global [%0], [%1], 4, %2;" :: "r"(dst), "l"(src), "r"(sz))
#define CP_COMMIT() asm volatile("cp.async.commit_group;")
#define CP_WAIT0()  asm volatile("cp.async.wait_group 0;" ::: "memory")

// ---- weight prep: fp32 [COUT][CIN][5] -> [mt][ch][m 128][k 48] fp16, tap j=5 zeroed ----
template<int CIN, int MT>
__global__ void prep_w_kernel(const float* __restrict__ w, __half* __restrict__ dst)
{
    const int NCH = CIN / 8;
    int total = MT * NCH * 128 * 48;
    int idx = blockIdx.x * 256 + threadIdx.x;
    if (idx >= total) return;
    int kl = idx % 48;
    int m  = (idx / 48) % 128;
    int ch = (idx / (48 * 128)) % NCH;
    int mt = idx / (48 * 128 * NCH);
    int cl = kl / 6, j = kl - 6 * cl;
    float wv = (j < 5) ? w[(((size_t)(mt * 128 + m)) * CIN + ch * 8 + cl) * 5 + j] : 0.f;
    dst[idx] = __float2half_rn(wv);
}

// ---- conv blocks 2/3: fp16 mma, 2-pass B-split, cp.async pipeline ----
// CTA: M=128 x N=256 conv positions (->128 pooled). 16 warps as 2(M) x 8(N); warp = M64 x N32.
// smem: A[2]@0 (12288 ea), Braw[2]@24576 (8448 ea), sB[2]@41472 (16896 ea) = 75264 B
template<int CIN, int COUT, int LIN, int WHICH>
__global__ void __launch_bounds__(512)
convmma_kernel(const float* __restrict__ cb, const float* __restrict__ g,
               const float* __restrict__ be, const float* __restrict__ bm,
               const float* __restrict__ bv)
{
    const int NCH  = CIN / 8;
    const int LOUT = LIN / 2;
    const float* in = WHICH ? g_h2 : g_h1;
    float* out      = WHICH ? g_h3 : g_h2;
    const __half* wA = WHICH ? g_wA3 : g_wA2;

    extern __shared__ __align__(16) char smem[];
    uint32_t sbase = smem_u32(smem);
    int tid = threadIdx.x, wid = tid >> 5, lane = tid & 31;
    int pt = blockIdx.x, mt = blockIdx.y, b = blockIdx.z;
    int warp_m = wid & 1, warp_n = wid >> 1;          // 2 x 8
    int lrow = lane >> 2;
    int tb = pt * 256 - 2;
    const float* inb = in + (size_t)b * CIN * LIN;

    // invariant index math
    uint32_t aoff[4];
    #pragma unroll
    for (int m2 = 0; m2 < 4; m2++)
        aoff[m2] = (uint32_t)(((warp_m * 64 + m2 * 16 + (lane & 7) + ((lane >> 3) & 1) * 8) * 48
                              + (lane >> 4) * 8) * 2);
    int b0idx[3], b1idx[3];
    #pragma unroll
    for (int ks = 0; ks < 3; ks++) {
        int k0 = ks * 16 + (lane & 3) * 2;
        int c0 = k0 / 6, j0 = k0 - 6 * c0;
        int k1 = k0 + 8;
        int c1 = k1 / 6, j1 = k1 - 6 * c1;
        int t0 = warp_n * 32 + lrow + j0;
        int t1 = warp_n * 32 + lrow + j1;
        b0idx[ks] = ((t0 & 1) * 8 + c0) * 132 + (t0 >> 1);
        b1idx[ks] = ((t1 & 1) * 8 + c1) * 132 + (t1 >> 1);
    }

    float acc[4][4][4];
    #pragma unroll
    for (int i = 0; i < 4; i++)
        #pragma unroll
        for (int n = 0; n < 4; n++)
            #pragma unroll
            for (int q = 0; q < 4; q++) acc[i][n][q] = 0.f;

    // zero never-written tail of odd-parity copies (both buffers, both splits)
    if (tid < 32) {
        int buf = tid >> 4, sp = (tid >> 3) & 1, c = tid & 7;
        __half* p = (__half*)(smem + 41472 + buf * 16896);
        p[((sp * 2 + 1) * 8 + c) * 264 + 263] = __float2half(0.f);
    }

    #define STAGE_A(CH) do {                                                            \
        const uint4* _as = (const uint4*)(wA + (size_t)(mt * NCH + (CH)) * 128 * 48);   \
        uint32_t _ad = sbase + (((CH) & 1) ? 12288u : 0u);                              \
        for (int _i = tid; _i < 768; _i += 512) CP_ASYNC16(_ad + _i * 16, _as + _i);    \
    } while (0)
    #define STAGE_B(CH) do {                                                            \
        uint32_t _bd = sbase + 24576u + ((CH) & 1) * 8448u;                             \
        const float* _bb = inb + (size_t)(CH) * 8 * LIN;                                \
        for (int _i = tid; _i < 2112; _i += 512) {                                      \
            int _c = _i / 264, _u = _i - _c * 264;                                      \
            int _t = tb + _u;                                                           \
            int _ok = (_t >= 0 && _t < LIN);                                            \
            const float* _sp = _bb + (size_t)_c * LIN + (_ok ? _t : 0);                 \
            CP_ASYNC4Z(_bd + _i * 4, _sp, _ok ? 4 : 0);                                 \
        }                                                                               \
    } while (0)

    STAGE_A(0); STAGE_B(0); CP_COMMIT();
    CP_WAIT0();
    __syncthreads();

    for (int ch = 0; ch < NCH; ch++) {
        int cur = ch & 1;
        // convert raw floats -> fp16 hi/lo with dual parity copies
        {
            const float* braw = (const float*)(smem + 24576 + cur * 8448);
            __half* sBh = (__half*)(smem + 41472 + cur * 16896);
            for (int i = tid; i < 2112; i += 512) {
                int c = i / 264, u = i - c * 264;
                float v = braw[i];
                __half hi = __float2half_rn(v);
                __half lo = __float2half_rn(v - __half2float(hi));
                sBh[(0 * 8 + c) * 264 + u] = hi;              // split0, even
                sBh[(2 * 8 + c) * 264 + u] = lo;              // split1, even
                if (u) {
                    sBh[(1 * 8 + c) * 264 + u - 1] = hi;      // split0, odd
                    sBh[(3 * 8 + c) * 264 + u - 1] = lo;      // split1, odd
                }
            }
        }
        __syncthreads();
        if (ch + 1 < NCH) { STAGE_A(ch + 1); STAGE_B(ch + 1); CP_COMMIT(); }

        // compute on buffers [cur]
        {
            uint32_t Aaddr = sbase + (cur ? 12288u : 0u);
            const uint32_t* Bw = (const uint32_t*)(smem + 41472 + cur * 16896);
            #pragma unroll
            for (int ks = 0; ks < 3; ks++) {
                uint32_t afr[4][4];
                #pragma unroll
                for (int m2 = 0; m2 < 4; m2++) ldmA(afr[m2], Aaddr + aoff[m2] + ks * 32);
                #pragma unroll
                for (int pass = 0; pass < 2; pass++) {
                    const uint32_t* p0 = Bw + pass * 2112 + b0idx[ks];
                    const uint32_t* p1 = Bw + pass * 2112 + b1idx[ks];
                    #pragma unroll
                    for (int nt = 0; nt < 4; nt++) {
                        uint32_t bb0 = p0[nt * 4];
                        uint32_t bb1 = p1[nt * 4];
                        #pragma unroll
                        for (int m2 = 0; m2 < 4; m2++)
                            mma16816(acc[m2][nt], afr[m2], bb0, bb1);
                    }
                }
            }
        }
        if (ch + 1 < NCH) CP_WAIT0();
        __syncthreads();
    }
    #undef STAGE_A
    #undef STAGE_B

    // epilogue: BN + relu + maxpool2 (c0/c1, c2/c3 adjacent conv positions)
    int pcol = warp_n * 16 + (lane & 3);
    #pragma unroll
    for (int m2 = 0; m2 < 4; m2++) {
        #pragma unroll
        for (int h = 0; h < 2; h++) {
            int mg = mt * 128 + warp_m * 64 + m2 * 16 + h * 8 + lrow;
            float scv = g[mg] * rsqrtf(bv[mg] + 1e-5f);
            float shv = be[mg] - bm[mg] * scv + cb[mg] * scv;
            float* orow = out + ((size_t)b * COUT + mg) * LOUT + pt * 128;
            #pragma unroll
            for (int nt = 0; nt < 4; nt++) {
                float v0 = acc[m2][nt][2 * h]     * scv + shv;
                float v1 = acc[m2][nt][2 * h + 1] * scv + shv;
                orow[pcol + nt * 4] = fmaxf(fmaxf(v0, v1), 0.f);
            }
        }
    }
}

// =============== conv1: 1->64, k=7, +BN+relu+pool2 (8 channels per thread) ===============
__global__ void conv1_kernel(const float* __restrict__ x, const float* __restrict__ w,
                             const float* __restrict__ cb, const float* __restrict__ g,
                             const float* __restrict__ be, const float* __restrict__ m,
                             const float* __restrict__ v)
{
    __shared__ float sx[519];
    __shared__ float swv[56];
    __shared__ float sbn[16];
    int tid = threadIdx.x;                 // 256
    int pb  = blockIdx.x * 256;
    int c8  = blockIdx.y * 8;
    int b   = blockIdx.z;
    const float* xb = x + (size_t)b * 16384;
    for (int idx = tid; idx < 519; idx += 256) {
        int t = 2*pb - 3 + idx;
        sx[idx] = (t >= 0 && t < 16384) ? xb[t] : 0.f;
    }
    if (tid < 56) swv[tid] = w[c8*7 + tid];
    if (tid < 8) {
        int c = c8 + tid;
        float sc = g[c] * rsqrtf(v[c] + 1e-5f);
        sbn[tid] = sc;
        sbn[8 + tid] = be[c] - m[c]*sc + cb[c]*sc;
    }
    __syncthreads();
    float xv[8];
    #pragma unroll
    for (int j = 0; j < 8; j++) xv[j] = sx[2*tid + j];
    #pragma unroll
    for (int c = 0; c < 8; c++) {
        float y0 = 0.f, y1 = 0.f;
        #pragma unroll
        for (int j = 0; j < 7; j++) {
            float wc = swv[c*7 + j];
            y0 = fmaf(wc, xv[j],   y0);
            y1 = fmaf(wc, xv[j+1], y1);
        }
        float sc = sbn[c], sh = sbn[8 + c];
        g_h1[((size_t)(b*64 + c8 + c))*8192 + pb + tid] =
            fmaxf(fmaxf(y0*sc + sh, y1*sc + sh), 0.f);
    }
}

// =============== masked global average over time ===============
__global__ void timepool_kernel(const int* __restrict__ lengths)
{
    int c = blockIdx.x, b = blockIdx.y, tid = threadIdx.x;
    int plen = lengths[b] >> 3; if (plen < 1) plen = 1;
    const float* p = g_h3 + ((size_t)b*256 + c)*2048;
    float s = 0.f;
    for (int t = tid; t < plen; t += 128) s += p[t];
    __shared__ float red[4];
    #pragma unroll
    for (int off = 16; off; off >>= 1) s += __shfl_down_sync(0xffffffffu, s, off);
    if ((tid & 31) == 0) red[tid >> 5] = s;
    __syncthreads();
    if (tid == 0) g_timevec[b*256 + c] = (red[0]+red[1]+red[2]+red[3]) / (float)plen;
}

// =============== FFT: Bluestein, M=32768, radix-4 Stockham + fused tails ===============
__global__ void fft_twiddle_kernel()
{
    int p = blockIdx.x*blockDim.x + threadIdx.x;
    int off = 0;
    #pragma unroll
    for (int st = 0; st < 15; st++) {
        int n = FFT_M >> st, mm = n >> 1;
        if (p < mm) {
            float sv, cv; sincosf(-2.f*PI_F*(float)p/(float)n, &sv, &cv);
            g_tw[off + p] = make_float2(cv, sv);
        }
        off += mm;
    }
}

__global__ void fft_build_kernel(const float* __restrict__ x, const int* __restrict__ lengths)
{
    int n = blockIdx.x*blockDim.x + threadIdx.x;
    int i = blockIdx.y;
    int L = lengths[i];
    int mm = (n <= FFT_M - n) ? n : FFT_M - n;
    float2 a  = make_float2(0.f, 0.f);
    float2 bb = make_float2(0.f, 0.f);
    if (mm < L) {
        unsigned r = ((unsigned)mm * (unsigned)mm) % (unsigned)(2*L);
        float sv, cv; sincosf(PI_F * (float)r / (float)L, &sv, &cv);
        bb = make_float2(cv, sv);
        if (n < L) {
            float xv = x[(size_t)i*16384 + n];
            a = make_float2(xv*cv, -xv*sv);
        }
    }
    g_fftA[(size_t)i*FFT_M + n]      = a;
    g_fftA[(size_t)(64+i)*FFT_M + n] = bb;
}

__global__ void fft4_stage_kernel(int sel, int sShift, int twOff)
{
    const float2* __restrict__ src = sel ? g_fftB : g_fftA;
    float2* __restrict__ dst       = sel ? g_fftA : g_fftB;
    int i = blockIdx.x*blockDim.x + threadIdx.x;
    size_t base = (size_t)blockIdx.y * FFT_M;
    int p = i >> sShift;
    int s = 1 << sShift;
    float2 a = src[base + i];
    float2 b = src[base + i + 8192];
    float2 c = src[base + i + 16384];
    float2 d = src[base + i + 24576];
    float2 w1 = g_tw[twOff + p];
    float2 w2 = g_tw[twOff + 2*p];
    float2 w3 = make_float2(w1.x*w2.x - w1.y*w2.y, w1.x*w2.y + w1.y*w2.x);
    float2 apc = make_float2(a.x + c.x, a.y + c.y);
    float2 amc = make_float2(a.x - c.x, a.y - c.y);
    float2 bpd = make_float2(b.x + d.x, b.y + d.y);
    float2 tbd = make_float2(b.x - d.x, b.y - d.y);
    float2 bmd = make_float2(tbd.y, -tbd.x);
    float2 y0 = make_float2(apc.x + bpd.x, apc.y + bpd.y);
    float2 u1 = make_float2(amc.x + bmd.x, amc.y + bmd.y);
    float2 u2 = make_float2(apc.x - bpd.x, apc.y - bpd.y);
    float2 u3 = make_float2(amc.x - bmd.x, amc.y - bmd.y);
    int j = i + 3*p*s;
    dst[base + j]       = y0;
    dst[base + j + s]   = make_float2(fmaf(u1.x,w1.x,-u1.y*w1.y), fmaf(u1.x,w1.y, u1.y*w1.x));
    dst[base + j + 2*s] = make_float2(fmaf(u2.x,w2.x,-u2.y*w2.y), fmaf(u2.x,w2.y, u2.y*w2.x));
    dst[base + j + 3*s] = make_float2(fmaf(u3.x,w3.x,-u3.y*w3.y), fmaf(u3.x,w3.y, u3.y*w3.x));
}

// forward final radix-2 fused with conj pointwise product: reads g_fftB, writes g_fftA (data arrays)
__global__ void fft2_pointwise_kernel()
{
    int i = blockIdx.x*blockDim.x + threadIdx.x;  // 0..16383
    int arr = blockIdx.y;                          // 0..63
    const float2* d  = g_fftB + (size_t)arr * FFT_M;
    const float2* cc = g_fftB + (size_t)(64 + arr) * FFT_M;
    float2 a = d[i],  b = d[i + 16384];
    float2 ac = cc[i], bc = cc[i + 16384];
    float2 d0 = make_float2(a.x + b.x, a.y + b.y);
    float2 d1 = make_float2(a.x - b.x, a.y - b.y);
    float2 c0 = make_float2(ac.x + bc.x, ac.y + bc.y);
    float2 c1 = make_float2(ac.x - bc.x, ac.y - bc.y);
    float2* o = g_fftA + (size_t)arr * FFT_M;
    o[i]         = make_float2(d0.x*c0.x - d0.y*c0.y, -(d0.x*c0.y + d0.y*c0.x));
    o[i + 16384] = make_float2(d1.x*c1.x - d1.y*c1.y, -(d1.x*c1.y + d1.y*c1.x));
}

// inverse final radix-2 fused with magnitude/log1p: reads g_fftB, writes g_spec only (k<=8192 needed)
__global__ void fft2_finalize_kernel(const int* __restrict__ lengths)
{
    int i = blockIdx.x*blockDim.x + threadIdx.x;  // 0..8447
    int arr = blockIdx.y;
    int K = lengths[arr] / 2 + 1;
    if (i >= K) return;
    const float2* d = g_fftB + (size_t)arr * FFT_M;
    float2 a = d[i], b = d[i + 16384];
    float2 s = make_float2(a.x + b.x, a.y + b.y);
    g_spec[(size_t)arr * 8448 + i] = log1pf(sqrtf(s.x*s.x + s.y*s.y) * (1.0f/32768.0f));
}

__global__ void apool_kernel(const int* __restrict__ lengths)
{
    int i = blockIdx.x, j = threadIdx.x;
    int K = lengths[i]/2 + 1;
    int s0 = (j*K) >> 8;
    int e0 = ((j+1)*K + 255) >> 8;
    const float* sp = g_spec + (size_t)i*8448;
    float s = 0.f;
    for (int t = s0; t < e0; t++) s += sp[t];
    g_spectrum[i*256 + j] = s / (float)(e0 - s0);
}

// =============== small GEMMs ===============
__global__ void freqlin_kernel(const float* __restrict__ fw, const float* __restrict__ fb)
{
    int i = blockIdx.x, h = threadIdx.x;
    __shared__ float sp[256];
    for (int f = h; f < 256; f += 128) sp[f] = g_spectrum[i*256 + f];
    __syncthreads();
    float acc = fb[h];
    const float* wr = fw + (size_t)h*256;
    for (int f = 0; f < 256; f++) acc = fmaf(sp[f], wr[f], acc);
    g_freqvec[i*128 + h] = fmaxf(acc, 0.f);
}

__global__ void head_kernel(const float* __restrict__ w0, const float* __restrict__ b0,
                            const float* __restrict__ w1, const float* __restrict__ b1,
                            float* __restrict__ out)
{
    int b = blockIdx.x, tid = threadIdx.x;
    __shared__ float fused[384];
    __shared__ float hid[128];
    for (int j = tid; j < 384; j += 128)
        fused[j] = (j < 256) ? g_timevec[b*256 + j] : g_freqvec[b*128 + (j - 256)];
    __syncthreads();
    float acc = b0[tid];
    const float* wr = w0 + (size_t)tid*384;
    for (int j = 0; j < 384; j++) acc = fmaf(fused[j], wr[j], acc);
    hid[tid] = fmaxf(acc, 0.f);
    __syncthreads();
    int wid = tid >> 5, lane = tid & 31;
    float s = 0.f;
    for (int t = lane; t < 128; t += 32) s += hid[t] * w1[wid*128 + t];
    #pragma unroll
    for (int off = 16; off; off >>= 1) s += __shfl_down_sync(0xffffffffu, s, off);
    if (lane == 0) out[b*4 + wid] = s + b1[wid];
}

// =============== launch ===============
extern "C" void kernel_launch(void* const* d_in, const int* in_sizes, int n_in,
                              void* d_out, int out_size)
{
    const float* x   = (const float*)d_in[0];
    const int*   len = (const int*)  d_in[1];
    const float *cw0 = (const float*)d_in[2],  *cb0 = (const float*)d_in[3];
    const float *g0  = (const float*)d_in[4],  *be0 = (const float*)d_in[5];
    const float *m0  = (const float*)d_in[6],  *v0  = (const float*)d_in[7];
    const float *cw1 = (const float*)d_in[8],  *cb1 = (const float*)d_in[9];
    const float *g1  = (const float*)d_in[10], *be1 = (const float*)d_in[11];
    const float *m1  = (const float*)d_in[12], *v1  = (const float*)d_in[13];
    const float *cw2 = (const float*)d_in[14], *cb2 = (const float*)d_in[15];
    const float *g2  = (const float*)d_in[16], *be2 = (const float*)d_in[17];
    const float *m2  = (const float*)d_in[18], *v2  = (const float*)d_in[19];
    const float *fw  = (const float*)d_in[20], *fb  = (const float*)d_in[21];
    const float *hw0 = (const float*)d_in[22], *hb0 = (const float*)d_in[23];
    const float *hw1 = (const float*)d_in[24], *hb1 = (const float*)d_in[25];
    float* out = (float*)d_out;

    const int SMEM_CONV = 75264;
    cudaFuncSetAttribute(convmma_kernel<64,128,8192,0>, cudaFuncAttributeMaxDynamicSharedMemorySize, SMEM_CONV);
    cudaFuncSetAttribute(convmma_kernel<128,256,4096,1>, cudaFuncAttributeMaxDynamicSharedMemorySize, SMEM_CONV);

    __half *wa2, *wa3;
    cudaGetSymbolAddress((void**)&wa2, g_wA2);
    cudaGetSymbolAddress((void**)&wa3, g_wA3);
    prep_w_kernel<64, 1><<<(1*8*128*48  + 255)/256, 256>>>(cw1, wa2);
    prep_w_kernel<128,2><<<(2*16*128*48 + 255)/256, 256>>>(cw2, wa3);

    // time branch
    conv1_kernel<<<dim3(32,8,64), 256>>>(x, cw0, cb0, g0, be0, m0, v0);
    convmma_kernel<64,128,8192,0><<<dim3(32,1,64), 512, SMEM_CONV>>>(cb1, g1, be1, m1, v1);
    convmma_kernel<128,256,4096,1><<<dim3(16,2,64), 512, SMEM_CONV>>>(cb2, g2, be2, m2, v2);
    timepool_kernel<<<dim3(256,64), 128>>>(len);

    // frequency branch
    fft_twiddle_kernel<<<64, 256>>>();
    fft_build_kernel<<<dim3(128,64), 256>>>(x, len);
    int sel = 0;
    for (int st = 0; st < 7; st++) {                  // forward: 7 radix-4 stages (batch 128)
        int n = FFT_M >> (2*st);
        fft4_stage_kernel<<<dim3(32,128), 256>>>(sel, 2*st, 32768 - n);
        sel ^= 1;
    }                                                  // data now in g_fftB
    fft2_pointwise_kernel<<<dim3(64,64), 256>>>();     // fused final radix-2 + conj product -> g_fftA
    sel = 0;
    for (int st = 0; st < 7; st++) {                  // inverse: 7 radix-4 stages (batch 64)
        int n = FFT_M >> (2*st);
        fft4_stage_kernel<<<dim3(32,64), 256>>>(sel, 2*st, 32768 - n);
        sel ^= 1;
    }                                                  // data now in g_fftB
    fft2_finalize_kernel<<<dim3(33,64), 256>>>(len);   // fused final radix-2 + |.| + log1p -> g_spec
    apool_kernel<<<64, 256>>>(len);
    freqlin_kernel<<<64, 128>>>(fw, fb);

    head_kernel<<<64, 128>>>(hw0, hb0, hw1, hb1, out);
}

// round 10
// speedup vs baseline: 6.6584x; 1.2488x over previous
#include <cuda_runtime.h>
#include <cuda_fp16.h>
#include <cstdint>
#include <cstddef>

#define PI_F 3.14159265358979323846f
#define FFT_M 32768

// ---- static scratch ----
// fp16 activation arrays with dual parity copies; stride = 8 + L + 8, 16B-aligned
__device__ uint4  g_h1h4[4202496], g_h1o4[4202496];   // [64][64][8208] halves
__device__ uint4  g_h2h4[4210688], g_h2o4[4210688];   // [64][128][4112] halves
__device__ float  g_h3[64u*256u*2048u];
__device__ float2 g_fftA[128u*32768u];
__device__ float2 g_fftB[128u*32768u];
__device__ float2 g_tw[32768];
__device__ float  g_spec[64u*8448u];
__device__ float  g_spectrum[64u*256u];
__device__ float  g_timevec[64u*256u];
__device__ float  g_freqvec[64u*128u];
// prepped fp16 weights: [mt][ch16][m=128][k=96]
__device__ __half g_wA2[1u*4u*128u*96u];
__device__ __half g_wA3[2u*8u*128u*96u];

// ---- helpers ----
__device__ __forceinline__ uint32_t smem_u32(const void* p) {
    uint32_t a; asm("{ .reg .u64 t; cvta.to.shared.u64 t, %1; cvt.u32.u64 %0, t; }" : "=r"(a) : "l"(p));
    return a;
}
__device__ __forceinline__ void mma16816(float* c, const uint32_t* a, uint32_t b0, uint32_t b1) {
    asm volatile("mma.sync.aligned.m16n8k16.row.col.f32.f16.f16.f32 "
        "{%0,%1,%2,%3}, {%4,%5,%6,%7}, {%8,%9}, {%0,%1,%2,%3};"
        : "+f"(c[0]), "+f"(c[1]), "+f"(c[2]), "+f"(c[3])
        : "r"(a[0]), "r"(a[1]), "r"(a[2]), "r"(a[3]), "r"(b0), "r"(b1));
}
__device__ __forceinline__ void ldmA(uint32_t* a, uint32_t addr) {
    asm volatile("ldmatrix.sync.aligned.m8n8.x4.shared.b16 {%0,%1,%2,%3}, [%4];"
        : "=r"(a[0]), "=r"(a[1]), "=r"(a[2]), "=r"(a[3]) : "r"(addr));
}
#define CP_ASYNC16(dst, src) asm volatile("cp.async.cg.shared.global [%0], [%1], 16;" :: "r"(dst), "l"(src))
#define CP_ASYNC4(dst, src)  asm volatile("cp.async.ca.shared.global [%0], [%1], 4;"  :: "r"(dst), "l"(src))
#define CP_COMMIT() asm volatile("cp.async.commit_group;")
#define CP_WAIT0()  asm volatile("cp.async.wait_group 0;" ::: "memory")

// ---- weight prep: fp32 [COUT][CIN][5] -> [mt][ch16][m 128][k 96] fp16, tap j=5 zeroed ----
template<int CIN, int MT>
__global__ void prep_w_kernel(const float* __restrict__ w, __half* __restrict__ dst)
{
    const int NCH = CIN / 16;
    int total = MT * NCH * 128 * 96;
    int idx = blockIdx.x * 256 + threadIdx.x;
    if (idx >= total) return;
    int kl = idx % 96;
    int m  = (idx / 96) % 128;
    int ch = (idx / (96 * 128)) % NCH;
    int mt = idx / (96 * 128 * NCH);
    int cl = kl / 6, j = kl - 6 * cl;
    float wv = (j < 5) ? w[(((size_t)(mt * 128 + m)) * CIN + ch * 16 + cl) * 5 + j] : 0.f;
    dst[idx] = __float2half_rn(wv);
}

// ---- conv blocks 2/3: fp16 mma 1-pass, direct fp16 cp.async staging ----
// CTA: M=128 x N=256 conv positions (->128 pooled). 16 warps 2(M) x 8(N); warp = M64 x N32.
// smem: A[2]@0 (24576 ea), sB[2]@49152 (17408 ea: 32 rows x 544B, data at byte 12) = 83968 B
template<int CIN, int COUT, int LIN, int WHICH>
__global__ void __launch_bounds__(512)
convmma_kernel(const float* __restrict__ cb, const float* __restrict__ g,
               const float* __restrict__ be, const float* __restrict__ bm,
               const float* __restrict__ bv)
{
    const int NCH  = CIN / 16;
    const int ISTR = WHICH ? 4112 : 8208;
    const int NPT  = LIN / 256;               // blocks along positions
    const __half* inh = WHICH ? (const __half*)g_h2h4 : (const __half*)g_h1h4;
    const __half* ino = WHICH ? (const __half*)g_h2o4 : (const __half*)g_h1o4;
    const __half* wA  = WHICH ? g_wA3 : g_wA2;
    __half* h2h = (__half*)g_h2h4;
    __half* h2o = (__half*)g_h2o4;

    extern __shared__ __align__(16) char smem[];
    uint32_t sbase = smem_u32(smem);
    int tid = threadIdx.x, wid = tid >> 5, lane = tid & 31;
    int pt = blockIdx.x, mt = blockIdx.y, b = blockIdx.z;
    int warp_m = wid & 1, warp_n = wid >> 1;
    int lrow = lane >> 2;
    int tb = pt * 256 - 2;                    // tb ≡ 6 (mod 8)

    // invariant index math
    uint32_t aoff[4];
    #pragma unroll
    for (int m2 = 0; m2 < 4; m2++)
        aoff[m2] = (uint32_t)(((warp_m * 64 + m2 * 16 + (lane & 7) + ((lane >> 3) & 1) * 8) * 96
                              + (lane >> 4) * 8) * 2);
    int b0idx[6], b1idx[6];
    #pragma unroll
    for (int ks = 0; ks < 6; ks++) {
        int k0 = ks * 16 + (lane & 3) * 2;
        int c0 = k0 / 6, j0 = k0 - 6 * c0;
        int k1 = k0 + 8;
        int c1 = k1 / 6, j1 = k1 - 6 * c1;
        int t0 = warp_n * 32 + lrow + j0;
        int t1 = warp_n * 32 + lrow + j1;
        b0idx[ks] = ((t0 & 1) * 16 + c0) * 136 + 3 + (t0 >> 1);
        b1idx[ks] = ((t1 & 1) * 16 + c1) * 136 + 3 + (t1 >> 1);
    }

    float acc[4][4][4];
    #pragma unroll
    for (int i = 0; i < 4; i++)
        #pragma unroll
        for (int n = 0; n < 4; n++)
            #pragma unroll
            for (int q = 0; q < 4; q++) acc[i][n][q] = 0.f;

    #define STAGE_A(CH) do {                                                             \
        const uint4* _as = (const uint4*)(wA + (size_t)(mt * NCH + (CH)) * 128 * 96);    \
        uint32_t _ad = sbase + (((CH) & 1) ? 24576u : 0u);                               \
        for (int _i = tid; _i < 1536; _i += 512) CP_ASYNC16(_ad + _i * 16, _as + _i);    \
    } while (0)
    #define STAGE_B(CH) do {                                                             \
        uint32_t _bb = sbase + 49152u + ((CH) & 1) * 17408u;                             \
        for (int _i = tid; _i < 1152; _i += 512) {                                       \
            int _row = _i / 36, _op = _i - _row * 36;                                    \
            int _p = _row >> 4, _c = _row & 15;                                          \
            const __half* _g = (_p ? ino : inh)                                          \
                + ((size_t)b * CIN + (CH) * 16 + _c) * ISTR + 8 + tb;                    \
            uint32_t _d = _bb + _row * 544u + 12u;                                       \
            if (_op == 0)        CP_ASYNC4(_d, _g);                                      \
            else if (_op <= 32) { int _m = 1 + (_op - 1) * 4; CP_ASYNC16(_d + _m * 4, _g + 2 * _m); } \
            else                { int _m = 96 + _op;          CP_ASYNC4 (_d + _m * 4, _g + 2 * _m); } \
        }                                                                                \
    } while (0)

    STAGE_A(0); STAGE_B(0); CP_COMMIT();
    CP_WAIT0();
    __syncthreads();

    for (int ch = 0; ch < NCH; ch++) {
        int cur = ch & 1;
        if (ch + 1 < NCH) { STAGE_A(ch + 1); STAGE_B(ch + 1); CP_COMMIT(); }
        {
            uint32_t Aaddr = sbase + (cur ? 24576u : 0u);
            const uint32_t* Bw = (const uint32_t*)(smem + 49152 + cur * 17408);
            #pragma unroll
            for (int ks = 0; ks < 6; ks++) {
                uint32_t afr[4][4];
                #pragma unroll
                for (int m2 = 0; m2 < 4; m2++) ldmA(afr[m2], Aaddr + aoff[m2] + ks * 32);
                const uint32_t* p0 = Bw + b0idx[ks];
                const uint32_t* p1 = Bw + b1idx[ks];
                #pragma unroll
                for (int nt = 0; nt < 4; nt++) {
                    uint32_t bb0 = p0[nt * 4];
                    uint32_t bb1 = p1[nt * 4];
                    #pragma unroll
                    for (int m2 = 0; m2 < 4; m2++)
                        mma16816(acc[m2][nt], afr[m2], bb0, bb1);
                }
            }
        }
        if (ch + 1 < NCH) CP_WAIT0();
        __syncthreads();
    }
    #undef STAGE_A
    #undef STAGE_B

    // epilogue: BN + relu + maxpool2
    int pcol = warp_n * 16 + (lane & 3);
    #pragma unroll
    for (int m2 = 0; m2 < 4; m2++) {
        #pragma unroll
        for (int h = 0; h < 2; h++) {
            int mg = mt * 128 + warp_m * 64 + m2 * 16 + h * 8 + lrow;
            float scv = g[mg] * rsqrtf(bv[mg] + 1e-5f);
            float shv = be[mg] - bm[mg] * scv + cb[mg] * scv;
            #pragma unroll
            for (int nt = 0; nt < 4; nt++) {
                float v0 = acc[m2][nt][2 * h]     * scv + shv;
                float v1 = acc[m2][nt][2 * h + 1] * scv + shv;
                float r = fmaxf(fmaxf(v0, v1), 0.f);
                int P = pt * 128 + pcol + nt * 4;
                if (WHICH == 0) {
                    size_t base = ((size_t)(b * 128 + mg)) * 4112;
                    __half hr = __float2half_rn(r);
                    h2h[base + 8 + P] = hr;
                    h2o[base + 7 + P] = hr;
                } else {
                    g_h3[((size_t)b * 256 + mg) * 2048 + P] = r;
                }
            }
        }
    }
    // pad maintenance for g_h2 arrays (conv2 only)
    if (WHICH == 0) {
        if (pt == 0) {
            for (int idx = tid; idx < 128 * 15; idx += 512) {
                int row = idx / 15, s = idx - row * 15;
                size_t base = ((size_t)(b * 128 + mt * 128 + row)) * 4112;
                if (s < 8) h2h[base + s] = __float2half(0.f);
                else       h2o[base + (s - 8)] = __float2half(0.f);
            }
        }
        if (pt == NPT - 1) {
            for (int idx = tid; idx < 128 * 17; idx += 512) {
                int row = idx / 17, s = idx - row * 17;
                size_t base = ((size_t)(b * 128 + mt * 128 + row)) * 4112;
                if (s < 8) h2h[base + 4104 + s] = __float2half(0.f);
                else       h2o[base + 4103 + (s - 8)] = __float2half(0.f);
            }
        }
    }
}

// =============== conv1: 1->64, k=7, +BN+relu+pool2, fp16 dual-parity output ===============
__global__ void conv1_kernel(const float* __restrict__ x, const float* __restrict__ w,
                             const float* __restrict__ cb, const float* __restrict__ g,
                             const float* __restrict__ be, const float* __restrict__ m,
                             const float* __restrict__ v)
{
    __shared__ float sx[519];
    __shared__ float swv[56];
    __shared__ float sbn[16];
    int tid = threadIdx.x;                 // 256
    int pb  = blockIdx.x * 256;
    int c8  = blockIdx.y * 8;
    int b   = blockIdx.z;
    __half* h1h = (__half*)g_h1h4;
    __half* h1o = (__half*)g_h1o4;
    const float* xb = x + (size_t)b * 16384;
    for (int idx = tid; idx < 519; idx += 256) {
        int t = 2*pb - 3 + idx;
        sx[idx] = (t >= 0 && t < 16384) ? xb[t] : 0.f;
    }
    if (tid < 56) swv[tid] = w[c8*7 + tid];
    if (tid < 8) {
        int c = c8 + tid;
        float sc = g[c] * rsqrtf(v[c] + 1e-5f);
        sbn[tid] = sc;
        sbn[8 + tid] = be[c] - m[c]*sc + cb[c]*sc;
    }
    __syncthreads();
    float xv[8];
    #pragma unroll
    for (int j = 0; j < 8; j++) xv[j] = sx[2*tid + j];
    int P = pb + tid;
    #pragma unroll
    for (int c = 0; c < 8; c++) {
        float y0 = 0.f, y1 = 0.f;
        #pragma unroll
        for (int j = 0; j < 7; j++) {
            float wc = swv[c*7 + j];
            y0 = fmaf(wc, xv[j],   y0);
            y1 = fmaf(wc, xv[j+1], y1);
        }
        float sc = sbn[c], sh = sbn[8 + c];
        float r = fmaxf(fmaxf(y0*sc + sh, y1*sc + sh), 0.f);
        size_t base = ((size_t)(b*64 + c8 + c)) * 8208;
        __half hr = __float2half_rn(r);
        h1h[base + 8 + P] = hr;
        h1o[base + 7 + P] = hr;
    }
    // pads
    if (pb == 0) {
        for (int idx = tid; idx < 8 * 15; idx += 256) {
            int c = idx / 15, s = idx - c * 15;
            size_t base = ((size_t)(b*64 + c8 + c)) * 8208;
            if (s < 8) h1h[base + s] = __float2half(0.f);
            else       h1o[base + (s - 8)] = __float2half(0.f);
        }
    }
    if (pb == 8192 - 256) {
        for (int idx = tid; idx < 8 * 17; idx += 256) {
            int c = idx / 17, s = idx - c * 17;
            size_t base = ((size_t)(b*64 + c8 + c)) * 8208;
            if (s < 8) h1h[base + 8200 + s] = __float2half(0.f);
            else       h1o[base + 8199 + (s - 8)] = __float2half(0.f);
        }
    }
}

// =============== masked global average over time ===============
__global__ void timepool_kernel(const int* __restrict__ lengths)
{
    int c = blockIdx.x, b = blockIdx.y, tid = threadIdx.x;
    int plen = lengths[b] >> 3; if (plen < 1) plen = 1;
    const float* p = g_h3 + ((size_t)b*256 + c)*2048;
    float s = 0.f;
    for (int t = tid; t < plen; t += 128) s += p[t];
    __shared__ float red[4];
    #pragma unroll
    for (int off = 16; off; off >>= 1) s += __shfl_down_sync(0xffffffffu, s, off);
    if ((tid & 31) == 0) red[tid >> 5] = s;
    __syncthreads();
    if (tid == 0) g_timevec[b*256 + c] = (red[0]+red[1]+red[2]+red[3]) / (float)plen;
}

// =============== FFT: Bluestein, M=32768, radix-4 Stockham + fused tails ===============
__global__ void fft_twiddle_kernel()
{
    int p = blockIdx.x*blockDim.x + threadIdx.x;
    int off = 0;
    #pragma unroll
    for (int st = 0; st < 15; st++) {
        int n = FFT_M >> st, mm = n >> 1;
        if (p < mm) {
            float sv, cv; sincosf(-2.f*PI_F*(float)p/(float)n, &sv, &cv);
            g_tw[off + p] = make_float2(cv, sv);
        }
        off += mm;
    }
}

__global__ void fft_build_kernel(const float* __restrict__ x, const int* __restrict__ lengths)
{
    int n = blockIdx.x*blockDim.x + threadIdx.x;
    int i = blockIdx.y;
    int L = lengths[i];
    int mm = (n <= FFT_M - n) ? n : FFT_M - n;
    float2 a  = make_float2(0.f, 0.f);
    float2 bb = make_float2(0.f, 0.f);
    if (mm < L) {
        unsigned r = ((unsigned)mm * (unsigned)mm) % (unsigned)(2*L);
        float sv, cv; sincosf(PI_F * (float)r / (float)L, &sv, &cv);
        bb = make_float2(cv, sv);
        if (n < L) {
            float xv = x[(size_t)i*16384 + n];
            a = make_float2(xv*cv, -xv*sv);
        }
    }
    g_fftA[(size_t)i*FFT_M + n]      = a;
    g_fftA[(size_t)(64+i)*FFT_M + n] = bb;
}

__global__ void fft4_stage_kernel(int sel, int sShift, int twOff)
{
    const float2* __restrict__ src = sel ? g_fftB : g_fftA;
    float2* __restrict__ dst       = sel ? g_fftA : g_fftB;
    int i = blockIdx.x*blockDim.x + threadIdx.x;
    size_t base = (size_t)blockIdx.y * FFT_M;
    int p = i >> sShift;
    int s = 1 << sShift;
    float2 a = src[base + i];
    float2 b = src[base + i + 8192];
    float2 c = src[base + i + 16384];
    float2 d = src[base + i + 24576];
    float2 w1 = g_tw[twOff + p];
    float2 w2 = g_tw[twOff + 2*p];
    float2 w3 = make_float2(w1.x*w2.x - w1.y*w2.y, w1.x*w2.y + w1.y*w2.x);
    float2 apc = make_float2(a.x + c.x, a.y + c.y);
    float2 amc = make_float2(a.x - c.x, a.y - c.y);
    float2 bpd = make_float2(b.x + d.x, b.y + d.y);
    float2 tbd = make_float2(b.x - d.x, b.y - d.y);
    float2 bmd = make_float2(tbd.y, -tbd.x);
    float2 y0 = make_float2(apc.x + bpd.x, apc.y + bpd.y);
    float2 u1 = make_float2(amc.x + bmd.x, amc.y + bmd.y);
    float2 u2 = make_float2(apc.x - bpd.x, apc.y - bpd.y);
    float2 u3 = make_float2(amc.x - bmd.x, amc.y - bmd.y);
    int j = i + 3*p*s;
    dst[base + j]       = y0;
    dst[base + j + s]   = make_float2(fmaf(u1.x,w1.x,-u1.y*w1.y), fmaf(u1.x,w1.y, u1.y*w1.x));
    dst[base + j + 2*s] = make_float2(fmaf(u2.x,w2.x,-u2.y*w2.y), fmaf(u2.x,w2.y, u2.y*w2.x));
    dst[base + j + 3*s] = make_float2(fmaf(u3.x,w3.x,-u3.y*w3.y), fmaf(u3.x,w3.y, u3.y*w3.x));
}

// forward final radix-2 fused with conj pointwise product
__global__ void fft2_pointwise_kernel()
{
    int i = blockIdx.x*blockDim.x + threadIdx.x;
    int arr = blockIdx.y;
    const float2* d  = g_fftB + (size_t)arr * FFT_M;
    const float2* cc = g_fftB + (size_t)(64 + arr) * FFT_M;
    float2 a = d[i],  b = d[i + 16384];
    float2 ac = cc[i], bc = cc[i + 16384];
    float2 d0 = make_float2(a.x + b.x, a.y + b.y);
    float2 d1 = make_float2(a.x - b.x, a.y - b.y);
    float2 c0 = make_float2(ac.x + bc.x, ac.y + bc.y);
    float2 c1 = make_float2(ac.x - bc.x, ac.y - bc.y);
    float2* o = g_fftA + (size_t)arr * FFT_M;
    o[i]         = make_float2(d0.x*c0.x - d0.y*c0.y, -(d0.x*c0.y + d0.y*c0.x));
    o[i + 16384] = make_float2(d1.x*c1.x - d1.y*c1.y, -(d1.x*c1.y + d1.y*c1.x));
}

// inverse final radix-2 fused with magnitude/log1p
__global__ void fft2_finalize_kernel(const int* __restrict__ lengths)
{
    int i = blockIdx.x*blockDim.x + threadIdx.x;
    int arr = blockIdx.y;
    int K = lengths[arr] / 2 + 1;
    if (i >= K) return;
    const float2* d = g_fftB + (size_t)arr * FFT_M;
    float2 a = d[i], b = d[i + 16384];
    float2 s = make_float2(a.x + b.x, a.y + b.y);
    g_spec[(size_t)arr * 8448 + i] = log1pf(sqrtf(s.x*s.x + s.y*s.y) * (1.0f/32768.0f));
}

__global__ void apool_kernel(const int* __restrict__ lengths)
{
    int i = blockIdx.x, j = threadIdx.x;
    int K = lengths[i]/2 + 1;
    int s0 = (j*K) >> 8;
    int e0 = ((j+1)*K + 255) >> 8;
    const float* sp = g_spec + (size_t)i*8448;
    float s = 0.f;
    for (int t = s0; t < e0; t++) s += sp[t];
    g_spectrum[i*256 + j] = s / (float)(e0 - s0);
}

// =============== small GEMMs ===============
__global__ void freqlin_kernel(const float* __restrict__ fw, const float* __restrict__ fb)
{
    int i = blockIdx.x, h = threadIdx.x;
    __shared__ float sp[256];
    for (int f = h; f < 256; f += 128) sp[f] = g_spectrum[i*256 + f];
    __syncthreads();
    float acc = fb[h];
    const float* wr = fw + (size_t)h*256;
    for (int f = 0; f < 256; f++) acc = fmaf(sp[f], wr[f], acc);
    g_freqvec[i*128 + h] = fmaxf(acc, 0.f);
}

__global__ void head_kernel(const float* __restrict__ w0, const float* __restrict__ b0,
                            const float* __restrict__ w1, const float* __restrict__ b1,
                            float* __restrict__ out)
{
    int b = blockIdx.x, tid = threadIdx.x;
    __shared__ float fused[384];
    __shared__ float hid[128];
    for (int j = tid; j < 384; j += 128)
        fused[j] = (j < 256) ? g_timevec[b*256 + j] : g_freqvec[b*128 + (j - 256)];
    __syncthreads();
    float acc = b0[tid];
    const float* wr = w0 + (size_t)tid*384;
    for (int j = 0; j < 384; j++) acc = fmaf(fused[j], wr[j], acc);
    hid[tid] = fmaxf(acc, 0.f);
    __syncthreads();
    int wid = tid >> 5, lane = tid & 31;
    float s = 0.f;
    for (int t = lane; t < 128; t += 32) s += hid[t] * w1[wid*128 + t];
    #pragma unroll
    for (int off = 16; off; off >>= 1) s += __shfl_down_sync(0xffffffffu, s, off);
    if (lane == 0) out[b*4 + wid] = s + b1[wid];
}

// =============== launch ===============
extern "C" void kernel_launch(void* const* d_in, const int* in_sizes, int n_in,
                              void* d_out, int out_size)
{
    const float* x   = (const float*)d_in[0];
    const int*   len = (const int*)  d_in[1];
    const float *cw0 = (const float*)d_in[2],  *cb0 = (const float*)d_in[3];
    const float *g0  = (const float*)d_in[4],  *be0 = (const float*)d_in[5];
    const float *m0  = (const float*)d_in[6],  *v0  = (const float*)d_in[7];
    const float *cw1 = (const float*)d_in[8],  *cb1 = (const float*)d_in[9];
    const float *g1  = (const float*)d_in[10], *be1 = (const float*)d_in[11];
    const float *m1  = (const float*)d_in[12], *v1  = (const float*)d_in[13];
    const float *cw2 = (const float*)d_in[14], *cb2 = (const float*)d_in[15];
    const float *g2  = (const float*)d_in[16], *be2 = (const float*)d_in[17];
    const float *m2  = (const float*)d_in[18], *v2  = (const float*)d_in[19];
    const float *fw  = (const float*)d_in[20], *fb  = (const float*)d_in[21];
    const float *hw0 = (const float*)d_in[22], *hb0 = (const float*)d_in[23];
    const float *hw1 = (const float*)d_in[24], *hb1 = (const float*)d_in[25];
    float* out = (float*)d_out;

    const int SMEM_CONV = 83968;
    cudaFuncSetAttribute(convmma_kernel<64,128,8192,0>, cudaFuncAttributeMaxDynamicSharedMemorySize, SMEM_CONV);
    cudaFuncSetAttribute(convmma_kernel<128,256,4096,1>, cudaFuncAttributeMaxDynamicSharedMemorySize, SMEM_CONV);

    __half *wa2, *wa3;
    cudaGetSymbolAddress((void**)&wa2, g_wA2);
    cudaGetSymbolAddress((void**)&wa3, g_wA3);
    prep_w_kernel<64, 1><<<(1*4*128*96  + 255)/256, 256>>>(cw1, wa2);
    prep_w_kernel<128,2><<<(2*8*128*96 + 255)/256, 256>>>(cw2, wa3);

    // time branch
    conv1_kernel<<<dim3(32,8,64), 256>>>(x, cw0, cb0, g0, be0, m0, v0);
    convmma_kernel<64,128,8192,0><<<dim3(32,1,64), 512, SMEM_CONV>>>(cb1, g1, be1, m1, v1);
    convmma_kernel<128,256,4096,1><<<dim3(16,2,64), 512, SMEM_CONV>>>(cb2, g2, be2, m2, v2);
    timepool_kernel<<<dim3(256,64), 128>>>(len);

    // frequency branch
    fft_twiddle_kernel<<<64, 256>>>();
    fft_build_kernel<<<dim3(128,64), 256>>>(x, len);
    int sel = 0;
    for (int st = 0; st < 7; st++) {
        int n = FFT_M >> (2*st);
        fft4_stage_kernel<<<dim3(32,128), 256>>>(sel, 2*st, 32768 - n);
        sel ^= 1;
    }
    fft2_pointwise_kernel<<<dim3(64,64), 256>>>();
    sel = 0;
    for (int st = 0; st < 7; st++) {
        int n = FFT_M >> (2*st);
        fft4_stage_kernel<<<dim3(32,64), 256>>>(sel, 2*st, 32768 - n);
        sel ^= 1;
    }
    fft2_finalize_kernel<<<dim3(33,64), 256>>>(len);
    apool_kernel<<<64, 256>>>(len);
    freqlin_kernel<<<64, 128>>>(fw, fb);

    head_kernel<<<64, 128>>>(hw0, hb0, hw1, hb1, out);
}

// round 11
// speedup vs baseline: 6.9702x; 1.0468x over previous
#include <cuda_runtime.h>
#include <cuda_fp16.h>
#include <cstdint>
#include <cstddef>

#define PI_F 3.14159265358979323846f
#define FFT_M 32768

// ---- static scratch ----
// fp16 activation arrays with dual parity copies; stride = 8 + L + 8, 16B-aligned
__device__ uint4  g_h1h4[4202496], g_h1o4[4202496];   // [64][64][8208] halves
__device__ uint4  g_h2h4[4210688], g_h2o4[4210688];   // [64][128][4112] halves
__device__ float  g_h3[64u*256u*2048u];
__device__ float2 g_fftA[128u*32768u];
__device__ float2 g_fftB[128u*32768u];
__device__ float2 g_tw[32768];
__device__ float  g_spec[64u*8448u];
__device__ float  g_spectrum[64u*256u];
__device__ float  g_timevec[64u*256u];
__device__ float  g_freqvec[64u*128u];
// prepped fp16 weights: [mt][ch16][m=128][k=96]
__device__ __half g_wA2[1u*4u*128u*96u];
__device__ __half g_wA3[2u*8u*128u*96u];

// ---- helpers ----
__device__ __forceinline__ uint32_t smem_u32(const void* p) {
    uint32_t a; asm("{ .reg .u64 t; cvta.to.shared.u64 t, %1; cvt.u32.u64 %0, t; }" : "=r"(a) : "l"(p));
    return a;
}
__device__ __forceinline__ void mma16816(float* c, const uint32_t* a, uint32_t b0, uint32_t b1) {
    asm volatile("mma.sync.aligned.m16n8k16.row.col.f32.f16.f16.f32 "
        "{%0,%1,%2,%3}, {%4,%5,%6,%7}, {%8,%9}, {%0,%1,%2,%3};"
        : "+f"(c[0]), "+f"(c[1]), "+f"(c[2]), "+f"(c[3])
        : "r"(a[0]), "r"(a[1]), "r"(a[2]), "r"(a[3]), "r"(b0), "r"(b1));
}
__device__ __forceinline__ void ldmA(uint32_t* a, uint32_t addr) {
    asm volatile("ldmatrix.sync.aligned.m8n8.x4.shared.b16 {%0,%1,%2,%3}, [%4];"
        : "=r"(a[0]), "=r"(a[1]), "=r"(a[2]), "=r"(a[3]) : "r"(addr));
}
#define CP_ASYNC16(dst, src) asm volatile("cp.async.cg.shared.global [%0], [%1], 16;" :: "r"(dst), "l"(src))
#define CP_ASYNC4(dst, src)  asm volatile("cp.async.ca.shared.global [%0], [%1], 4;"  :: "r"(dst), "l"(src))
#define CP_COMMIT() asm volatile("cp.async.commit_group;")
#define CP_WAIT0()  asm volatile("cp.async.wait_group 0;" ::: "memory")

// ---- weight prep: fp32 [COUT][CIN][5] -> [mt][ch16][m 128][k 96] fp16, tap j=5 zeroed ----
template<int CIN, int MT>
__global__ void prep_w_kernel(const float* __restrict__ w, __half* __restrict__ dst)
{
    const int NCH = CIN / 16;
    int total = MT * NCH * 128 * 96;
    int idx = blockIdx.x * 256 + threadIdx.x;
    if (idx >= total) return;
    int kl = idx % 96;
    int m  = (idx / 96) % 128;
    int ch = (idx / (96 * 128)) % NCH;
    int mt = idx / (96 * 128 * NCH);
    int cl = kl / 6, j = kl - 6 * cl;
    float wv = (j < 5) ? w[(((size_t)(mt * 128 + m)) * CIN + ch * 16 + cl) * 5 + j] : 0.f;
    dst[idx] = __float2half_rn(wv);
}

// ---- conv blocks 2/3: fp16 mma 1-pass, direct fp16 cp.async staging, 2 CTA/SM ----
// CTA: 256 thr (8 warps 2Mx4N). Tile M=128 x N=128 conv positions (->64 pooled).
// smem: A[2]@0 (24576 ea), sB[2]@49152 (9216 ea: 32 rows x 288B, data at byte 12) = 67584 B
template<int CIN, int COUT, int LIN, int WHICH>
__global__ void __launch_bounds__(256, 2)
convmma_kernel(const float* __restrict__ cb, const float* __restrict__ g,
               const float* __restrict__ be, const float* __restrict__ bm,
               const float* __restrict__ bv)
{
    const int NCH  = CIN / 16;
    const int ISTR = WHICH ? 4112 : 8208;
    const int NPT  = LIN / 128;               // tiles along positions
    const __half* inh = WHICH ? (const __half*)g_h2h4 : (const __half*)g_h1h4;
    const __half* ino = WHICH ? (const __half*)g_h2o4 : (const __half*)g_h1o4;
    const __half* wA  = WHICH ? g_wA3 : g_wA2;
    __half* h2h = (__half*)g_h2h4;
    __half* h2o = (__half*)g_h2o4;

    extern __shared__ __align__(16) char smem[];
    uint32_t sbase = smem_u32(smem);
    int tid = threadIdx.x, wid = tid >> 5, lane = tid & 31;
    int pt = blockIdx.x, mt = blockIdx.y, b = blockIdx.z;
    int warp_m = wid & 1, warp_n = wid >> 1;  // 2 x 4
    int lrow = lane >> 2;
    int tb = pt * 128 - 2;                    // tb ≡ 6 (mod 8)

    // invariant index math
    uint32_t aoff[4];
    #pragma unroll
    for (int m2 = 0; m2 < 4; m2++)
        aoff[m2] = (uint32_t)(((warp_m * 64 + m2 * 16 + (lane & 7) + ((lane >> 3) & 1) * 8) * 96
                              + (lane >> 4) * 8) * 2);
    int b0idx[6], b1idx[6];
    #pragma unroll
    for (int ks = 0; ks < 6; ks++) {
        int k0 = ks * 16 + (lane & 3) * 2;
        int c0 = k0 / 6, j0 = k0 - 6 * c0;
        int k1 = k0 + 8;
        int c1 = k1 / 6, j1 = k1 - 6 * c1;
        int t0 = warp_n * 32 + lrow + j0;
        int t1 = warp_n * 32 + lrow + j1;
        b0idx[ks] = ((t0 & 1) * 16 + c0) * 72 + 3 + (t0 >> 1);
        b1idx[ks] = ((t1 & 1) * 16 + c1) * 72 + 3 + (t1 >> 1);
    }

    float acc[4][4][4];
    #pragma unroll
    for (int i = 0; i < 4; i++)
        #pragma unroll
        for (int n = 0; n < 4; n++)
            #pragma unroll
            for (int q = 0; q < 4; q++) acc[i][n][q] = 0.f;

    #define STAGE_A(CH) do {                                                             \
        const uint4* _as = (const uint4*)(wA + (size_t)(mt * NCH + (CH)) * 128 * 96);    \
        uint32_t _ad = sbase + (((CH) & 1) ? 24576u : 0u);                               \
        for (int _i = tid; _i < 1536; _i += 256) CP_ASYNC16(_ad + _i * 16, _as + _i);    \
    } while (0)
    #define STAGE_B(CH) do {                                                             \
        uint32_t _bb = sbase + 49152u + ((CH) & 1) * 9216u;                              \
        for (int _i = tid; _i < 608; _i += 256) {                                        \
            int _row = _i / 19, _op = _i - _row * 19;                                    \
            int _p = _row >> 4, _c = _row & 15;                                          \
            const __half* _g = (_p ? ino : inh)                                          \
                + ((size_t)b * CIN + (CH) * 16 + _c) * ISTR + 8 + tb;                    \
            uint32_t _d = _bb + _row * 288u + 12u;                                       \
            if (_op == 0)        CP_ASYNC4(_d, _g);                                      \
            else if (_op <= 16) { int _m = 1 + (_op - 1) * 4; CP_ASYNC16(_d + _m * 4, _g + 2 * _m); } \
            else                { int _m = 64 + (_op - 16);   CP_ASYNC4 (_d + _m * 4, _g + 2 * _m); } \
        }                                                                                \
    } while (0)

    STAGE_A(0); STAGE_B(0); CP_COMMIT();
    CP_WAIT0();
    __syncthreads();

    for (int ch = 0; ch < NCH; ch++) {
        int cur = ch & 1;
        if (ch + 1 < NCH) { STAGE_A(ch + 1); STAGE_B(ch + 1); CP_COMMIT(); }
        {
            uint32_t Aaddr = sbase + (cur ? 24576u : 0u);
            const uint32_t* Bw = (const uint32_t*)(smem + 49152 + cur * 9216);
            #pragma unroll
            for (int ks = 0; ks < 6; ks++) {
                uint32_t afr[4][4];
                #pragma unroll
                for (int m2 = 0; m2 < 4; m2++) ldmA(afr[m2], Aaddr + aoff[m2] + ks * 32);
                const uint32_t* p0 = Bw + b0idx[ks];
                const uint32_t* p1 = Bw + b1idx[ks];
                #pragma unroll
                for (int nt = 0; nt < 4; nt++) {
                    uint32_t bb0 = p0[nt * 4];
                    uint32_t bb1 = p1[nt * 4];
                    #pragma unroll
                    for (int m2 = 0; m2 < 4; m2++)
                        mma16816(acc[m2][nt], afr[m2], bb0, bb1);
                }
            }
        }
        if (ch + 1 < NCH) CP_WAIT0();
        __syncthreads();
    }
    #undef STAGE_A
    #undef STAGE_B

    // epilogue: BN + relu + maxpool2
    int pcol = warp_n * 16 + (lane & 3);
    #pragma unroll
    for (int m2 = 0; m2 < 4; m2++) {
        #pragma unroll
        for (int h = 0; h < 2; h++) {
            int mg = mt * 128 + warp_m * 64 + m2 * 16 + h * 8 + lrow;
            float scv = g[mg] * rsqrtf(bv[mg] + 1e-5f);
            float shv = be[mg] - bm[mg] * scv + cb[mg] * scv;
            #pragma unroll
            for (int nt = 0; nt < 4; nt++) {
                float v0 = acc[m2][nt][2 * h]     * scv + shv;
                float v1 = acc[m2][nt][2 * h + 1] * scv + shv;
                float r = fmaxf(fmaxf(v0, v1), 0.f);
                int P = pt * 64 + pcol + nt * 4;
                if (WHICH == 0) {
                    size_t base = ((size_t)(b * 128 + mg)) * 4112;
                    __half hr = __float2half_rn(r);
                    h2h[base + 8 + P] = hr;
                    h2o[base + 7 + P] = hr;
                } else {
                    g_h3[((size_t)b * 256 + mg) * 2048 + P] = r;
                }
            }
        }
    }
    // pad maintenance for g_h2 arrays (conv2 only)
    if (WHICH == 0) {
        if (pt == 0) {
            for (int idx = tid; idx < 128 * 15; idx += 256) {
                int row = idx / 15, s = idx - row * 15;
                size_t base = ((size_t)(b * 128 + mt * 128 + row)) * 4112;
                if (s < 8) h2h[base + s] = __float2half(0.f);
                else       h2o[base + (s - 8)] = __float2half(0.f);
            }
        }
        if (pt == NPT - 1) {
            for (int idx = tid; idx < 128 * 17; idx += 256) {
                int row = idx / 17, s = idx - row * 17;
                size_t base = ((size_t)(b * 128 + mt * 128 + row)) * 4112;
                if (s < 8) h2h[base + 4104 + s] = __float2half(0.f);
                else       h2o[base + 4103 + (s - 8)] = __float2half(0.f);
            }
        }
    }
}

// =============== conv1: 1->64, k=7, +BN+relu+pool2, fp16 dual-parity output ===============
__global__ void conv1_kernel(const float* __restrict__ x, const float* __restrict__ w,
                             const float* __restrict__ cb, const float* __restrict__ g,
                             const float* __restrict__ be, const float* __restrict__ m,
                             const float* __restrict__ v)
{
    __shared__ float sx[519];
    __shared__ float swv[56];
    __shared__ float sbn[16];
    int tid = threadIdx.x;                 // 256
    int pb  = blockIdx.x * 256;
    int c8  = blockIdx.y * 8;
    int b   = blockIdx.z;
    __half* h1h = (__half*)g_h1h4;
    __half* h1o = (__half*)g_h1o4;
    const float* xb = x + (size_t)b * 16384;
    for (int idx = tid; idx < 519; idx += 256) {
        int t = 2*pb - 3 + idx;
        sx[idx] = (t >= 0 && t < 16384) ? xb[t] : 0.f;
    }
    if (tid < 56) swv[tid] = w[c8*7 + tid];
    if (tid < 8) {
        int c = c8 + tid;
        float sc = g[c] * rsqrtf(v[c] + 1e-5f);
        sbn[tid] = sc;
        sbn[8 + tid] = be[c] - m[c]*sc + cb[c]*sc;
    }
    __syncthreads();
    float xv[8];
    #pragma unroll
    for (int j = 0; j < 8; j++) xv[j] = sx[2*tid + j];
    int P = pb + tid;
    #pragma unroll
    for (int c = 0; c < 8; c++) {
        float y0 = 0.f, y1 = 0.f;
        #pragma unroll
        for (int j = 0; j < 7; j++) {
            float wc = swv[c*7 + j];
            y0 = fmaf(wc, xv[j],   y0);
            y1 = fmaf(wc, xv[j+1], y1);
        }
        float sc = sbn[c], sh = sbn[8 + c];
        float r = fmaxf(fmaxf(y0*sc + sh, y1*sc + sh), 0.f);
        size_t base = ((size_t)(b*64 + c8 + c)) * 8208;
        __half hr = __float2half_rn(r);
        h1h[base + 8 + P] = hr;
        h1o[base + 7 + P] = hr;
    }
    if (pb == 0) {
        for (int idx = tid; idx < 8 * 15; idx += 256) {
            int c = idx / 15, s = idx - c * 15;
            size_t base = ((size_t)(b*64 + c8 + c)) * 8208;
            if (s < 8) h1h[base + s] = __float2half(0.f);
            else       h1o[base + (s - 8)] = __float2half(0.f);
        }
    }
    if (pb == 8192 - 256) {
        for (int idx = tid; idx < 8 * 17; idx += 256) {
            int c = idx / 17, s = idx - c * 17;
            size_t base = ((size_t)(b*64 + c8 + c)) * 8208;
            if (s < 8) h1h[base + 8200 + s] = __float2half(0.f);
            else       h1o[base + 8199 + (s - 8)] = __float2half(0.f);
        }
    }
}

// =============== masked global average over time ===============
__global__ void timepool_kernel(const int* __restrict__ lengths)
{
    int c = blockIdx.x, b = blockIdx.y, tid = threadIdx.x;
    int plen = lengths[b] >> 3; if (plen < 1) plen = 1;
    const float* p = g_h3 + ((size_t)b*256 + c)*2048;
    float s = 0.f;
    for (int t = tid; t < plen; t += 128) s += p[t];
    __shared__ float red[4];
    #pragma unroll
    for (int off = 16; off; off >>= 1) s += __shfl_down_sync(0xffffffffu, s, off);
    if ((tid & 31) == 0) red[tid >> 5] = s;
    __syncthreads();
    if (tid == 0) g_timevec[b*256 + c] = (red[0]+red[1]+red[2]+red[3]) / (float)plen;
}

// =============== FFT: Bluestein, M=32768, radix-4 Stockham + fused tails ===============
__global__ void fft_twiddle_kernel()
{
    int p = blockIdx.x*blockDim.x + threadIdx.x;
    int off = 0;
    #pragma unroll
    for (int st = 0; st < 15; st++) {
        int n = FFT_M >> st, mm = n >> 1;
        if (p < mm) {
            float sv, cv; sincosf(-2.f*PI_F*(float)p/(float)n, &sv, &cv);
            g_tw[off + p] = make_float2(cv, sv);
        }
        off += mm;
    }
}

__global__ void fft_build_kernel(const float* __restrict__ x, const int* __restrict__ lengths)
{
    int n = blockIdx.x*blockDim.x + threadIdx.x;
    int i = blockIdx.y;
    int L = lengths[i];
    int mm = (n <= FFT_M - n) ? n : FFT_M - n;
    float2 a  = make_float2(0.f, 0.f);
    float2 bb = make_float2(0.f, 0.f);
    if (mm < L) {
        unsigned r = ((unsigned)mm * (unsigned)mm) % (unsigned)(2*L);
        float sv, cv; sincosf(PI_F * (float)r / (float)L, &sv, &cv);
        bb = make_float2(cv, sv);
        if (n < L) {
            float xv = x[(size_t)i*16384 + n];
            a = make_float2(xv*cv, -xv*sv);
        }
    }
    g_fftA[(size_t)i*FFT_M + n]      = a;
    g_fftA[(size_t)(64+i)*FFT_M + n] = bb;
}

__global__ void fft4_stage_kernel(int sel, int sShift, int twOff)
{
    const float2* __restrict__ src = sel ? g_fftB : g_fftA;
    float2* __restrict__ dst       = sel ? g_fftA : g_fftB;
    int i = blockIdx.x*blockDim.x + threadIdx.x;
    size_t base = (size_t)blockIdx.y * FFT_M;
    int p = i >> sShift;
    int s = 1 << sShift;
    float2 a = src[base + i];
    float2 b = src[base + i + 8192];
    float2 c = src[base + i + 16384];
    float2 d = src[base + i + 24576];
    float2 w1 = g_tw[twOff + p];
    float2 w2 = g_tw[twOff + 2*p];
    float2 w3 = make_float2(w1.x*w2.x - w1.y*w2.y, w1.x*w2.y + w1.y*w2.x);
    float2 apc = make_float2(a.x + c.x, a.y + c.y);
    float2 amc = make_float2(a.x - c.x, a.y - c.y);
    float2 bpd = make_float2(b.x + d.x, b.y + d.y);
    float2 tbd = make_float2(b.x - d.x, b.y - d.y);
    float2 bmd = make_float2(tbd.y, -tbd.x);
    float2 y0 = make_float2(apc.x + bpd.x, apc.y + bpd.y);
    float2 u1 = make_float2(amc.x + bmd.x, amc.y + bmd.y);
    float2 u2 = make_float2(apc.x - bpd.x, apc.y - bpd.y);
    float2 u3 = make_float2(amc.x - bmd.x, amc.y - bmd.y);
    int j = i + 3*p*s;
    dst[base + j]       = y0;
    dst[base + j + s]   = make_float2(fmaf(u1.x,w1.x,-u1.y*w1.y), fmaf(u1.x,w1.y, u1.y*w1.x));
    dst[base + j + 2*s] = make_float2(fmaf(u2.x,w2.x,-u2.y*w2.y), fmaf(u2.x,w2.y, u2.y*w2.x));
    dst[base + j + 3*s] = make_float2(fmaf(u3.x,w3.x,-u3.y*w3.y), fmaf(u3.x,w3.y, u3.y*w3.x));
}

// forward final radix-2 fused with conj pointwise product
__global__ void fft2_pointwise_kernel()
{
    int i = blockIdx.x*blockDim.x + threadIdx.x;
    int arr = blockIdx.y;
    const float2* d  = g_fftB + (size_t)arr * FFT_M;
    const float2* cc = g_fftB + (size_t)(64 + arr) * FFT_M;
    float2 a = d[i],  b = d[i + 16384];
    float2 ac = cc[i], bc = cc[i + 16384];
    float2 d0 = make_float2(a.x + b.x, a.y + b.y);
    float2 d1 = make_float2(a.x - b.x, a.y - b.y);
    float2 c0 = make_float2(ac.x + bc.x, ac.y + bc.y);
    float2 c1 = make_float2(ac.x - bc.x, ac.y - bc.y);
    float2* o = g_fftA + (size_t)arr * FFT_M;
    o[i]         = make_float2(d0.x*c0.x - d0.y*c0.y, -(d0.x*c0.y + d0.y*c0.x));
    o[i + 16384] = make_float2(d1.x*c1.x - d1.y*c1.y, -(d1.x*c1.y + d1.y*c1.x));
}

// inverse final radix-2 fused with magnitude/log1p
__global__ void fft2_finalize_kernel(const int* __restrict__ lengths)
{
    int i = blockIdx.x*blockDim.x + threadIdx.x;
    int arr = blockIdx.y;
    int K = lengths[arr] / 2 + 1;
    if (i >= K) return;
    const float2* d = g_fftB + (size_t)arr * FFT_M;
    float2 a = d[i], b = d[i + 16384];
    float2 s = make_float2(a.x + b.x, a.y + b.y);
    g_spec[(size_t)arr * 8448 + i] = log1pf(sqrtf(s.x*s.x + s.y*s.y) * (1.0f/32768.0f));
}

__global__ void apool_kernel(const int* __restrict__ lengths)
{
    int i = blockIdx.x, j = threadIdx.x;
    int K = lengths[i]/2 + 1;
    int s0 = (j*K) >> 8;
    int e0 = ((j+1)*K + 255) >> 8;
    const float* sp = g_spec + (size_t)i*8448;
    float s = 0.f;
    for (int t = s0; t < e0; t++) s += sp[t];
    g_spectrum[i*256 + j] = s / (float)(e0 - s0);
}

// =============== small GEMMs ===============
__global__ void freqlin_kernel(const float* __restrict__ fw, const float* __restrict__ fb)
{
    int i = blockIdx.x, h = threadIdx.x;
    __shared__ float sp[256];
    for (int f = h; f < 256; f += 128) sp[f] = g_spectrum[i*256 + f];
    __syncthreads();
    float acc = fb[h];
    const float* wr = fw + (size_t)h*256;
    for (int f = 0; f < 256; f++) acc = fmaf(sp[f], wr[f], acc);
    g_freqvec[i*128 + h] = fmaxf(acc, 0.f);
}

__global__ void head_kernel(const float* __restrict__ w0, const float* __restrict__ b0,
                            const float* __restrict__ w1, const float* __restrict__ b1,
                            float* __restrict__ out)
{
    int b = blockIdx.x, tid = threadIdx.x;
    __shared__ float fused[384];
    __shared__ float hid[128];
    for (int j = tid; j < 384; j += 128)
        fused[j] = (j < 256) ? g_timevec[b*256 + j] : g_freqvec[b*128 + (j - 256)];
    __syncthreads();
    float acc = b0[tid];
    const float* wr = w0 + (size_t)tid*384;
    for (int j = 0; j < 384; j++) acc = fmaf(fused[j], wr[j], acc);
    hid[tid] = fmaxf(acc, 0.f);
    __syncthreads();
    int wid = tid >> 5, lane = tid & 31;
    float s = 0.f;
    for (int t = lane; t < 128; t += 32) s += hid[t] * w1[wid*128 + t];
    #pragma unroll
    for (int off = 16; off; off >>= 1) s += __shfl_down_sync(0xffffffffu, s, off);
    if (lane == 0) out[b*4 + wid] = s + b1[wid];
}

// =============== launch ===============
extern "C" void kernel_launch(void* const* d_in, const int* in_sizes, int n_in,
                              void* d_out, int out_size)
{
    const float* x   = (const float*)d_in[0];
    const int*   len = (const int*)  d_in[1];
    const float *cw0 = (const float*)d_in[2],  *cb0 = (const float*)d_in[3];
    const float *g0  = (const float*)d_in[4],  *be0 = (const float*)d_in[5];
    const float *m0  = (const float*)d_in[6],  *v0  = (const float*)d_in[7];
    const float *cw1 = (const float*)d_in[8],  *cb1 = (const float*)d_in[9];
    const float *g1  = (const float*)d_in[10], *be1 = (const float*)d_in[11];
    const float *m1  = (const float*)d_in[12], *v1  = (const float*)d_in[13];
    const float *cw2 = (const float*)d_in[14], *cb2 = (const float*)d_in[15];
    const float *g2  = (const float*)d_in[16], *be2 = (const float*)d_in[17];
    const float *m2  = (const float*)d_in[18], *v2  = (const float*)d_in[19];
    const float *fw  = (const float*)d_in[20], *fb  = (const float*)d_in[21];
    const float *hw0 = (const float*)d_in[22], *hb0 = (const float*)d_in[23];
    const float *hw1 = (const float*)d_in[24], *hb1 = (const float*)d_in[25];
    float* out = (float*)d_out;

    const int SMEM_CONV = 67584;
    cudaFuncSetAttribute(convmma_kernel<64,128,8192,0>, cudaFuncAttributeMaxDynamicSharedMemorySize, SMEM_CONV);
    cudaFuncSetAttribute(convmma_kernel<128,256,4096,1>, cudaFuncAttributeMaxDynamicSharedMemorySize, SMEM_CONV);

    __half *wa2, *wa3;
    cudaGetSymbolAddress((void**)&wa2, g_wA2);
    cudaGetSymbolAddress((void**)&wa3, g_wA3);
    prep_w_kernel<64, 1><<<(1*4*128*96  + 255)/256, 256>>>(cw1, wa2);
    prep_w_kernel<128,2><<<(2*8*128*96 + 255)/256, 256>>>(cw2, wa3);

    // time branch
    conv1_kernel<<<dim3(32,8,64), 256>>>(x, cw0, cb0, g0, be0, m0, v0);
    convmma_kernel<64,128,8192,0><<<dim3(64,1,64), 256, SMEM_CONV>>>(cb1, g1, be1, m1, v1);
    convmma_kernel<128,256,4096,1><<<dim3(32,2,64), 256, SMEM_CONV>>>(cb2, g2, be2, m2, v2);
    timepool_kernel<<<dim3(256,64), 128>>>(len);

    // frequency branch
    fft_twiddle_kernel<<<64, 256>>>();
    fft_build_kernel<<<dim3(128,64), 256>>>(x, len);
    int sel = 0;
    for (int st = 0; st < 7; st++) {
        int n = FFT_M >> (2*st);
        fft4_stage_kernel<<<dim3(32,128), 256>>>(sel, 2*st, 32768 - n);
        sel ^= 1;
    }
    fft2_pointwise_kernel<<<dim3(64,64), 256>>>();
    sel = 0;
    for (int st = 0; st < 7; st++) {
        int n = FFT_M >> (2*st);
        fft4_stage_kernel<<<dim3(32,64), 256>>>(sel, 2*st, 32768 - n);
        sel ^= 1;
    }
    fft2_finalize_kernel<<<dim3(33,64), 256>>>(len);
    apool_kernel<<<64, 256>>>(len);
    freqlin_kernel<<<64, 128>>>(fw, fb);

    head_kernel<<<64, 128>>>(hw0, hb0, hw1, hb1, out);
}

// round 13
// speedup vs baseline: 7.0747x; 1.0150x over previous
#include <cuda_runtime.h>
#include <cuda_fp16.h>
#include <cstdint>
#include <cstddef>

#define PI_F 3.14159265358979323846f
#define FFT_M 32768

// ---- static scratch ----
__device__ uint4  g_h1h4[4202496], g_h1o4[4202496];   // [64][64][8208] halves
__device__ uint4  g_h2h4[4210688], g_h2o4[4210688];   // [64][128][4112] halves
__device__ float  g_h3[64u*256u*2048u];
__device__ float2 g_fftA[128u*32768u];
__device__ float2 g_fftB[128u*32768u];
__device__ float2 g_tw[32768];
__device__ float  g_spec[64u*8448u];
__device__ float  g_spectrum[64u*256u];
__device__ float  g_timevec[64u*256u];
__device__ float  g_freqvec[64u*128u];
__device__ __half g_wA2[1u*4u*128u*96u];
__device__ __half g_wA3[2u*8u*128u*96u];

// ---- helpers ----
__device__ __forceinline__ uint32_t smem_u32(const void* p) {
    uint32_t a; asm("{ .reg .u64 t; cvta.to.shared.u64 t, %1; cvt.u32.u64 %0, t; }" : "=r"(a) : "l"(p));
    return a;
}
__device__ __forceinline__ void mma16816(float* c, const uint32_t* a, uint32_t b0, uint32_t b1) {
    asm volatile("mma.sync.aligned.m16n8k16.row.col.f32.f16.f16.f32 "
        "{%0,%1,%2,%3}, {%4,%5,%6,%7}, {%8,%9}, {%0,%1,%2,%3};"
        : "+f"(c[0]), "+f"(c[1]), "+f"(c[2]), "+f"(c[3])
        : "r"(a[0]), "r"(a[1]), "r"(a[2]), "r"(a[3]), "r"(b0), "r"(b1));
}
__device__ __forceinline__ void ldmA(uint32_t* a, uint32_t addr) {
    asm volatile("ldmatrix.sync.aligned.m8n8.x4.shared.b16 {%0,%1,%2,%3}, [%4];"
        : "=r"(a[0]), "=r"(a[1]), "=r"(a[2]), "=r"(a[3]) : "r"(addr));
}
__device__ __forceinline__ float2 cmul(float2 a, float2 b) {
    return make_float2(a.x*b.x - a.y*b.y, a.x*b.y + a.y*b.x);
}
#define CP_ASYNC16(dst, src) asm volatile("cp.async.cg.shared.global [%0], [%1], 16;" :: "r"(dst), "l"(src))
#define CP_ASYNC4(dst, src)  asm volatile("cp.async.ca.shared.global [%0], [%1], 4;"  :: "r"(dst), "l"(src))
#define CP_COMMIT() asm volatile("cp.async.commit_group;")
#define CP_WAIT0()  asm volatile("cp.async.wait_group 0;" ::: "memory")

// B parity-block offset: 1156 words (4624 B) — 16B-aligned, ≡4 mod 32 banks (kills 2-way conflict)
#define BPAR_W 1156
#define BPAR_B 4624
#define BBUF_B 9248

// ---- weight prep ----
template<int CIN, int MT>
__global__ void prep_w_kernel(const float* __restrict__ w, __half* __restrict__ dst)
{
    const int NCH = CIN / 16;
    int total = MT * NCH * 128 * 96;
    int idx = blockIdx.x * 256 + threadIdx.x;
    if (idx >= total) return;
    int kl = idx % 96;
    int m  = (idx / 96) % 128;
    int ch = (idx / (96 * 128)) % NCH;
    int mt = idx / (96 * 128 * NCH);
    int cl = kl / 6, j = kl - 6 * cl;
    float wv = (j < 5) ? w[(((size_t)(mt * 128 + m)) * CIN + ch * 16 + cl) * 5 + j] : 0.f;
    dst[idx] = __float2half_rn(wv);
}

// ---- conv blocks 2/3: fp16 mma 1-pass, direct fp16 cp.async staging, 2 CTA/SM ----
// CTA: 256 thr (8 warps 2Mx4N). Tile M=128 x N=128 conv positions (->64 pooled).
// smem: A[2]@0 (24576 ea), sB[2]@49152 (9248 ea) = 67648 B
template<int CIN, int COUT, int LIN, int WHICH>
__global__ void __launch_bounds__(256, 2)
convmma_kernel(const float* __restrict__ cb, const float* __restrict__ g,
               const float* __restrict__ be, const float* __restrict__ bm,
               const float* __restrict__ bv)
{
    const int NCH  = CIN / 16;
    const int ISTR = WHICH ? 4112 : 8208;
    const int NPT  = LIN / 128;
    const __half* inh = WHICH ? (const __half*)g_h2h4 : (const __half*)g_h1h4;
    const __half* ino = WHICH ? (const __half*)g_h2o4 : (const __half*)g_h1o4;
    const __half* wA  = WHICH ? g_wA3 : g_wA2;
    __half* h2h = (__half*)g_h2h4;
    __half* h2o = (__half*)g_h2o4;

    extern __shared__ __align__(16) char smem[];
    uint32_t sbase = smem_u32(smem);
    int tid = threadIdx.x, wid = tid >> 5, lane = tid & 31;
    int pt = blockIdx.x, mt = blockIdx.y, b = blockIdx.z;
    int warp_m = wid & 1, warp_n = wid >> 1;
    int lrow = lane >> 2;
    int tb = pt * 128 - 2;                    // tb ≡ 6 (mod 8)

    uint32_t aoff[4];
    #pragma unroll
    for (int m2 = 0; m2 < 4; m2++)
        aoff[m2] = (uint32_t)(((warp_m * 64 + m2 * 16 + (lane & 7) + ((lane >> 3) & 1) * 8) * 96
                              + (lane >> 4) * 8) * 2);
    int b0idx[6], b1idx[6];
    #pragma unroll
    for (int ks = 0; ks < 6; ks++) {
        int k0 = ks * 16 + (lane & 3) * 2;
        int c0 = k0 / 6, j0 = k0 - 6 * c0;
        int k1 = k0 + 8;
        int c1 = k1 / 6, j1 = k1 - 6 * c1;
        int t0 = warp_n * 32 + lrow + j0;
        int t1 = warp_n * 32 + lrow + j1;
        b0idx[ks] = (t0 & 1) * BPAR_W + c0 * 72 + 3 + (t0 >> 1);
        b1idx[ks] = (t1 & 1) * BPAR_W + c1 * 72 + 3 + (t1 >> 1);
    }

    float acc[4][4][4];
    #pragma unroll
    for (int i = 0; i < 4; i++)
        #pragma unroll
        for (int n = 0; n < 4; n++)
            #pragma unroll
            for (int q = 0; q < 4; q++) acc[i][n][q] = 0.f;

    #define STAGE_A(CH) do {                                                             \
        const uint4* _as = (const uint4*)(wA + (size_t)(mt * NCH + (CH)) * 128 * 96);    \
        uint32_t _ad = sbase + (((CH) & 1) ? 24576u : 0u);                               \
        for (int _i = tid; _i < 1536; _i += 256) CP_ASYNC16(_ad + _i * 16, _as + _i);    \
    } while (0)
    #define STAGE_B(CH) do {                                                             \
        uint32_t _bb = sbase + 49152u + ((CH) & 1) * (uint32_t)BBUF_B;                   \
        for (int _i = tid; _i < 608; _i += 256) {                                        \
            int _row = _i / 19, _op = _i - _row * 19;                                    \
            int _p = _row >> 4, _c = _row & 15;                                          \
            const __half* _g = (_p ? ino : inh)                                          \
                + ((size_t)b * CIN + (CH) * 16 + _c) * ISTR + 8 + tb;                    \
            uint32_t _d = _bb + _p * (uint32_t)BPAR_B + _c * 288u + 12u;                 \
            if (_op == 0)        CP_ASYNC4(_d, _g);                                      \
            else if (_op <= 16) { int _m = 1 + (_op - 1) * 4; CP_ASYNC16(_d + _m * 4, _g + 2 * _m); } \
            else                { int _m = 64 + (_op - 16);   CP_ASYNC4 (_d + _m * 4, _g + 2 * _m); } \
        }                                                                                \
    } while (0)

    STAGE_A(0); STAGE_B(0); CP_COMMIT();
    CP_WAIT0();
    __syncthreads();

    for (int ch = 0; ch < NCH; ch++) {
        int cur = ch & 1;
        if (ch + 1 < NCH) { STAGE_A(ch + 1); STAGE_B(ch + 1); CP_COMMIT(); }
        {
            uint32_t Aaddr = sbase + (cur ? 24576u : 0u);
            const uint32_t* Bw = (const uint32_t*)(smem + 49152 + cur * BBUF_B);
            #pragma unroll
            for (int ks = 0; ks < 6; ks++) {
                uint32_t afr[4][4];
                #pragma unroll
                for (int m2 = 0; m2 < 4; m2++) ldmA(afr[m2], Aaddr + aoff[m2] + ks * 32);
                const uint32_t* p0 = Bw + b0idx[ks];
                const uint32_t* p1 = Bw + b1idx[ks];
                #pragma unroll
                for (int nt = 0; nt < 4; nt++) {
                    uint32_t bb0 = p0[nt * 4];
                    uint32_t bb1 = p1[nt * 4];
                    #pragma unroll
                    for (int m2 = 0; m2 < 4; m2++)
                        mma16816(acc[m2][nt], afr[m2], bb0, bb1);
                }
            }
        }
        if (ch + 1 < NCH) CP_WAIT0();
        __syncthreads();
    }
    #undef STAGE_A
    #undef STAGE_B

    // epilogue: BN + relu + maxpool2
    int pcol = warp_n * 16 + (lane & 3);
    #pragma unroll
    for (int m2 = 0; m2 < 4; m2++) {
        #pragma unroll
        for (int h = 0; h < 2; h++) {
            int mg = mt * 128 + warp_m * 64 + m2 * 16 + h * 8 + lrow;
            float scv = g[mg] * rsqrtf(bv[mg] + 1e-5f);
            float shv = be[mg] - bm[mg] * scv + cb[mg] * scv;
            #pragma unroll
            for (int nt = 0; nt < 4; nt++) {
                float v0 = acc[m2][nt][2 * h]     * scv + shv;
                float v1 = acc[m2][nt][2 * h + 1] * scv + shv;
                float r = fmaxf(fmaxf(v0, v1), 0.f);
                int P = pt * 64 + pcol + nt * 4;
                if (WHICH == 0) {
                    size_t base = ((size_t)(b * 128 + mg)) * 4112;
                    __half hr = __float2half_rn(r);
                    h2h[base + 8 + P] = hr;
                    h2o[base + 7 + P] = hr;
                } else {
                    g_h3[((size_t)b * 256 + mg) * 2048 + P] = r;
                }
            }
        }
    }
    if (WHICH == 0) {
        if (pt == 0) {
            for (int idx = tid; idx < 128 * 15; idx += 256) {
                int row = idx / 15, s = idx - row * 15;
                size_t base = ((size_t)(b * 128 + mt * 128 + row)) * 4112;
                if (s < 8) h2h[base + s] = __float2half(0.f);
                else       h2o[base + (s - 8)] = __float2half(0.f);
            }
        }
        if (pt == NPT - 1) {
            for (int idx = tid; idx < 128 * 17; idx += 256) {
                int row = idx / 17, s = idx - row * 17;
                size_t base = ((size_t)(b * 128 + mt * 128 + row)) * 4112;
                if (s < 8) h2h[base + 4104 + s] = __float2half(0.f);
                else       h2o[base + 4103 + (s - 8)] = __float2half(0.f);
            }
        }
    }
}

// =============== conv1 ===============
__global__ void conv1_kernel(const float* __restrict__ x, const float* __restrict__ w,
                             const float* __restrict__ cb, const float* __restrict__ g,
                             const float* __restrict__ be, const float* __restrict__ m,
                             const float* __restrict__ v)
{
    __shared__ float sx[519];
    __shared__ float swv[56];
    __shared__ float sbn[16];
    int tid = threadIdx.x;
    int pb  = blockIdx.x * 256;
    int c8  = blockIdx.y * 8;
    int b   = blockIdx.z;
    __half* h1h = (__half*)g_h1h4;
    __half* h1o = (__half*)g_h1o4;
    const float* xb = x + (size_t)b * 16384;
    for (int idx = tid; idx < 519; idx += 256) {
        int t = 2*pb - 3 + idx;
        sx[idx] = (t >= 0 && t < 16384) ? xb[t] : 0.f;
    }
    if (tid < 56) swv[tid] = w[c8*7 + tid];
    if (tid < 8) {
        int c = c8 + tid;
        float sc = g[c] * rsqrtf(v[c] + 1e-5f);
        sbn[tid] = sc;
        sbn[8 + tid] = be[c] - m[c]*sc + cb[c]*sc;
    }
    __syncthreads();
    float xv[8];
    #pragma unroll
    for (int j = 0; j < 8; j++) xv[j] = sx[2*tid + j];
    int P = pb + tid;
    #pragma unroll
    for (int c = 0; c < 8; c++) {
        float y0 = 0.f, y1 = 0.f;
        #pragma unroll
        for (int j = 0; j < 7; j++) {
            float wc = swv[c*7 + j];
            y0 = fmaf(wc, xv[j],   y0);
            y1 = fmaf(wc, xv[j+1], y1);
        }
        float sc = sbn[c], sh = sbn[8 + c];
        float r = fmaxf(fmaxf(y0*sc + sh, y1*sc + sh), 0.f);
        size_t base = ((size_t)(b*64 + c8 + c)) * 8208;
        __half hr = __float2half_rn(r);
        h1h[base + 8 + P] = hr;
        h1o[base + 7 + P] = hr;
    }
    if (pb == 0) {
        for (int idx = tid; idx < 8 * 15; idx += 256) {
            int c = idx / 15, s = idx - c * 15;
            size_t base = ((size_t)(b*64 + c8 + c)) * 8208;
            if (s < 8) h1h[base + s] = __float2half(0.f);
            else       h1o[base + (s - 8)] = __float2half(0.f);
        }
    }
    if (pb == 8192 - 256) {
        for (int idx = tid; idx < 8 * 17; idx += 256) {
            int c = idx / 17, s = idx - c * 17;
            size_t base = ((size_t)(b*64 + c8 + c)) * 8208;
            if (s < 8) h1h[base + 8200 + s] = __float2half(0.f);
            else       h1o[base + 8199 + (s - 8)] = __float2half(0.f);
        }
    }
}

// =============== masked global average over time ===============
__global__ void timepool_kernel(const int* __restrict__ lengths)
{
    int c = blockIdx.x, b = blockIdx.y, tid = threadIdx.x;
    int plen = lengths[b] >> 3; if (plen < 1) plen = 1;
    const float* p = g_h3 + ((size_t)b*256 + c)*2048;
    float s = 0.f;
    for (int t = tid; t < plen; t += 128) s += p[t];
    __shared__ float red[4];
    #pragma unroll
    for (int off = 16; off; off >>= 1) s += __shfl_down_sync(0xffffffffu, s, off);
    if ((tid & 31) == 0) red[tid >> 5] = s;
    __syncthreads();
    if (tid == 0) g_timevec[b*256 + c] = (red[0]+red[1]+red[2]+red[3]) / (float)plen;
}

// =============== FFT: Bluestein, M=32768 = 8^5, radix-8 Stockham ===============
__global__ void fft_twiddle_kernel()
{
    int p = blockIdx.x*blockDim.x + threadIdx.x;
    int off = 0;
    #pragma unroll
    for (int st = 0; st < 15; st++) {
        int n = FFT_M >> st, mm = n >> 1;
        if (p < mm) {
            float sv, cv; sincosf(-2.f*PI_F*(float)p/(float)n, &sv, &cv);
            g_tw[off + p] = make_float2(cv, sv);
        }
        off += mm;
    }
}

__global__ void fft_build_kernel(const float* __restrict__ x, const int* __restrict__ lengths)
{
    int n = blockIdx.x*blockDim.x + threadIdx.x;
    int i = blockIdx.y;
    int L = lengths[i];
    int mm = (n <= FFT_M - n) ? n : FFT_M - n;
    float2 a  = make_float2(0.f, 0.f);
    float2 bb = make_float2(0.f, 0.f);
    if (mm < L) {
        unsigned r = ((unsigned)mm * (unsigned)mm) % (unsigned)(2*L);
        float sv, cv; sincosf(PI_F * (float)r / (float)L, &sv, &cv);
        bb = make_float2(cv, sv);
        if (n < L) {
            float xv = x[(size_t)i*16384 + n];
            a = make_float2(xv*cv, -xv*sv);
        }
    }
    g_fftA[(size_t)i*FFT_M + n]      = a;
    g_fftA[(size_t)(64+i)*FFT_M + n] = bb;
}

// one radix-8 Stockham stage: sShift = 3*st, n = M >> 3st, twOff = 32768 - n
__global__ void fft8_stage_kernel(int sel, int sShift, int twOff)
{
    const float2* __restrict__ src = sel ? g_fftB : g_fftA;
    float2* __restrict__ dst       = sel ? g_fftA : g_fftB;
    int i = blockIdx.x*blockDim.x + threadIdx.x;   // 0..4095
    size_t base = (size_t)blockIdx.y * FFT_M;
    int p = i >> sShift;
    int s = 1 << sShift;
    float2 x0 = src[base + i];
    float2 x1 = src[base + i + 4096];
    float2 x2 = src[base + i + 8192];
    float2 x3 = src[base + i + 12288];
    float2 x4 = src[base + i + 16384];
    float2 x5 = src[base + i + 20480];
    float2 x6 = src[base + i + 24576];
    float2 x7 = src[base + i + 28672];
    float2 t0 = make_float2(x0.x + x4.x, x0.y + x4.y);
    float2 t1 = make_float2(x0.x - x4.x, x0.y - x4.y);
    float2 t2 = make_float2(x2.x + x6.x, x2.y + x6.y);
    float2 t3 = make_float2(x2.y - x6.y, -(x2.x - x6.x));
    float2 E0 = make_float2(t0.x + t2.x, t0.y + t2.y);
    float2 E1 = make_float2(t1.x + t3.x, t1.y + t3.y);
    float2 E2 = make_float2(t0.x - t2.x, t0.y - t2.y);
    float2 E3 = make_float2(t1.x - t3.x, t1.y - t3.y);
    float2 u0 = make_float2(x1.x + x5.x, x1.y + x5.y);
    float2 u1 = make_float2(x1.x - x5.x, x1.y - x5.y);
    float2 u2 = make_float2(x3.x + x7.x, x3.y + x7.y);
    float2 u3 = make_float2(x3.y - x7.y, -(x3.x - x7.x));
    float2 O0 = make_float2(u0.x + u2.x, u0.y + u2.y);
    float2 O1 = make_float2(u1.x + u3.x, u1.y + u3.y);
    float2 O2 = make_float2(u0.x - u2.x, u0.y - u2.y);
    float2 O3 = make_float2(u1.x - u3.x, u1.y - u3.y);
    const float r = 0.70710678118654752f;
    float2 P0 = O0;
    float2 P1 = make_float2(r*(O1.x + O1.y), r*(O1.y - O1.x));
    float2 P2 = make_float2(O2.y, -O2.x);
    float2 P3 = make_float2(r*(O3.y - O3.x), -r*(O3.x + O3.y));
    float2 y0 = make_float2(E0.x + P0.x, E0.y + P0.y);
    float2 y1 = make_float2(E1.x + P1.x, E1.y + P1.y);
    float2 y2 = make_float2(E2.x + P2.x, E2.y + P2.y);
    float2 y3 = make_float2(E3.x + P3.x, E3.y + P3.y);
    float2 y4 = make_float2(E0.x - P0.x, E0.y - P0.y);
    float2 y5 = make_float2(E1.x - P1.x, E1.y - P1.y);
    float2 y6 = make_float2(E2.x - P2.x, E2.y - P2.y);
    float2 y7 = make_float2(E3.x - P3.x, E3.y - P3.y);
    float2 w1 = g_tw[twOff + p];
    float2 w2 = g_tw[twOff + 2*p];
    float2 w4 = g_tw[twOff + 4*p];
    float2 w3 = cmul(w1, w2);
    float2 w5 = cmul(w1, w4);
    float2 w6 = cmul(w2, w4);
    float2 w7 = cmul(w3, w4);
    size_t j = base + i + (size_t)7*p*s;
    dst[j]       = y0;
    dst[j + s]   = cmul(y1, w1);
    dst[j + 2*s] = cmul(y2, w2);
    dst[j + 3*s] = cmul(y3, w3);
    dst[j + 4*s] = cmul(y4, w4);
    dst[j + 5*s] = cmul(y5, w5);
    dst[j + 6*s] = cmul(y6, w6);
    dst[j + 7*s] = cmul(y7, w7);
}

// conj pointwise product: g_fftB (data, chirp) -> g_fftA
__global__ void fft_pointwise_kernel()
{
    int n = blockIdx.x*blockDim.x + threadIdx.x;
    int i = blockIdx.y;
    float2 A = g_fftB[(size_t)i*FFT_M + n];
    float2 B = g_fftB[(size_t)(64+i)*FFT_M + n];
    g_fftA[(size_t)i*FFT_M + n] =
        make_float2(A.x*B.x - A.y*B.y, -(A.x*B.y + A.y*B.x));
}

// magnitude/log1p: reads g_fftB
__global__ void fft_finalize_kernel(const int* __restrict__ lengths)
{
    int k = blockIdx.x*blockDim.x + threadIdx.x;
    int arr = blockIdx.y;
    int K = lengths[arr] / 2 + 1;
    if (k >= K) return;
    float2 c = g_fftB[(size_t)arr * FFT_M + k];
    g_spec[(size_t)arr * 8448 + k] = log1pf(sqrtf(c.x*c.x + c.y*c.y) * (1.0f/32768.0f));
}

__global__ void apool_kernel(const int* __restrict__ lengths)
{
    int i = blockIdx.x, j = threadIdx.x;
    int K = lengths[i]/2 + 1;
    int s0 = (j*K) >> 8;
    int e0 = ((j+1)*K + 255) >> 8;
    const float* sp = g_spec + (size_t)i*8448;
    float s = 0.f;
    for (int t = s0; t < e0; t++) s += sp[t];
    g_spectrum[i*256 + j] = s / (float)(e0 - s0);
}

// =============== small GEMMs ===============
__global__ void freqlin_kernel(const float* __restrict__ fw, const float* __restrict__ fb)
{
    int i = blockIdx.x, h = threadIdx.x;
    __shared__ float sp[256];
    for (int f = h; f < 256; f += 128) sp[f] = g_spectrum[i*256 + f];
    __syncthreads();
    float acc = fb[h];
    const float* wr = fw + (size_t)h*256;
    for (int f = 0; f < 256; f++) acc = fmaf(sp[f], wr[f], acc);
    g_freqvec[i*128 + h] = fmaxf(acc, 0.f);
}

__global__ void head_kernel(const float* __restrict__ w0, const float* __restrict__ b0,
                            const float* __restrict__ w1, const float* __restrict__ b1,
                            float* __restrict__ out)
{
    int b = blockIdx.x, tid = threadIdx.x;
    __shared__ float fused[384];
    __shared__ float hid[128];
    for (int j = tid; j < 384; j += 128)
        fused[j] = (j < 256) ? g_timevec[b*256 + j] : g_freqvec[b*128 + (j - 256)];
    __syncthreads();
    float acc = b0[tid];
    const float* wr = w0 + (size_t)tid*384;
    for (int j = 0; j < 384; j++) acc = fmaf(fused[j], wr[j], acc);
    hid[tid] = fmaxf(acc, 0.f);
    __syncthreads();
    int wid = tid >> 5, lane = tid & 31;
    float s = 0.f;
    for (int t = lane; t < 128; t += 32) s += hid[t] * w1[wid*128 + t];
    #pragma unroll
    for (int off = 16; off; off >>= 1) s += __shfl_down_sync(0xffffffffu, s, off);
    if (lane == 0) out[b*4 + wid] = s + b1[wid];
}

// =============== launch ===============
extern "C" void kernel_launch(void* const* d_in, const int* in_sizes, int n_in,
                              void* d_out, int out_size)
{
    const float* x   = (const float*)d_in[0];
    const int*   len = (const int*)  d_in[1];
    const float *cw0 = (const float*)d_in[2],  *cb0 = (const float*)d_in[3];
    const float *g0  = (const float*)d_in[4],  *be0 = (const float*)d_in[5];
    const float *m0  = (const float*)d_in[6],  *v0  = (const float*)d_in[7];
    const float *cw1 = (const float*)d_in[8],  *cb1 = (const float*)d_in[9];
    const float *g1  = (const float*)d_in[10], *be1 = (const float*)d_in[11];
    const float *m1  = (const float*)d_in[12], *v1  = (const float*)d_in[13];
    const float *cw2 = (const float*)d_in[14], *cb2 = (const float*)d_in[15];
    const float *g2  = (const float*)d_in[16], *be2 = (const float*)d_in[17];
    const float *m2  = (const float*)d_in[18], *v2  = (const float*)d_in[19];
    const float *fw  = (const float*)d_in[20], *fb  = (const float*)d_in[21];
    const float *hw0 = (const float*)d_in[22], *hb0 = (const float*)d_in[23];
    const float *hw1 = (const float*)d_in[24], *hb1 = (const float*)d_in[25];
    float* out = (float*)d_out;

    const int SMEM_CONV = 49152 + 2 * BBUF_B;   // 67648
    cudaFuncSetAttribute(convmma_kernel<64,128,8192,0>, cudaFuncAttributeMaxDynamicSharedMemorySize, SMEM_CONV);
    cudaFuncSetAttribute(convmma_kernel<128,256,4096,1>, cudaFuncAttributeMaxDynamicSharedMemorySize, SMEM_CONV);

    __half *wa2, *wa3;
    cudaGetSymbolAddress((void**)&wa2, g_wA2);
    cudaGetSymbolAddress((void**)&wa3, g_wA3);
    prep_w_kernel<64, 1><<<(1*4*128*96  + 255)/256, 256>>>(cw1, wa2);
    prep_w_kernel<128,2><<<(2*8*128*96 + 255)/256, 256>>>(cw2, wa3);

    // time branch
    conv1_kernel<<<dim3(32,8,64), 256>>>(x, cw0, cb0, g0, be0, m0, v0);
    convmma_kernel<64,128,8192,0><<<dim3(64,1,64), 256, SMEM_CONV>>>(cb1, g1, be1, m1, v1);
    convmma_kernel<128,256,4096,1><<<dim3(32,2,64), 256, SMEM_CONV>>>(cb2, g2, be2, m2, v2);
    timepool_kernel<<<dim3(256,64), 128>>>(len);

    // frequency branch: 5 radix-8 stages each way
    fft_twiddle_kernel<<<64, 256>>>();
    fft_build_kernel<<<dim3(128,64), 256>>>(x, len);
    int sel = 0;
    for (int st = 0; st < 5; st++) {
        int n = FFT_M >> (3*st);
        fft8_stage_kernel<<<dim3(16,128), 256>>>(sel, 3*st, 32768 - n);
        sel ^= 1;
    }                                                  // ends in g_fftB
    fft_pointwise_kernel<<<dim3(128,64), 256>>>();     // B -> A
    sel = 0;
    for (int st = 0; st < 5; st++) {
        int n = FFT_M >> (3*st);
        fft8_stage_kernel<<<dim3(16,64), 256>>>(sel, 3*st, 32768 - n);
        sel ^= 1;
    }                                                  // ends in g_fftB
    fft_finalize_kernel<<<dim3(33,64), 256>>>(len);
    apool_kernel<<<64, 256>>>(len);
    freqlin_kernel<<<64, 128>>>(fw, fb);

    head_kernel<<<64, 128>>>(hw0, hb0, hw1, hb1, out);
}

// round 14
// speedup vs baseline: 7.4692x; 1.0558x over previous
#include <cuda_runtime.h>
#include <cuda_fp16.h>
#include <cstdint>
#include <cstddef>

#define PI_F 3.14159265358979323846f
#define FFT_M 32768

// ---- static scratch ----
__device__ uint4  g_h1h4[4202496], g_h1o4[4202496];   // [64][64][8208] halves
__device__ uint4  g_h2h4[4210688], g_h2o4[4210688];   // [64][128][4112] halves
__device__ float  g_tpart[64u*256u*32u];              // masked time-pool partials [b][ch][pt]
__device__ float2 g_fftA[128u*32768u];
__device__ float2 g_fftB[128u*32768u];
__device__ float2 g_tw[32768];
__device__ float  g_spec[64u*8448u];
__device__ float  g_spectrum[64u*256u];
__device__ float  g_timevec[64u*256u];
__device__ float  g_freqvec[64u*128u];
__device__ __half g_wA2[1u*4u*128u*96u];
__device__ __half g_wA3[2u*8u*128u*96u];

// ---- helpers ----
__device__ __forceinline__ uint32_t smem_u32(const void* p) {
    uint32_t a; asm("{ .reg .u64 t; cvta.to.shared.u64 t, %1; cvt.u32.u64 %0, t; }" : "=r"(a) : "l"(p));
    return a;
}
__device__ __forceinline__ void mma16816(float* c, const uint32_t* a, uint32_t b0, uint32_t b1) {
    asm volatile("mma.sync.aligned.m16n8k16.row.col.f32.f16.f16.f32 "
        "{%0,%1,%2,%3}, {%4,%5,%6,%7}, {%8,%9}, {%0,%1,%2,%3};"
        : "+f"(c[0]), "+f"(c[1]), "+f"(c[2]), "+f"(c[3])
        : "r"(a[0]), "r"(a[1]), "r"(a[2]), "r"(a[3]), "r"(b0), "r"(b1));
}
__device__ __forceinline__ void ldmA(uint32_t* a, uint32_t addr) {
    asm volatile("ldmatrix.sync.aligned.m8n8.x4.shared.b16 {%0,%1,%2,%3}, [%4];"
        : "=r"(a[0]), "=r"(a[1]), "=r"(a[2]), "=r"(a[3]) : "r"(addr));
}
__device__ __forceinline__ float2 cmul(float2 a, float2 b) {
    return make_float2(a.x*b.x - a.y*b.y, a.x*b.y + a.y*b.x);
}
#define CP_ASYNC16(dst, src) asm volatile("cp.async.cg.shared.global [%0], [%1], 16;" :: "r"(dst), "l"(src))
#define CP_ASYNC4(dst, src)  asm volatile("cp.async.ca.shared.global [%0], [%1], 4;"  :: "r"(dst), "l"(src))
#define CP_COMMIT() asm volatile("cp.async.commit_group;")
#define CP_WAIT0()  asm volatile("cp.async.wait_group 0;" ::: "memory")

#define BPAR_W 1156
#define BPAR_B 4624
#define BBUF_B 9248

// ---- weight prep ----
template<int CIN, int MT>
__global__ void prep_w_kernel(const float* __restrict__ w, __half* __restrict__ dst)
{
    const int NCH = CIN / 16;
    int total = MT * NCH * 128 * 96;
    int idx = blockIdx.x * 256 + threadIdx.x;
    if (idx >= total) return;
    int kl = idx % 96;
    int m  = (idx / 96) % 128;
    int ch = (idx / (96 * 128)) % NCH;
    int mt = idx / (96 * 128 * NCH);
    int cl = kl / 6, j = kl - 6 * cl;
    float wv = (j < 5) ? w[(((size_t)(mt * 128 + m)) * CIN + ch * 16 + cl) * 5 + j] : 0.f;
    dst[idx] = __float2half_rn(wv);
}

// ---- conv blocks 2/3: fp16 mma 1-pass, direct fp16 cp.async staging, 2 CTA/SM ----
// CTA: 256 thr (8 warps 2Mx4N). Tile M=128 x N=128 conv positions (->64 pooled).
// WHICH==1 fuses BN+relu+maxpool+masked time-pool partial sums (no g_h3 array at all).
template<int CIN, int COUT, int LIN, int WHICH>
__global__ void __launch_bounds__(256, 2)
convmma_kernel(const float* __restrict__ cb, const float* __restrict__ g,
               const float* __restrict__ be, const float* __restrict__ bm,
               const float* __restrict__ bv, const int* __restrict__ lengths)
{
    const int NCH  = CIN / 16;
    const int ISTR = WHICH ? 4112 : 8208;
    const int NPT  = LIN / 128;
    const __half* inh = WHICH ? (const __half*)g_h2h4 : (const __half*)g_h1h4;
    const __half* ino = WHICH ? (const __half*)g_h2o4 : (const __half*)g_h1o4;
    const __half* wA  = WHICH ? g_wA3 : g_wA2;
    __half* h2h = (__half*)g_h2h4;
    __half* h2o = (__half*)g_h2o4;

    extern __shared__ __align__(16) char smem[];
    uint32_t sbase = smem_u32(smem);
    int tid = threadIdx.x, wid = tid >> 5, lane = tid & 31;
    int pt = blockIdx.x, mt = blockIdx.y, b = blockIdx.z;
    int warp_m = wid & 1, warp_n = wid >> 1;
    int lrow = lane >> 2;
    int tb = pt * 128 - 2;                    // tb ≡ 6 (mod 8)

    uint32_t aoff[4];
    #pragma unroll
    for (int m2 = 0; m2 < 4; m2++)
        aoff[m2] = (uint32_t)(((warp_m * 64 + m2 * 16 + (lane & 7) + ((lane >> 3) & 1) * 8) * 96
                              + (lane >> 4) * 8) * 2);
    int b0idx[6], b1idx[6];
    #pragma unroll
    for (int ks = 0; ks < 6; ks++) {
        int k0 = ks * 16 + (lane & 3) * 2;
        int c0 = k0 / 6, j0 = k0 - 6 * c0;
        int k1 = k0 + 8;
        int c1 = k1 / 6, j1 = k1 - 6 * c1;
        int t0 = warp_n * 32 + lrow + j0;
        int t1 = warp_n * 32 + lrow + j1;
        b0idx[ks] = (t0 & 1) * BPAR_W + c0 * 72 + 3 + (t0 >> 1);
        b1idx[ks] = (t1 & 1) * BPAR_W + c1 * 72 + 3 + (t1 >> 1);
    }

    float acc[4][4][4];
    #pragma unroll
    for (int i = 0; i < 4; i++)
        #pragma unroll
        for (int n = 0; n < 4; n++)
            #pragma unroll
            for (int q = 0; q < 4; q++) acc[i][n][q] = 0.f;

    #define STAGE_A(CH) do {                                                             \
        const uint4* _as = (const uint4*)(wA + (size_t)(mt * NCH + (CH)) * 128 * 96);    \
        uint32_t _ad = sbase + (((CH) & 1) ? 24576u : 0u);                               \
        for (int _i = tid; _i < 1536; _i += 256) CP_ASYNC16(_ad + _i * 16, _as + _i);    \
    } while (0)
    #define STAGE_B(CH) do {                                                             \
        uint32_t _bb = sbase + 49152u + ((CH) & 1) * (uint32_t)BBUF_B;                   \
        for (int _i = tid; _i < 608; _i += 256) {                                        \
            int _row = _i / 19, _op = _i - _row * 19;                                    \
            int _p = _row >> 4, _c = _row & 15;                                          \
            const __half* _g = (_p ? ino : inh)                                          \
                + ((size_t)b * CIN + (CH) * 16 + _c) * ISTR + 8 + tb;                    \
            uint32_t _d = _bb + _p * (uint32_t)BPAR_B + _c * 288u + 12u;                 \
            if (_op == 0)        CP_ASYNC4(_d, _g);                                      \
            else if (_op <= 16) { int _m = 1 + (_op - 1) * 4; CP_ASYNC16(_d + _m * 4, _g + 2 * _m); } \
            else                { int _m = 64 + (_op - 16);   CP_ASYNC4 (_d + _m * 4, _g + 2 * _m); } \
        }                                                                                \
    } while (0)

    STAGE_A(0); STAGE_B(0); CP_COMMIT();
    CP_WAIT0();
    __syncthreads();

    for (int ch = 0; ch < NCH; ch++) {
        int cur = ch & 1;
        if (ch + 1 < NCH) { STAGE_A(ch + 1); STAGE_B(ch + 1); CP_COMMIT(); }
        {
            uint32_t Aaddr = sbase + (cur ? 24576u : 0u);
            const uint32_t* Bw = (const uint32_t*)(smem + 49152 + cur * BBUF_B);
            #pragma unroll
            for (int ks = 0; ks < 6; ks++) {
                uint32_t afr[4][4];
                #pragma unroll
                for (int m2 = 0; m2 < 4; m2++) ldmA(afr[m2], Aaddr + aoff[m2] + ks * 32);
                const uint32_t* p0 = Bw + b0idx[ks];
                const uint32_t* p1 = Bw + b1idx[ks];
                #pragma unroll
                for (int nt = 0; nt < 4; nt++) {
                    uint32_t bb0 = p0[nt * 4];
                    uint32_t bb1 = p1[nt * 4];
                    #pragma unroll
                    for (int m2 = 0; m2 < 4; m2++)
                        mma16816(acc[m2][nt], afr[m2], bb0, bb1);
                }
            }
        }
        if (ch + 1 < NCH) CP_WAIT0();
        __syncthreads();
    }
    #undef STAGE_A
    #undef STAGE_B

    int pcol = warp_n * 16 + (lane & 3);
    if (WHICH == 0) {
        // epilogue: BN + relu + maxpool2 -> fp16 dual-parity h2 arrays
        #pragma unroll
        for (int m2 = 0; m2 < 4; m2++) {
            #pragma unroll
            for (int h = 0; h < 2; h++) {
                int mg = mt * 128 + warp_m * 64 + m2 * 16 + h * 8 + lrow;
                float scv = g[mg] * rsqrtf(bv[mg] + 1e-5f);
                float shv = be[mg] - bm[mg] * scv + cb[mg] * scv;
                #pragma unroll
                for (int nt = 0; nt < 4; nt++) {
                    float v0 = acc[m2][nt][2 * h]     * scv + shv;
                    float v1 = acc[m2][nt][2 * h + 1] * scv + shv;
                    float r = fmaxf(fmaxf(v0, v1), 0.f);
                    int P = pt * 64 + pcol + nt * 4;
                    size_t base = ((size_t)(b * 128 + mg)) * 4112;
                    __half hr = __float2half_rn(r);
                    h2h[base + 8 + P] = hr;
                    h2o[base + 7 + P] = hr;
                }
            }
        }
        if (pt == 0) {
            for (int idx = tid; idx < 128 * 15; idx += 256) {
                int row = idx / 15, s = idx - row * 15;
                size_t base = ((size_t)(b * 128 + mt * 128 + row)) * 4112;
                if (s < 8) h2h[base + s] = __float2half(0.f);
                else       h2o[base + (s - 8)] = __float2half(0.f);
            }
        }
        if (pt == NPT - 1) {
            for (int idx = tid; idx < 128 * 17; idx += 256) {
                int row = idx / 17, s = idx - row * 17;
                size_t base = ((size_t)(b * 128 + mt * 128 + row)) * 4112;
                if (s < 8) h2h[base + 4104 + s] = __float2half(0.f);
                else       h2o[base + 4103 + (s - 8)] = __float2half(0.f);
            }
        }
    } else {
        // epilogue: BN + relu + maxpool2 + masked time-pool partial sum (g_h3 never materialized)
        int plen = lengths[b] >> 3;
        float* tbuf = (float*)smem;                 // [4 warp_n][128 ch] — loop's final sync freed smem
        #pragma unroll
        for (int m2 = 0; m2 < 4; m2++) {
            #pragma unroll
            for (int h = 0; h < 2; h++) {
                int c_loc = warp_m * 64 + m2 * 16 + h * 8 + lrow;
                int mg = mt * 128 + c_loc;
                float scv = g[mg] * rsqrtf(bv[mg] + 1e-5f);
                float shv = be[mg] - bm[mg] * scv + cb[mg] * scv;
                float s = 0.f;
                #pragma unroll
                for (int nt = 0; nt < 4; nt++) {
                    float v0 = acc[m2][nt][2 * h]     * scv + shv;
                    float v1 = acc[m2][nt][2 * h + 1] * scv + shv;
                    float r = fmaxf(fmaxf(v0, v1), 0.f);
                    int P = pt * 64 + pcol + nt * 4;
                    if (P < plen) s += r;
                }
                s += __shfl_xor_sync(0xffffffffu, s, 1);
                s += __shfl_xor_sync(0xffffffffu, s, 2);
                if ((lane & 3) == 0) tbuf[warp_n * 128 + c_loc] = s;
            }
        }
        __syncthreads();
        if (tid < 128) {
            float s = tbuf[tid] + tbuf[128 + tid] + tbuf[256 + tid] + tbuf[384 + tid];
            g_tpart[((size_t)b * 256 + mt * 128 + tid) * 32 + pt] = s;
        }
    }
}

// finish time pool: sum 32 pt partials, divide by plen
__global__ void timered_kernel(const int* __restrict__ lengths)
{
    int idx = blockIdx.x * 256 + threadIdx.x;   // 0..16383
    int b = idx >> 8;
    const float* p = g_tpart + (size_t)idx * 32;
    float s = 0.f;
    #pragma unroll
    for (int i = 0; i < 32; i++) s += p[i];
    int plen = lengths[b] >> 3;
    g_timevec[idx] = s / (float)plen;
}

// =============== conv1 ===============
__global__ void conv1_kernel(const float* __restrict__ x, const float* __restrict__ w,
                             const float* __restrict__ cb, const float* __restrict__ g,
                             const float* __restrict__ be, const float* __restrict__ m,
                             const float* __restrict__ v)
{
    __shared__ float sx[519];
    __shared__ float swv[56];
    __shared__ float sbn[16];
    int tid = threadIdx.x;
    int pb  = blockIdx.x * 256;
    int c8  = blockIdx.y * 8;
    int b   = blockIdx.z;
    __half* h1h = (__half*)g_h1h4;
    __half* h1o = (__half*)g_h1o4;
    const float* xb = x + (size_t)b * 16384;
    for (int idx = tid; idx < 519; idx += 256) {
        int t = 2*pb - 3 + idx;
        sx[idx] = (t >= 0 && t < 16384) ? xb[t] : 0.f;
    }
    if (tid < 56) swv[tid] = w[c8*7 + tid];
    if (tid < 8) {
        int c = c8 + tid;
        float sc = g[c] * rsqrtf(v[c] + 1e-5f);
        sbn[tid] = sc;
        sbn[8 + tid] = be[c] - m[c]*sc + cb[c]*sc;
    }
    __syncthreads();
    float xv[8];
    #pragma unroll
    for (int j = 0; j < 8; j++) xv[j] = sx[2*tid + j];
    int P = pb + tid;
    #pragma unroll
    for (int c = 0; c < 8; c++) {
        float y0 = 0.f, y1 = 0.f;
        #pragma unroll
        for (int j = 0; j < 7; j++) {
            float wc = swv[c*7 + j];
            y0 = fmaf(wc, xv[j],   y0);
            y1 = fmaf(wc, xv[j+1], y1);
        }
        float sc = sbn[c], sh = sbn[8 + c];
        float r = fmaxf(fmaxf(y0*sc + sh, y1*sc + sh), 0.f);
        size_t base = ((size_t)(b*64 + c8 + c)) * 8208;
        __half hr = __float2half_rn(r);
        h1h[base + 8 + P] = hr;
        h1o[base + 7 + P] = hr;
    }
    if (pb == 0) {
        for (int idx = tid; idx < 8 * 15; idx += 256) {
            int c = idx / 15, s = idx - c * 15;
            size_t base = ((size_t)(b*64 + c8 + c)) * 8208;
            if (s < 8) h1h[base + s] = __float2half(0.f);
            else       h1o[base + (s - 8)] = __float2half(0.f);
        }
    }
    if (pb == 8192 - 256) {
        for (int idx = tid; idx < 8 * 17; idx += 256) {
            int c = idx / 17, s = idx - c * 17;
            size_t base = ((size_t)(b*64 + c8 + c)) * 8208;
            if (s < 8) h1h[base + 8200 + s] = __float2half(0.f);
            else       h1o[base + 8199 + (s - 8)] = __float2half(0.f);
        }
    }
}

// =============== FFT: Bluestein, M=32768 = 8^5, radix-8 Stockham ===============
__global__ void fft_twiddle_kernel()
{
    int p = blockIdx.x*blockDim.x + threadIdx.x;
    int off = 0;
    #pragma unroll
    for (int st = 0; st < 15; st++) {
        int n = FFT_M >> st, mm = n >> 1;
        if (p < mm) {
            float sv, cv; sincosf(-2.f*PI_F*(float)p/(float)n, &sv, &cv);
            g_tw[off + p] = make_float2(cv, sv);
        }
        off += mm;
    }
}

// build with chirp symmetry: thread n (0..16383) writes n and 32768-n; sincos only for n < L
__global__ void fft_build_kernel(const float* __restrict__ x, const int* __restrict__ lengths)
{
    int n = blockIdx.x*blockDim.x + threadIdx.x;   // 0..16383
    int i = blockIdx.y;                             // 0..63
    int L = lengths[i];
    float2 a  = make_float2(0.f, 0.f);
    float2 bb = make_float2(0.f, 0.f);
    if (n < L) {
        unsigned r = ((unsigned)n * (unsigned)n) % (unsigned)(2*L);
        float sv, cv; sincosf(PI_F * (float)r / (float)L, &sv, &cv);
        bb = make_float2(cv, sv);
        float xv = x[(size_t)i*16384 + n];
        a = make_float2(xv*cv, -xv*sv);
    }
    size_t dbase = (size_t)i*FFT_M, cbase = (size_t)(64+i)*FFT_M;
    g_fftA[dbase + n] = a;
    g_fftA[cbase + n] = bb;
    if (n > 0) {
        g_fftA[dbase + FFT_M - n] = make_float2(0.f, 0.f);   // data: positions >16384 always 0
        g_fftA[cbase + FFT_M - n] = bb;                      // chirp symmetric
    } else {
        g_fftA[dbase + 16384] = make_float2(0.f, 0.f);
        g_fftA[cbase + 16384] = make_float2(0.f, 0.f);       // mm=16384 >= L always
    }
}

__device__ __forceinline__ void radix8_bf_store(float2* __restrict__ dst, size_t jb, int s,
                                                int p, int twOff, const float2* xx)
{
    float2 x0=xx[0],x1=xx[1],x2=xx[2],x3=xx[3],x4=xx[4],x5=xx[5],x6=xx[6],x7=xx[7];
    float2 t0 = make_float2(x0.x + x4.x, x0.y + x4.y);
    float2 t1 = make_float2(x0.x - x4.x, x0.y - x4.y);
    float2 t2 = make_float2(x2.x + x6.x, x2.y + x6.y);
    float2 t3 = make_float2(x2.y - x6.y, -(x2.x - x6.x));
    float2 E0 = make_float2(t0.x + t2.x, t0.y + t2.y);
    float2 E1 = make_float2(t1.x + t3.x, t1.y + t3.y);
    float2 E2 = make_float2(t0.x - t2.x, t0.y - t2.y);
    float2 E3 = make_float2(t1.x - t3.x, t1.y - t3.y);
    float2 u0 = make_float2(x1.x + x5.x, x1.y + x5.y);
    float2 u1 = make_float2(x1.x - x5.x, x1.y - x5.y);
    float2 u2 = make_float2(x3.x + x7.x, x3.y + x7.y);
    float2 u3 = make_float2(x3.y - x7.y, -(x3.x - x7.x));
    float2 O0 = make_float2(u0.x + u2.x, u0.y + u2.y);
    float2 O1 = make_float2(u1.x + u3.x, u1.y + u3.y);
    float2 O2 = make_float2(u0.x - u2.x, u0.y - u2.y);
    float2 O3 = make_float2(u1.x - u3.x, u1.y - u3.y);
    const float r = 0.70710678118654752f;
    float2 P0 = O0;
    float2 P1 = make_float2(r*(O1.x + O1.y), r*(O1.y - O1.x));
    float2 P2 = make_float2(O2.y, -O2.x);
    float2 P3 = make_float2(r*(O3.y - O3.x), -r*(O3.x + O3.y));
    float2 y0 = make_float2(E0.x + P0.x, E0.y + P0.y);
    float2 y1 = make_float2(E1.x + P1.x, E1.y + P1.y);
    float2 y2 = make_float2(E2.x + P2.x, E2.y + P2.y);
    float2 y3 = make_float2(E3.x + P3.x, E3.y + P3.y);
    float2 y4 = make_float2(E0.x - P0.x, E0.y - P0.y);
    float2 y5 = make_float2(E1.x - P1.x, E1.y - P1.y);
    float2 y6 = make_float2(E2.x - P2.x, E2.y - P2.y);
    float2 y7 = make_float2(E3.x - P3.x, E3.y - P3.y);
    float2 w1 = g_tw[twOff + p];
    float2 w2 = g_tw[twOff + 2*p];
    float2 w4 = g_tw[twOff + 4*p];
    float2 w3 = cmul(w1, w2);
    float2 w5 = cmul(w1, w4);
    float2 w6 = cmul(w2, w4);
    float2 w7 = cmul(w3, w4);
    dst[jb]       = y0;
    dst[jb + s]   = cmul(y1, w1);
    dst[jb + 2*s] = cmul(y2, w2);
    dst[jb + 3*s] = cmul(y3, w3);
    dst[jb + 4*s] = cmul(y4, w4);
    dst[jb + 5*s] = cmul(y5, w5);
    dst[jb + 6*s] = cmul(y6, w6);
    dst[jb + 7*s] = cmul(y7, w7);
}

__global__ void fft8_stage_kernel(int sel, int sShift, int twOff)
{
    const float2* __restrict__ src = sel ? g_fftB : g_fftA;
    float2* __restrict__ dst       = sel ? g_fftA : g_fftB;
    int i = blockIdx.x*blockDim.x + threadIdx.x;   // 0..4095
    size_t base = (size_t)blockIdx.y * FFT_M;
    int p = i >> sShift;
    int s = 1 << sShift;
    float2 xx[8];
    #pragma unroll
    for (int q = 0; q < 8; q++) xx[q] = src[base + i + q*4096];
    radix8_bf_store(dst, base + i + (size_t)7*p*s, s, p, twOff, xx);
}

// inverse first stage fused with conj pointwise product: reads g_fftB halves, writes g_fftA
__global__ void fft8_inv_first_kernel()
{
    int i = blockIdx.x*blockDim.x + threadIdx.x;   // 0..4095
    int arr = blockIdx.y;                           // 0..63
    const float2* D = g_fftB + (size_t)arr * FFT_M;
    const float2* C = g_fftB + (size_t)(64 + arr) * FFT_M;
    float2 xx[8];
    #pragma unroll
    for (int q = 0; q < 8; q++) {
        int n = i + q*4096;
        float2 d = D[n], c = C[n];
        xx[q] = make_float2(d.x*c.x - d.y*c.y, -(d.x*c.y + d.y*c.x));
    }
    float2* dst = g_fftA + (size_t)arr * FFT_M;
    radix8_bf_store(dst, (size_t)8*i, 1, i, 0, xx);  // st=0: p=i, s=1, twOff=0
}

// magnitude/log1p: reads g_fftA (inverse ends there)
__global__ void fft_finalize_kernel(const int* __restrict__ lengths)
{
    int k = blockIdx.x*blockDim.x + threadIdx.x;
    int arr = blockIdx.y;
    int K = lengths[arr] / 2 + 1;
    if (k >= K) return;
    float2 c = g_fftA[(size_t)arr * FFT_M + k];
    g_spec[(size_t)arr * 8448 + k] = log1pf(sqrtf(c.x*c.x + c.y*c.y) * (1.0f/32768.0f));
}

__global__ void apool_kernel(const int* __restrict__ lengths)
{
    int i = blockIdx.x, j = threadIdx.x;
    int K = lengths[i]/2 + 1;
    int s0 = (j*K) >> 8;
    int e0 = ((j+1)*K + 255) >> 8;
    const float* sp = g_spec + (size_t)i*8448;
    float s = 0.f;
    for (int t = s0; t < e0; t++) s += sp[t];
    g_spectrum[i*256 + j] = s / (float)(e0 - s0);
}

// =============== small GEMMs ===============
__global__ void freqlin_kernel(const float* __restrict__ fw, const float* __restrict__ fb)
{
    int i = blockIdx.x, h = threadIdx.x;
    __shared__ float sp[256];
    for (int f = h; f < 256; f += 128) sp[f] = g_spectrum[i*256 + f];
    __syncthreads();
    float acc = fb[h];
    const float* wr = fw + (size_t)h*256;
    for (int f = 0; f < 256; f++) acc = fmaf(sp[f], wr[f], acc);
    g_freqvec[i*128 + h] = fmaxf(acc, 0.f);
}

__global__ void head_kernel(const float* __restrict__ w0, const float* __restrict__ b0,
                            const float* __restrict__ w1, const float* __restrict__ b1,
                            float* __restrict__ out)
{
    int b = blockIdx.x, tid = threadIdx.x;
    __shared__ float fused[384];
    __shared__ float hid[128];
    for (int j = tid; j < 384; j += 128)
        fused[j] = (j < 256) ? g_timevec[b*256 + j] : g_freqvec[b*128 + (j - 256)];
    __syncthreads();
    float acc = b0[tid];
    const float* wr = w0 + (size_t)tid*384;
    for (int j = 0; j < 384; j++) acc = fmaf(fused[j], wr[j], acc);
    hid[tid] = fmaxf(acc, 0.f);
    __syncthreads();
    int wid = tid >> 5, lane = tid & 31;
    float s = 0.f;
    for (int t = lane; t < 128; t += 32) s += hid[t] * w1[wid*128 + t];
    #pragma unroll
    for (int off = 16; off; off >>= 1) s += __shfl_down_sync(0xffffffffu, s, off);
    if (lane == 0) out[b*4 + wid] = s + b1[wid];
}

// =============== launch ===============
extern "C" void kernel_launch(void* const* d_in, const int* in_sizes, int n_in,
                              void* d_out, int out_size)
{
    const float* x   = (const float*)d_in[0];
    const int*   len = (const int*)  d_in[1];
    const float *cw0 = (const float*)d_in[2],  *cb0 = (const float*)d_in[3];
    const float *g0  = (const float*)d_in[4],  *be0 = (const float*)d_in[5];
    const float *m0  = (const float*)d_in[6],  *v0  = (const float*)d_in[7];
    const float *cw1 = (const float*)d_in[8],  *cb1 = (const float*)d_in[9];
    const float *g1  = (const float*)d_in[10], *be1 = (const float*)d_in[11];
    const float *m1  = (const float*)d_in[12], *v1  = (const float*)d_in[13];
    const float *cw2 = (const float*)d_in[14], *cb2 = (const float*)d_in[15];
    const float *g2  = (const float*)d_in[16], *be2 = (const float*)d_in[17];
    const float *m2  = (const float*)d_in[18], *v2  = (const float*)d_in[19];
    const float *fw  = (const float*)d_in[20], *fb  = (const float*)d_in[21];
    const float *hw0 = (const float*)d_in[22], *hb0 = (const float*)d_in[23];
    const float *hw1 = (const float*)d_in[24], *hb1 = (const float*)d_in[25];
    float* out = (float*)d_out;

    const int SMEM_CONV = 49152 + 2 * BBUF_B;   // 67648
    cudaFuncSetAttribute(convmma_kernel<64,128,8192,0>, cudaFuncAttributeMaxDynamicSharedMemorySize, SMEM_CONV);
    cudaFuncSetAttribute(convmma_kernel<128,256,4096,1>, cudaFuncAttributeMaxDynamicSharedMemorySize, SMEM_CONV);

    __half *wa2, *wa3;
    cudaGetSymbolAddress((void**)&wa2, g_wA2);
    cudaGetSymbolAddress((void**)&wa3, g_wA3);
    prep_w_kernel<64, 1><<<(1*4*128*96  + 255)/256, 256>>>(cw1, wa2);
    prep_w_kernel<128,2><<<(2*8*128*96 + 255)/256, 256>>>(cw2, wa3);

    // time branch
    conv1_kernel<<<dim3(32,8,64), 256>>>(x, cw0, cb0, g0, be0, m0, v0);
    convmma_kernel<64,128,8192,0><<<dim3(64,1,64), 256, SMEM_CONV>>>(cb1, g1, be1, m1, v1, len);
    convmma_kernel<128,256,4096,1><<<dim3(32,2,64), 256, SMEM_CONV>>>(cb2, g2, be2, m2, v2, len);
    timered_kernel<<<64, 256>>>(len);

    // frequency branch: 5 radix-8 stages each way, tails fused
    fft_twiddle_kernel<<<64, 256>>>();
    fft_build_kernel<<<dim3(64,64), 256>>>(x, len);
    int sel = 0;
    for (int st = 0; st < 5; st++) {                   // forward (batch 128): ends in g_fftB
        int n = FFT_M >> (3*st);
        fft8_stage_kernel<<<dim3(16,128), 256>>>(sel, 3*st, 32768 - n);
        sel ^= 1;
    }
    fft8_inv_first_kernel<<<dim3(16,64), 256>>>();     // fused pointwise + inv stage 0: B -> A
    sel = 0;
    for (int st = 1; st < 5; st++) {                   // inverse stages 1..4: ends in g_fftA
        int n = FFT_M >> (3*st);
        fft8_stage_kernel<<<dim3(16,64), 256>>>(sel, 3*st, 32768 - n);
        sel ^= 1;
    }
    fft_finalize_kernel<<<dim3(33,64), 256>>>(len);
    apool_kernel<<<64, 256>>>(len);
    freqlin_kernel<<<64, 128>>>(fw, fb);

    head_kernel<<<64, 128>>>(hw0, hb0, hw1, hb1, out);
}

// round 15
// speedup vs baseline: 14.4694x; 1.9372x over previous
#include <cuda_runtime.h>
#include <cuda_fp16.h>
#include <cstdint>
#include <cstddef>

#define PI_F 3.14159265358979323846f
#define FFT_M 32768

// ---- static scratch ----
// channel-pair-interleaved fp16 activations: word w(b, cpair, t) = (x[2c][t], x[2c+1][t])
// row stride = 8 + L + 8 words
__device__ uint4  g_x1[4202496];     // conv1 out: [64][32 pairs][8208 words]
__device__ uint4  g_x2[4210688];     // conv2 out: [64][64 pairs][4112 words]
__device__ float  g_tpart[64u*256u*32u];
__device__ float2 g_fftA[128u*32768u];
__device__ float2 g_fftB[128u*32768u];
__device__ float2 g_tw[32768];
__device__ float  g_spec[64u*8448u];
__device__ float  g_spectrum[64u*256u];
__device__ float  g_timevec[64u*256u];
__device__ float  g_freqvec[64u*128u];
// prepped fp16 weights: [mt][ch16][m=128][88 padded cols, 80 used], tap-major k = j*16+c
__device__ __half g_wA2[4u*128u*88u];
__device__ __half g_wA3[16u*128u*88u];

// ---- helpers ----
__device__ __forceinline__ uint32_t smem_u32(const void* p) {
    uint32_t a; asm("{ .reg .u64 t; cvta.to.shared.u64 t, %1; cvt.u32.u64 %0, t; }" : "=r"(a) : "l"(p));
    return a;
}
__device__ __forceinline__ void mma16816(float* c, const uint32_t* a, uint32_t b0, uint32_t b1) {
    asm volatile("mma.sync.aligned.m16n8k16.row.col.f32.f16.f16.f32 "
        "{%0,%1,%2,%3}, {%4,%5,%6,%7}, {%8,%9}, {%0,%1,%2,%3};"
        : "+f"(c[0]), "+f"(c[1]), "+f"(c[2]), "+f"(c[3])
        : "r"(a[0]), "r"(a[1]), "r"(a[2]), "r"(a[3]), "r"(b0), "r"(b1));
}
__device__ __forceinline__ void ldmA(uint32_t* a, uint32_t addr) {
    asm volatile("ldmatrix.sync.aligned.m8n8.x4.shared.b16 {%0,%1,%2,%3}, [%4];"
        : "=r"(a[0]), "=r"(a[1]), "=r"(a[2]), "=r"(a[3]) : "r"(addr));
}
__device__ __forceinline__ float2 cmul(float2 a, float2 b) {
    return make_float2(a.x*b.x - a.y*b.y, a.x*b.y + a.y*b.x);
}
#define CP_ASYNC16(dst, src) asm volatile("cp.async.cg.shared.global [%0], [%1], 16;" :: "r"(dst), "l"(src))
#define CP_ASYNC8(dst, src)  asm volatile("cp.async.ca.shared.global [%0], [%1], 8;"  :: "r"(dst), "l"(src))
#define CP_COMMIT() asm volatile("cp.async.commit_group;")
#define CP_WAIT0()  asm volatile("cp.async.wait_group 0;" ::: "memory")

// smem layout (bytes): A[2] @0 (22528 ea), sB[2] @45056 (4864 ea: 8 rows x 608B) = 54784
#define A_CHUNK_B 22528
#define SB_OFF    45056
#define SB_BUF_B  4864
#define SB_ROW_W  152            // words; 152 % 32 = 24 -> conflict-free quad pattern

// ---- weight prep: fp32 [COUT][CIN][5] -> [mt][ch16][m][88] fp16, k = j*16 + c ----
template<int CIN, int MT>
__global__ void prep_w_kernel(const float* __restrict__ w, __half* __restrict__ dst)
{
    const int NCH = CIN / 16;
    int total = MT * NCH * 128 * 80;
    int idx = blockIdx.x * 256 + threadIdx.x;
    if (idx >= total) return;
    int kl = idx % 80;
    int m  = (idx / 80) % 128;
    int ch = (idx / (80 * 128)) % NCH;
    int mt = idx / (80 * 128 * NCH);
    int j = kl >> 4, c = kl & 15;
    float wv = w[(((size_t)(mt * 128 + m)) * CIN + ch * 16 + c) * 5 + j];
    dst[((size_t)(mt * NCH + ch) * 128 + m) * 88 + kl] = __float2half_rn(wv);
}

// ---- conv blocks 2/3: fp16 mma, tap-major K=80/chunk, pair-interleaved B, 2 CTA/SM ----
// CTA: 256 thr (8 warps 2Mx4N). Tile M=128 x N=128 conv positions (->64 pooled).
template<int CIN, int COUT, int LIN, int WHICH>
__global__ void __launch_bounds__(256, 2)
convmma_kernel(const float* __restrict__ cb, const float* __restrict__ g,
               const float* __restrict__ be, const float* __restrict__ bm,
               const float* __restrict__ bv, const int* __restrict__ lengths)
{
    const int NCH   = CIN / 16;
    const int ROWW  = WHICH ? 4112 : 8208;    // input row words
    const int NPT   = LIN / 128;
    const uint32_t* inw = WHICH ? (const uint32_t*)g_x2 : (const uint32_t*)g_x1;
    const __half* wA    = WHICH ? g_wA3 : g_wA2;
    uint32_t* x2w = (uint32_t*)g_x2;

    extern __shared__ __align__(16) char smem[];
    uint32_t sbase = smem_u32(smem);
    int tid = threadIdx.x, wid = tid >> 5, lane = tid & 31;
    int pt = blockIdx.x, mt = blockIdx.y, b = blockIdx.z;
    int warp_m = wid & 1, warp_n = wid >> 1;
    int lrow = lane >> 2;
    int tb = pt * 128 - 2;

    uint32_t aoff[4];
    #pragma unroll
    for (int m2 = 0; m2 < 4; m2++)
        aoff[m2] = (uint32_t)(((warp_m * 64 + m2 * 16 + (lane & 7) + ((lane >> 3) & 1) * 8) * 88
                              + (lane >> 4) * 8) * 2);
    int b0base = (lane & 3) * SB_ROW_W + 2 + warp_n * 32 + lrow;   // word index
    int b1base = b0base + 4 * SB_ROW_W;

    float acc[4][4][4];
    #pragma unroll
    for (int i = 0; i < 4; i++)
        #pragma unroll
        for (int n = 0; n < 4; n++)
            #pragma unroll
            for (int q = 0; q < 4; q++) acc[i][n][q] = 0.f;

    #define STAGE_A(CH) do {                                                             \
        const uint4* _as = (const uint4*)(wA + (size_t)(mt * NCH + (CH)) * 128 * 88);    \
        uint32_t _ad = sbase + (((CH) & 1) ? (uint32_t)A_CHUNK_B : 0u);                  \
        for (int _i = tid; _i < 1408; _i += 256) CP_ASYNC16(_ad + _i * 16, _as + _i);    \
    } while (0)
    // per chunk: 8 pair rows x 136 words; ops/row: 8B head + 33x16B + 8B tail = 35
    #define STAGE_B(CH) do {                                                             \
        uint32_t _bb = sbase + (uint32_t)SB_OFF + ((CH) & 1) * (uint32_t)SB_BUF_B;       \
        for (int _i = tid; _i < 280; _i += 256) {                                        \
            int _row = _i / 35, _op = _i - _row * 35;                                    \
            const uint32_t* _g = inw + ((size_t)b * (CIN/2) + (CH) * 8 + _row) * ROWW    \
                                 + 8 + tb;                                               \
            uint32_t _d = _bb + _row * 608u;                                             \
            if (_op == 0)       CP_ASYNC8(_d + 8u, _g);                                  \
            else if (_op < 34) { int _t = 2 + 4 * (_op - 1); CP_ASYNC16(_d + 8u + _t * 4, _g + _t); } \
            else               CP_ASYNC8(_d + 8u + 536u, _g + 134);                      \
        }                                                                                \
    } while (0)

    STAGE_A(0); STAGE_B(0); CP_COMMIT();
    CP_WAIT0();
    __syncthreads();

    for (int ch = 0; ch < NCH; ch++) {
        int cur = ch & 1;
        if (ch + 1 < NCH) { STAGE_A(ch + 1); STAGE_B(ch + 1); CP_COMMIT(); }
        {
            uint32_t Aaddr = sbase + (cur ? (uint32_t)A_CHUNK_B : 0u);
            const uint32_t* Bw = (const uint32_t*)(smem + SB_OFF + cur * SB_BUF_B);
            #pragma unroll
            for (int ks = 0; ks < 5; ks++) {                 // j = ks (tap)
                uint32_t afr[4][4];
                #pragma unroll
                for (int m2 = 0; m2 < 4; m2++) ldmA(afr[m2], Aaddr + aoff[m2] + ks * 32);
                const uint32_t* p0 = Bw + b0base + ks;
                const uint32_t* p1 = Bw + b1base + ks;
                #pragma unroll
                for (int nt = 0; nt < 4; nt++) {
                    uint32_t bb0 = p0[nt * 8];
                    uint32_t bb1 = p1[nt * 8];
                    #pragma unroll
                    for (int m2 = 0; m2 < 4; m2++)
                        mma16816(acc[m2][nt], afr[m2], bb0, bb1);
                }
            }
        }
        if (ch + 1 < NCH) CP_WAIT0();
        __syncthreads();
    }
    #undef STAGE_A
    #undef STAGE_B

    int pcol = warp_n * 16 + (lane & 3);
    if (WHICH == 0) {
        // BN + relu + maxpool2 -> pair-interleaved fp16 words (shfl pairs adjacent channels)
        #pragma unroll
        for (int m2 = 0; m2 < 4; m2++) {
            #pragma unroll
            for (int h = 0; h < 2; h++) {
                int mg = mt * 128 + warp_m * 64 + m2 * 16 + h * 8 + lrow;
                float scv = g[mg] * rsqrtf(bv[mg] + 1e-5f);
                float shv = be[mg] - bm[mg] * scv + cb[mg] * scv;
                #pragma unroll
                for (int nt = 0; nt < 4; nt++) {
                    float v0 = acc[m2][nt][2 * h]     * scv + shv;
                    float v1 = acc[m2][nt][2 * h + 1] * scv + shv;
                    float r = fmaxf(fmaxf(v0, v1), 0.f);
                    float rp = __shfl_xor_sync(0xffffffffu, r, 4);   // partner channel
                    if ((lrow & 1) == 0) {
                        __half2 wv = __halves2half2(__float2half_rn(r), __float2half_rn(rp));
                        int P = pt * 64 + pcol + nt * 4;
                        x2w[((size_t)b * 64 + (mg >> 1)) * 4112 + 8 + P] = *(uint32_t*)&wv;
                    }
                }
            }
        }
        if (pt == 0) {
            for (int idx = tid; idx < 64 * 8; idx += 256)
                x2w[((size_t)b * 64 + (idx >> 3)) * 4112 + (idx & 7)] = 0u;
        }
        if (pt == NPT - 1) {
            for (int idx = tid; idx < 64 * 8; idx += 256)
                x2w[((size_t)b * 64 + (idx >> 3)) * 4112 + 4104 + (idx & 7)] = 0u;
        }
    } else {
        // BN + relu + maxpool2 + masked time-pool partial sum
        int plen = lengths[b] >> 3;
        float* tbuf = (float*)smem;
        #pragma unroll
        for (int m2 = 0; m2 < 4; m2++) {
            #pragma unroll
            for (int h = 0; h < 2; h++) {
                int c_loc = warp_m * 64 + m2 * 16 + h * 8 + lrow;
                int mg = mt * 128 + c_loc;
                float scv = g[mg] * rsqrtf(bv[mg] + 1e-5f);
                float shv = be[mg] - bm[mg] * scv + cb[mg] * scv;
                float s = 0.f;
                #pragma unroll
                for (int nt = 0; nt < 4; nt++) {
                    float v0 = acc[m2][nt][2 * h]     * scv + shv;
                    float v1 = acc[m2][nt][2 * h + 1] * scv + shv;
                    float r = fmaxf(fmaxf(v0, v1), 0.f);
                    int P = pt * 64 + pcol + nt * 4;
                    if (P < plen) s += r;
                }
                s += __shfl_xor_sync(0xffffffffu, s, 1);
                s += __shfl_xor_sync(0xffffffffu, s, 2);
                if ((lane & 3) == 0) tbuf[warp_n * 128 + c_loc] = s;
            }
        }
        __syncthreads();
        if (tid < 128) {
            float s = tbuf[tid] + tbuf[128 + tid] + tbuf[256 + tid] + tbuf[384 + tid];
            g_tpart[((size_t)b * 256 + mt * 128 + tid) * 32 + pt] = s;
        }
    }
}

__global__ void timered_kernel(const int* __restrict__ lengths)
{
    int idx = blockIdx.x * 256 + threadIdx.x;
    int b = idx >> 8;
    const float* p = g_tpart + (size_t)idx * 32;
    float s = 0.f;
    #pragma unroll
    for (int i = 0; i < 32; i++) s += p[i];
    g_timevec[idx] = s / (float)(lengths[b] >> 3);
}

// =============== conv1: 1->64, k=7, +BN+relu+pool2, pair-interleaved fp16 out ===============
__global__ void conv1_kernel(const float* __restrict__ x, const float* __restrict__ w,
                             const float* __restrict__ cb, const float* __restrict__ g,
                             const float* __restrict__ be, const float* __restrict__ m,
                             const float* __restrict__ v)
{
    __shared__ float sx[519];
    __shared__ float swv[56];
    __shared__ float sbn[16];
    int tid = threadIdx.x;
    int pb  = blockIdx.x * 256;
    int c8  = blockIdx.y * 8;
    int b   = blockIdx.z;
    uint32_t* x1w = (uint32_t*)g_x1;
    const float* xb = x + (size_t)b * 16384;
    for (int idx = tid; idx < 519; idx += 256) {
        int t = 2*pb - 3 + idx;
        sx[idx] = (t >= 0 && t < 16384) ? xb[t] : 0.f;
    }
    if (tid < 56) swv[tid] = w[c8*7 + tid];
    if (tid < 8) {
        int c = c8 + tid;
        float sc = g[c] * rsqrtf(v[c] + 1e-5f);
        sbn[tid] = sc;
        sbn[8 + tid] = be[c] - m[c]*sc + cb[c]*sc;
    }
    __syncthreads();
    float xv[8];
    #pragma unroll
    for (int j = 0; j < 8; j++) xv[j] = sx[2*tid + j];
    int P = pb + tid;
    float rr[8];
    #pragma unroll
    for (int c = 0; c < 8; c++) {
        float y0 = 0.f, y1 = 0.f;
        #pragma unroll
        for (int j = 0; j < 7; j++) {
            float wc = swv[c*7 + j];
            y0 = fmaf(wc, xv[j],   y0);
            y1 = fmaf(wc, xv[j+1], y1);
        }
        float sc = sbn[c], sh = sbn[8 + c];
        rr[c] = fmaxf(fmaxf(y0*sc + sh, y1*sc + sh), 0.f);
    }
    #pragma unroll
    for (int c2 = 0; c2 < 4; c2++) {
        __half2 wv2 = __halves2half2(__float2half_rn(rr[2*c2]), __float2half_rn(rr[2*c2+1]));
        x1w[((size_t)b * 32 + (c8 >> 1) + c2) * 8208 + 8 + P] = *(uint32_t*)&wv2;
    }
    if (pb == 0) {
        for (int idx = tid; idx < 32; idx += 256) ;   // (4 rows x 8 words handled below)
        if (tid < 32)
            x1w[((size_t)b * 32 + (c8 >> 1) + (tid >> 3)) * 8208 + (tid & 7)] = 0u;
    }
    if (pb == 8192 - 256) {
        if (tid < 32)
            x1w[((size_t)b * 32 + (c8 >> 1) + (tid >> 3)) * 8208 + 8200 + (tid & 7)] = 0u;
    }
}

// =============== FFT: Bluestein, M=32768 = 8^5, radix-8 Stockham ===============
__global__ void fft_twiddle_kernel()
{
    int p = blockIdx.x*blockDim.x + threadIdx.x;
    int off = 0;
    #pragma unroll
    for (int st = 0; st < 15; st++) {
        int n = FFT_M >> st, mm = n >> 1;
        if (p < mm) {
            float sv, cv; sincosf(-2.f*PI_F*(float)p/(float)n, &sv, &cv);
            g_tw[off + p] = make_float2(cv, sv);
        }
        off += mm;
    }
}

__global__ void fft_build_kernel(const float* __restrict__ x, const int* __restrict__ lengths)
{
    int n = blockIdx.x*blockDim.x + threadIdx.x;   // 0..16383
    int i = blockIdx.y;
    int L = lengths[i];
    float2 a  = make_float2(0.f, 0.f);
    float2 bb = make_float2(0.f, 0.f);
    if (n < L) {
        unsigned r = ((unsigned)n * (unsigned)n) % (unsigned)(2*L);
        float sv, cv; sincosf(PI_F * (float)r / (float)L, &sv, &cv);
        bb = make_float2(cv, sv);
        float xv = x[(size_t)i*16384 + n];
        a = make_float2(xv*cv, -xv*sv);
    }
    size_t dbase = (size_t)i*FFT_M, cbase = (size_t)(64+i)*FFT_M;
    g_fftA[dbase + n] = a;
    g_fftA[cbase + n] = bb;
    if (n > 0) {
        g_fftA[dbase + FFT_M - n] = make_float2(0.f, 0.f);
        g_fftA[cbase + FFT_M - n] = bb;
    } else {
        g_fftA[dbase + 16384] = make_float2(0.f, 0.f);
        g_fftA[cbase + 16384] = make_float2(0.f, 0.f);
    }
}

__device__ __forceinline__ void radix8_bf(const float2* xx, float2* yy)
{
    float2 x0=xx[0],x1=xx[1],x2=xx[2],x3=xx[3],x4=xx[4],x5=xx[5],x6=xx[6],x7=xx[7];
    float2 t0 = make_float2(x0.x + x4.x, x0.y + x4.y);
    float2 t1 = make_float2(x0.x - x4.x, x0.y - x4.y);
    float2 t2 = make_float2(x2.x + x6.x, x2.y + x6.y);
    float2 t3 = make_float2(x2.y - x6.y, -(x2.x - x6.x));
    float2 E0 = make_float2(t0.x + t2.x, t0.y + t2.y);
    float2 E1 = make_float2(t1.x + t3.x, t1.y + t3.y);
    float2 E2 = make_float2(t0.x - t2.x, t0.y - t2.y);
    float2 E3 = make_float2(t1.x - t3.x, t1.y - t3.y);
    float2 u0 = make_float2(x1.x + x5.x, x1.y + x5.y);
    float2 u1 = make_float2(x1.x - x5.x, x1.y - x5.y);
    float2 u2 = make_float2(x3.x + x7.x, x3.y + x7.y);
    float2 u3 = make_float2(x3.y - x7.y, -(x3.x - x7.x));
    float2 O0 = make_float2(u0.x + u2.x, u0.y + u2.y);
    float2 O1 = make_float2(u1.x + u3.x, u1.y + u3.y);
    float2 O2 = make_float2(u0.x - u2.x, u0.y - u2.y);
    float2 O3 = make_float2(u1.x - u3.x, u1.y - u3.y);
    const float r = 0.70710678118654752f;
    float2 P1 = make_float2(r*(O1.x + O1.y), r*(O1.y - O1.x));
    float2 P2 = make_float2(O2.y, -O2.x);
    float2 P3 = make_float2(r*(O3.y - O3.x), -r*(O3.x + O3.y));
    yy[0] = make_float2(E0.x + O0.x, E0.y + O0.y);
    yy[1] = make_float2(E1.x + P1.x, E1.y + P1.y);
    yy[2] = make_float2(E2.x + P2.x, E2.y + P2.y);
    yy[3] = make_float2(E3.x + P3.x, E3.y + P3.y);
    yy[4] = make_float2(E0.x - O0.x, E0.y - O0.y);
    yy[5] = make_float2(E1.x - P1.x, E1.y - P1.y);
    yy[6] = make_float2(E2.x - P2.x, E2.y - P2.y);
    yy[7] = make_float2(E3.x - P3.x, E3.y - P3.y);
}

__device__ __forceinline__ void tw_store(float2* __restrict__ dst, size_t jb, int s,
                                         int p, int twOff, const float2* yy)
{
    float2 w1 = g_tw[twOff + p];
    float2 w2 = g_tw[twOff + 2*p];
    float2 w4 = g_tw[twOff + 4*p];
    float2 w3 = cmul(w1, w2);
    float2 w5 = cmul(w1, w4);
    float2 w6 = cmul(w2, w4);
    float2 w7 = cmul(w3, w4);
    dst[jb]       = yy[0];
    dst[jb + s]   = cmul(yy[1], w1);
    dst[jb + 2*s] = cmul(yy[2], w2);
    dst[jb + 3*s] = cmul(yy[3], w3);
    dst[jb + 4*s] = cmul(yy[4], w4);
    dst[jb + 5*s] = cmul(yy[5], w5);
    dst[jb + 6*s] = cmul(yy[6], w6);
    dst[jb + 7*s] = cmul(yy[7], w7);
}

__global__ void fft8_stage_kernel(int sel, int sShift, int twOff)
{
    const float2* __restrict__ src = sel ? g_fftB : g_fftA;
    float2* __restrict__ dst       = sel ? g_fftA : g_fftB;
    int i = blockIdx.x*blockDim.x + threadIdx.x;
    size_t base = (size_t)blockIdx.y * FFT_M;
    int p = i >> sShift;
    int s = 1 << sShift;
    float2 xx[8], yy[8];
    #pragma unroll
    for (int q = 0; q < 8; q++) xx[q] = src[base + i + q*4096];
    radix8_bf(xx, yy);
    tw_store(dst, base + i + (size_t)7*p*s, s, p, twOff, yy);
}

// inverse first stage fused with conj pointwise product: reads g_fftB halves, writes g_fftA
__global__ void fft8_inv_first_kernel()
{
    int i = blockIdx.x*blockDim.x + threadIdx.x;
    int arr = blockIdx.y;
    const float2* D = g_fftB + (size_t)arr * FFT_M;
    const float2* C = g_fftB + (size_t)(64 + arr) * FFT_M;
    float2 xx[8], yy[8];
    #pragma unroll
    for (int q = 0; q < 8; q++) {
        int n = i + q*4096;
        float2 d = D[n], c = C[n];
        xx[q] = make_float2(d.x*c.x - d.y*c.y, -(d.x*c.y + d.y*c.x));
    }
    radix8_bf(xx, yy);
    tw_store(g_fftA + (size_t)arr * FFT_M, (size_t)8*i, 1, i, 0, yy);
}

// inverse LAST stage (st=4: p=0, twiddles=1) fused with magnitude/log1p -> g_spec
__global__ void fft8_inv_last_kernel(const int* __restrict__ lengths)
{
    int i = blockIdx.x*blockDim.x + threadIdx.x;   // 0..4095
    int arr = blockIdx.y;
    int K = lengths[arr] / 2 + 1;
    const float2* src = g_fftB + (size_t)arr * FFT_M;
    float2 xx[8], yy[8];
    #pragma unroll
    for (int q = 0; q < 8; q++) xx[q] = src[i + q*4096];
    radix8_bf(xx, yy);
    float* sp = g_spec + (size_t)arr * 8448;
    #pragma unroll
    for (int q = 0; q < 3; q++) {                  // only j < K <= 8193 consumed
        int j = i + q*4096;
        if (j < K)
            sp[j] = log1pf(sqrtf(yy[q].x*yy[q].x + yy[q].y*yy[q].y) * (1.0f/32768.0f));
    }
}

__global__ void apool_kernel(const int* __restrict__ lengths)
{
    int i = blockIdx.x, j = threadIdx.x;
    int K = lengths[i]/2 + 1;
    int s0 = (j*K) >> 8;
    int e0 = ((j+1)*K + 255) >> 8;
    const float* sp = g_spec + (size_t)i*8448;
    float s = 0.f;
    for (int t = s0; t < e0; t++) s += sp[t];
    g_spectrum[i*256 + j] = s / (float)(e0 - s0);
}

// =============== small GEMMs ===============
__global__ void freqlin_kernel(const float* __restrict__ fw, const float* __restrict__ fb)
{
    int i = blockIdx.x, h = threadIdx.x;
    __shared__ float sp[256];
    for (int f = h; f < 256; f += 128) sp[f] = g_spectrum[i*256 + f];
    __syncthreads();
    float acc = fb[h];
    const float* wr = fw + (size_t)h*256;
    for (int f = 0; f < 256; f++) acc = fmaf(sp[f], wr[f], acc);
    g_freqvec[i*128 + h] = fmaxf(acc, 0.f);
}

__global__ void head_kernel(const float* __restrict__ w0, const float* __restrict__ b0,
                            const float* __restrict__ w1, const float* __restrict__ b1,
                            float* __restrict__ out)
{
    int b = blockIdx.x, tid = threadIdx.x;
    __shared__ float fused[384];
    __shared__ float hid[128];
    for (int j = tid; j < 384; j += 128)
        fused[j] = (j < 256) ? g_timevec[b*256 + j] : g_freqvec[b*128 + (j - 256)];
    __syncthreads();
    float acc = b0[tid];
    const float* wr = w0 + (size_t)tid*384;
    for (int j = 0; j < 384; j++) acc = fmaf(fused[j], wr[j], acc);
    hid[tid] = fmaxf(acc, 0.f);
    __syncthreads();
    int wid = tid >> 5, lane = tid & 31;
    float s = 0.f;
    for (int t = lane; t < 128; t += 32) s += hid[t] * w1[wid*128 + t];
    #pragma unroll
    for (int off = 16; off; off >>= 1) s += __shfl_down_sync(0xffffffffu, s, off);
    if (lane == 0) out[b*4 + wid] = s + b1[wid];
}

// =============== launch ===============
extern "C" void kernel_launch(void* const* d_in, const int* in_sizes, int n_in,
                              void* d_out, int out_size)
{
    const float* x   = (const float*)d_in[0];
    const int*   len = (const int*)  d_in[1];
    const float *cw0 = (const float*)d_in[2],  *cb0 = (const float*)d_in[3];
    const float *g0  = (const float*)d_in[4],  *be0 = (const float*)d_in[5];
    const float *m0  = (const float*)d_in[6],  *v0  = (const float*)d_in[7];
    const float *cw1 = (const float*)d_in[8],  *cb1 = (const float*)d_in[9];
    const float *g1  = (const float*)d_in[10], *be1 = (const float*)d_in[11];
    const float *m1  = (const float*)d_in[12], *v1  = (const float*)d_in[13];
    const float *cw2 = (const float*)d_in[14], *cb2 = (const float*)d_in[15];
    const float *g2  = (const float*)d_in[16], *be2 = (const float*)d_in[17];
    const float *m2  = (const float*)d_in[18], *v2  = (const float*)d_in[19];
    const float *fw  = (const float*)d_in[20], *fb  = (const float*)d_in[21];
    const float *hw0 = (const float*)d_in[22], *hb0 = (const float*)d_in[23];
    const float *hw1 = (const float*)d_in[24], *hb1 = (const float*)d_in[25];
    float* out = (float*)d_out;

    const int SMEM_CONV = 2*A_CHUNK_B + 2*SB_BUF_B;   // 54784
    cudaFuncSetAttribute(convmma_kernel<64,128,8192,0>, cudaFuncAttributeMaxDynamicSharedMemorySize, SMEM_CONV);
    cudaFuncSetAttribute(convmma_kernel<128,256,4096,1>, cudaFuncAttributeMaxDynamicSharedMemorySize, SMEM_CONV);

    __half *wa2, *wa3;
    cudaGetSymbolAddress((void**)&wa2, g_wA2);
    cudaGetSymbolAddress((void**)&wa3, g_wA3);
    prep_w_kernel<64, 1><<<(1*4*128*80  + 255)/256, 256>>>(cw1, wa2);
    prep_w_kernel<128,2><<<(2*8*128*80 + 255)/256, 256>>>(cw2, wa3);

    // time branch
    conv1_kernel<<<dim3(32,8,64), 256>>>(x, cw0, cb0, g0, be0, m0, v0);
    convmma_kernel<64,128,8192,0><<<dim3(64,1,64), 256, SMEM_CONV>>>(cb1, g1, be1, m1, v1, len);
    convmma_kernel<128,256,4096,1><<<dim3(32,2,64), 256, SMEM_CONV>>>(cb2, g2, be2, m2, v2, len);
    timered_kernel<<<64, 256>>>(len);

    // frequency branch
    fft_twiddle_kernel<<<64, 256>>>();
    fft_build_kernel<<<dim3(64,64), 256>>>(x, len);
    int sel = 0;
    for (int st = 0; st < 5; st++) {                   // forward (batch 128): ends in g_fftB
        int n = FFT_M >> (3*st);
        fft8_stage_kernel<<<dim3(16,128), 256>>>(sel, 3*st, 32768 - n);
        sel ^= 1;
    }
    fft8_inv_first_kernel<<<dim3(16,64), 256>>>();     // fused pointwise + inv st0: B -> A
    sel = 0;
    for (int st = 1; st < 4; st++) {                   // inv st1..3: A->B, B->A, A->B
        int n = FFT_M >> (3*st);
        fft8_stage_kernel<<<dim3(16,64), 256>>>(sel, 3*st, 32768 - n);
        sel ^= 1;
    }
    fft8_inv_last_kernel<<<dim3(16,64), 256>>>(len);   // fused inv st4 + |.| + log1p -> g_spec
    apool_kernel<<<64, 256>>>(len);
    freqlin_kernel<<<64, 128>>>(fw, fb);

    head_kernel<<<64, 128>>>(hw0, hb0, hw1, hb1, out);
}

// round 16
// speedup vs baseline: 15.1199x; 1.0450x over previous
#include <cuda_runtime.h>
#include <cuda_fp16.h>
#include <cstdint>
#include <cstddef>

#define PI_F 3.14159265358979323846f
#define FFT_M 32768

// ---- static scratch ----
// position-major fp16 activations: x[b][row = 8+t (8 pad rows each end)][channel halves]
__device__ uint4  g_x1[4202496];     // conv1 out: [64][8208 rows][64 halves]  (8 uint4/row)
__device__ uint4  g_x2[4210688];     // conv2 out: [64][4112 rows][128 halves] (16 uint4/row)
__device__ float  g_tpart[64u*256u*32u];
__device__ float2 g_fftA[128u*32768u];
__device__ float2 g_fftB[128u*32768u];
__device__ float2 g_tw[32768];
__device__ float  g_spec[64u*8448u];
__device__ float  g_spectrum[64u*256u];
__device__ float  g_timevec[64u*256u];
__device__ float  g_freqvec[64u*128u];
// prepped fp16 weights: [mt][ch16][m=128][88 padded cols, 80 used], k = j*16 + c
__device__ __half g_wA2[4u*128u*88u];
__device__ __half g_wA3[16u*128u*88u];

// ---- helpers ----
__device__ __forceinline__ uint32_t smem_u32(const void* p) {
    uint32_t a; asm("{ .reg .u64 t; cvta.to.shared.u64 t, %1; cvt.u32.u64 %0, t; }" : "=r"(a) : "l"(p));
    return a;
}
__device__ __forceinline__ void mma16816(float* c, const uint32_t* a, uint32_t b0, uint32_t b1) {
    asm volatile("mma.sync.aligned.m16n8k16.row.col.f32.f16.f16.f32 "
        "{%0,%1,%2,%3}, {%4,%5,%6,%7}, {%8,%9}, {%0,%1,%2,%3};"
        : "+f"(c[0]), "+f"(c[1]), "+f"(c[2]), "+f"(c[3])
        : "r"(a[0]), "r"(a[1]), "r"(a[2]), "r"(a[3]), "r"(b0), "r"(b1));
}
__device__ __forceinline__ void ldm4(uint32_t* a, uint32_t addr) {
    asm volatile("ldmatrix.sync.aligned.m8n8.x4.shared.b16 {%0,%1,%2,%3}, [%4];"
        : "=r"(a[0]), "=r"(a[1]), "=r"(a[2]), "=r"(a[3]) : "r"(addr));
}
__device__ __forceinline__ float2 cmul(float2 a, float2 b) {
    return make_float2(a.x*b.x - a.y*b.y, a.x*b.y + a.y*b.x);
}
#define CP_ASYNC16(dst, src) asm volatile("cp.async.cg.shared.global [%0], [%1], 16;" :: "r"(dst), "l"(src))
#define CP_COMMIT() asm volatile("cp.async.commit_group;")
#define CP_WAIT0()  asm volatile("cp.async.wait_group 0;" ::: "memory")

#define A_CHUNK_B 22528
#define SB_OFF    45056

// ---- weight prep: fp32 [COUT][CIN][5] -> [mt][ch16][m][88] fp16, k = j*16 + c ----
template<int CIN, int MT>
__global__ void prep_w_kernel(const float* __restrict__ w, __half* __restrict__ dst)
{
    const int NCH = CIN / 16;
    int total = MT * NCH * 128 * 80;
    int idx = blockIdx.x * 256 + threadIdx.x;
    if (idx >= total) return;
    int kl = idx % 80;
    int m  = (idx / 80) % 128;
    int ch = (idx / (80 * 128)) % NCH;
    int mt = idx / (80 * 128 * NCH);
    int j = kl >> 4, c = kl & 15;
    float wv = w[(((size_t)(mt * 128 + m)) * CIN + ch * 16 + c) * 5 + j];
    dst[((size_t)(mt * NCH + ch) * 128 + m) * 88 + kl] = __float2half_rn(wv);
}

// ---- conv blocks 2/3: fp16 mma, position-major B staged ONCE, ldmatrix B fragments ----
// CTA: 256 thr (8 warps 2Mx4N). Tile M=128 x N=128 conv positions (->64 pooled). 2 CTA/SM.
template<int CIN, int COUT, int LIN, int WHICH>
__global__ void __launch_bounds__(256, 2)
convmma_kernel(const float* __restrict__ cb, const float* __restrict__ g,
               const float* __restrict__ be, const float* __restrict__ bm,
               const float* __restrict__ bv, const int* __restrict__ lengths)
{
    const int NCH    = CIN / 16;
    const int GROWH  = WHICH ? 128 : 64;       // input halves per position row
    const int INROWS = WHICH ? 4112 : 8208;
    const int SROWH  = WHICH ? 136 : 72;       // smem B row halves (pad +8)
    const int SROWB  = SROWH * 2;
    const int NPT    = LIN / 128;
    const __half* inh = WHICH ? (const __half*)g_x2 : (const __half*)g_x1;
    const __half* wA  = WHICH ? g_wA3 : g_wA2;

    extern __shared__ __align__(16) char smem[];
    uint32_t sbase = smem_u32(smem);
    int tid = threadIdx.x, wid = tid >> 5, lane = tid & 31;
    int pt = blockIdx.x, mt = blockIdx.y, b = blockIdx.z;
    int warp_m = wid & 1, warp_n = wid >> 1;
    int lrow = lane >> 2;
    int tb = pt * 128 - 2;

    uint32_t aoff[4];
    #pragma unroll
    for (int m2 = 0; m2 < 4; m2++)
        aoff[m2] = (uint32_t)(((warp_m * 64 + m2 * 16 + (lane & 7) + ((lane >> 3) & 1) * 8) * 88
                              + (lane >> 4) * 8) * 2);
    // B ldmatrix lane address base: tiles (nb, kh): nb=(lane>>4), kh=(lane>>3)&1, row-in-tile=lane&7
    uint32_t bbase = (uint32_t)((warp_n * 32 + (lane >> 4) * 8 + (lane & 7)) * SROWB
                               + ((lane >> 3) & 1) * 16);

    float acc[4][4][4];
    #pragma unroll
    for (int i = 0; i < 4; i++)
        #pragma unroll
        for (int n = 0; n < 4; n++)
            #pragma unroll
            for (int q = 0; q < 4; q++) acc[i][n][q] = 0.f;

    #define STAGE_A(CH) do {                                                             \
        const uint4* _as = (const uint4*)(wA + (size_t)(mt * NCH + (CH)) * 128 * 88);    \
        uint32_t _ad = sbase + (((CH) & 1) ? (uint32_t)A_CHUNK_B : 0u);                  \
        for (int _i = tid; _i < 1408; _i += 256) CP_ASYNC16(_ad + _i * 16, _as + _i);    \
    } while (0)

    // stage full B tile once: 136 rows x GROWH halves (global rows 16B-multiples)
    {
        const int OPR = GROWH / 8;             // 16B ops per row
        for (int i = tid; i < 136 * OPR; i += 256) {
            int row = i / OPR, op = i - row * OPR;
            const __half* gsrc = inh + ((size_t)b * INROWS + 8 + tb + row) * GROWH + op * 8;
            uint32_t d = sbase + (uint32_t)SB_OFF + row * SROWB + op * 16;
            CP_ASYNC16(d, gsrc);
        }
    }
    STAGE_A(0); CP_COMMIT();
    CP_WAIT0();
    __syncthreads();

    for (int ch = 0; ch < NCH; ch++) {
        int cur = ch & 1;
        if (ch + 1 < NCH) { STAGE_A(ch + 1); CP_COMMIT(); }
        {
            uint32_t Aaddr = sbase + (cur ? (uint32_t)A_CHUNK_B : 0u);
            uint32_t Baddr = sbase + (uint32_t)SB_OFF + bbase + ch * 32;
            #pragma unroll
            for (int ks = 0; ks < 5; ks++) {
                uint32_t afr[4][4];
                #pragma unroll
                for (int m2 = 0; m2 < 4; m2++) ldm4(afr[m2], Aaddr + aoff[m2] + ks * 32);
                #pragma unroll
                for (int ntp = 0; ntp < 2; ntp++) {
                    uint32_t bb[4];
                    ldm4(bb, Baddr + (ks + ntp * 16) * SROWB);
                    #pragma unroll
                    for (int m2 = 0; m2 < 4; m2++) {
                        mma16816(acc[m2][2*ntp],     afr[m2], bb[0], bb[1]);
                        mma16816(acc[m2][2*ntp + 1], afr[m2], bb[2], bb[3]);
                    }
                }
            }
        }
        if (ch + 1 < NCH) CP_WAIT0();
        __syncthreads();
    }
    #undef STAGE_A

    int pcol = warp_n * 16 + (lane & 3);
    if (WHICH == 0) {
        // BN+relu+maxpool2 -> smem transpose -> coalesced position-major rows of g_x2
        __half* sOut = (__half*)(smem + SB_OFF);   // [64 pos][136 halves stride]
        #pragma unroll
        for (int m2 = 0; m2 < 4; m2++) {
            #pragma unroll
            for (int h = 0; h < 2; h++) {
                int mg = warp_m * 64 + m2 * 16 + h * 8 + lrow;   // mt==0 for conv2
                float scv = g[mg] * rsqrtf(bv[mg] + 1e-5f);
                float shv = be[mg] - bm[mg] * scv + cb[mg] * scv;
                #pragma unroll
                for (int nt = 0; nt < 4; nt++) {
                    float v0 = acc[m2][nt][2 * h]     * scv + shv;
                    float v1 = acc[m2][nt][2 * h + 1] * scv + shv;
                    float r = fmaxf(fmaxf(v0, v1), 0.f);
                    sOut[(pcol + nt * 4) * 136 + mg] = __float2half_rn(r);
                }
            }
        }
        __syncthreads();
        uint4* x2u = (uint4*)g_x2;
        const uint4* s4 = (const uint4*)(smem + SB_OFF);
        for (int i = tid; i < 1024; i += 256) {
            int row = i >> 4, u = i & 15;
            x2u[((size_t)b * 4112 + 8 + pt * 64 + row) * 16 + u] = s4[row * 17 + u];
        }
        if (pt == 0) {
            for (int i = tid; i < 256; i += 256) {
                int row = (i >> 4) < 8 ? (i >> 4) : 4096 + (i >> 4);  // rows 0..7, 4104..4111
                x2u[((size_t)b * 4112 + row) * 16 + (i & 15)] = make_uint4(0,0,0,0);
            }
        }
    } else {
        // BN+relu+maxpool2 + masked time-pool partial sum
        int plen = lengths[b] >> 3;
        float* tbuf = (float*)smem;
        #pragma unroll
        for (int m2 = 0; m2 < 4; m2++) {
            #pragma unroll
            for (int h = 0; h < 2; h++) {
                int c_loc = warp_m * 64 + m2 * 16 + h * 8 + lrow;
                int mg = mt * 128 + c_loc;
                float scv = g[mg] * rsqrtf(bv[mg] + 1e-5f);
                float shv = be[mg] - bm[mg] * scv + cb[mg] * scv;
                float s = 0.f;
                #pragma unroll
                for (int nt = 0; nt < 4; nt++) {
                    float v0 = acc[m2][nt][2 * h]     * scv + shv;
                    float v1 = acc[m2][nt][2 * h + 1] * scv + shv;
                    float r = fmaxf(fmaxf(v0, v1), 0.f);
                    int P = pt * 64 + pcol + nt * 4;
                    if (P < plen) s += r;
                }
                s += __shfl_xor_sync(0xffffffffu, s, 1);
                s += __shfl_xor_sync(0xffffffffu, s, 2);
                if ((lane & 3) == 0) tbuf[warp_n * 128 + c_loc] = s;
            }
        }
        __syncthreads();
        if (tid < 128) {
            float s = tbuf[tid] + tbuf[128 + tid] + tbuf[256 + tid] + tbuf[384 + tid];
            g_tpart[((size_t)b * 256 + mt * 128 + tid) * 32 + pt] = s;
        }
    }
}

__global__ void timered_kernel(const int* __restrict__ lengths)
{
    int idx = blockIdx.x * 256 + threadIdx.x;
    int b = idx >> 8;
    const float* p = g_tpart + (size_t)idx * 32;
    float s = 0.f;
    #pragma unroll
    for (int i = 0; i < 32; i++) s += p[i];
    g_timevec[idx] = s / (float)(lengths[b] >> 3);
}

// =============== conv1: 1->64, k=7, +BN+relu+pool2, position-major fp16 out ===============
__global__ void conv1_kernel(const float* __restrict__ x, const float* __restrict__ w,
                             const float* __restrict__ cb, const float* __restrict__ g,
                             const float* __restrict__ be, const float* __restrict__ m,
                             const float* __restrict__ v)
{
    __shared__ float sx[519];
    __shared__ float swv[56];
    __shared__ float sbn[16];
    int tid = threadIdx.x;
    int pb  = blockIdx.x * 256;
    int c8  = blockIdx.y * 8;
    int b   = blockIdx.z;
    const float* xb = x + (size_t)b * 16384;
    for (int idx = tid; idx < 519; idx += 256) {
        int t = 2*pb - 3 + idx;
        sx[idx] = (t >= 0 && t < 16384) ? xb[t] : 0.f;
    }
    if (tid < 56) swv[tid] = w[c8*7 + tid];
    if (tid < 8) {
        int c = c8 + tid;
        float sc = g[c] * rsqrtf(v[c] + 1e-5f);
        sbn[tid] = sc;
        sbn[8 + tid] = be[c] - m[c]*sc + cb[c]*sc;
    }
    __syncthreads();
    float xv[8];
    #pragma unroll
    for (int j = 0; j < 8; j++) xv[j] = sx[2*tid + j];
    int P = pb + tid;
    uint32_t wv2[4];
    #pragma unroll
    for (int c2 = 0; c2 < 4; c2++) {
        float r2[2];
        #pragma unroll
        for (int u = 0; u < 2; u++) {
            int c = 2*c2 + u;
            float y0 = 0.f, y1 = 0.f;
            #pragma unroll
            for (int j = 0; j < 7; j++) {
                float wc = swv[c*7 + j];
                y0 = fmaf(wc, xv[j],   y0);
                y1 = fmaf(wc, xv[j+1], y1);
            }
            float sc = sbn[c], sh = sbn[8 + c];
            r2[u] = fmaxf(fmaxf(y0*sc + sh, y1*sc + sh), 0.f);
        }
        __half2 h2 = __halves2half2(__float2half_rn(r2[0]), __float2half_rn(r2[1]));
        wv2[c2] = *(uint32_t*)&h2;
    }
    uint4 val = make_uint4(wv2[0], wv2[1], wv2[2], wv2[3]);
    g_x1[((size_t)b * 8208 + 8 + P) * 8 + blockIdx.y] = val;
    if (blockIdx.x == 0 && blockIdx.y == 0) {
        for (int i = tid; i < 128; i += 256) {
            int row = (i >> 3) < 8 ? (i >> 3) : 8192 + (i >> 3);  // rows 0..7, 8200..8207
            g_x1[((size_t)b * 8208 + row) * 8 + (i & 7)] = make_uint4(0,0,0,0);
        }
    }
}

// =============== FFT: Bluestein, M=32768 = 8^5, radix-8 Stockham ===============
__global__ void fft_twiddle_kernel()
{
    int p = blockIdx.x*blockDim.x + threadIdx.x;
    int off = 0;
    #pragma unroll
    for (int st = 0; st < 15; st++) {
        int n = FFT_M >> st, mm = n >> 1;
        if (p < mm) {
            float sv, cv; sincosf(-2.f*PI_F*(float)p/(float)n, &sv, &cv);
            g_tw[off + p] = make_float2(cv, sv);
        }
        off += mm;
    }
}

__global__ void fft_build_kernel(const float* __restrict__ x, const int* __restrict__ lengths)
{
    int n = blockIdx.x*blockDim.x + threadIdx.x;   // 0..16383
    int i = blockIdx.y;
    int L = lengths[i];
    float2 a  = make_float2(0.f, 0.f);
    float2 bb = make_float2(0.f, 0.f);
    if (n < L) {
        unsigned r = ((unsigned)n * (unsigned)n) % (unsigned)(2*L);
        float sv, cv; sincosf(PI_F * (float)r / (float)L, &sv, &cv);
        bb = make_float2(cv, sv);
        float xv = x[(size_t)i*16384 + n];
        a = make_float2(xv*cv, -xv*sv);
    }
    size_t dbase = (size_t)i*FFT_M, cbase = (size_t)(64+i)*FFT_M;
    g_fftA[dbase + n] = a;
    g_fftA[cbase + n] = bb;
    if (n > 0) {
        g_fftA[dbase + FFT_M - n] = make_float2(0.f, 0.f);
        g_fftA[cbase + FFT_M - n] = bb;
    } else {
        g_fftA[dbase + 16384] = make_float2(0.f, 0.f);
        g_fftA[cbase + 16384] = make_float2(0.f, 0.f);
    }
}

__device__ __forceinline__ void radix8_bf(const float2* xx, float2* yy)
{
    float2 x0=xx[0],x1=xx[1],x2=xx[2],x3=xx[3],x4=xx[4],x5=xx[5],x6=xx[6],x7=xx[7];
    float2 t0 = make_float2(x0.x + x4.x, x0.y + x4.y);
    float2 t1 = make_float2(x0.x - x4.x, x0.y - x4.y);
    float2 t2 = make_float2(x2.x + x6.x, x2.y + x6.y);
    float2 t3 = make_float2(x2.y - x6.y, -(x2.x - x6.x));
    float2 E0 = make_float2(t0.x + t2.x, t0.y + t2.y);
    float2 E1 = make_float2(t1.x + t3.x, t1.y + t3.y);
    float2 E2 = make_float2(t0.x - t2.x, t0.y - t2.y);
    float2 E3 = make_float2(t1.x - t3.x, t1.y - t3.y);
    float2 u0 = make_float2(x1.x + x5.x, x1.y + x5.y);
    float2 u1 = make_float2(x1.x - x5.x, x1.y - x5.y);
    float2 u2 = make_float2(x3.x + x7.x, x3.y + x7.y);
    float2 u3 = make_float2(x3.y - x7.y, -(x3.x - x7.x));
    float2 O0 = make_float2(u0.x + u2.x, u0.y + u2.y);
    float2 O1 = make_float2(u1.x + u3.x, u1.y + u3.y);
    float2 O2 = make_float2(u0.x - u2.x, u0.y - u2.y);
    float2 O3 = make_float2(u1.x - u3.x, u1.y - u3.y);
    const float r = 0.70710678118654752f;
    float2 P1 = make_float2(r*(O1.x + O1.y), r*(O1.y - O1.x));
    float2 P2 = make_float2(O2.y, -O2.x);
    float2 P3 = make_float2(r*(O3.y - O3.x), -r*(O3.x + O3.y));
    yy[0] = make_float2(E0.x + O0.x, E0.y + O0.y);
    yy[1] = make_float2(E1.x + P1.x, E1.y + P1.y);
    yy[2] = make_float2(E2.x + P2.x, E2.y + P2.y);
    yy[3] = make_float2(E3.x + P3.x, E3.y + P3.y);
    yy[4] = make_float2(E0.x - O0.x, E0.y - O0.y);
    yy[5] = make_float2(E1.x - P1.x, E1.y - P1.y);
    yy[6] = make_float2(E2.x - P2.x, E2.y - P2.y);
    yy[7] = make_float2(E3.x - P3.x, E3.y - P3.y);
}

__device__ __forceinline__ void tw_store(float2* __restrict__ dst, size_t jb, int s,
                                         int p, int twOff, const float2* yy)
{
    float2 w1 = g_tw[twOff + p];
    float2 w2 = g_tw[twOff + 2*p];
    float2 w4 = g_tw[twOff + 4*p];
    float2 w3 = cmul(w1, w2);
    float2 w5 = cmul(w1, w4);
    float2 w6 = cmul(w2, w4);
    float2 w7 = cmul(w3, w4);
    dst[jb]       = yy[0];
    dst[jb + s]   = cmul(yy[1], w1);
    dst[jb + 2*s] = cmul(yy[2], w2);
    dst[jb + 3*s] = cmul(yy[3], w3);
    dst[jb + 4*s] = cmul(yy[4], w4);
    dst[jb + 5*s] = cmul(yy[5], w5);
    dst[jb + 6*s] = cmul(yy[6], w6);
    dst[jb + 7*s] = cmul(yy[7], w7);
}

__global__ void fft8_stage_kernel(int sel, int sShift, int twOff)
{
    const float2* __restrict__ src = sel ? g_fftB : g_fftA;
    float2* __restrict__ dst       = sel ? g_fftA : g_fftB;
    int i = blockIdx.x*blockDim.x + threadIdx.x;
    size_t base = (size_t)blockIdx.y * FFT_M;
    int p = i >> sShift;
    int s = 1 << sShift;
    float2 xx[8], yy[8];
    #pragma unroll
    for (int q = 0; q < 8; q++) xx[q] = src[base + i + q*4096];
    radix8_bf(xx, yy);
    tw_store(dst, base + i + (size_t)7*p*s, s, p, twOff, yy);
}

__global__ void fft8_inv_first_kernel()
{
    int i = blockIdx.x*blockDim.x + threadIdx.x;
    int arr = blockIdx.y;
    const float2* D = g_fftB + (size_t)arr * FFT_M;
    const float2* C = g_fftB + (size_t)(64 + arr) * FFT_M;
    float2 xx[8], yy[8];
    #pragma unroll
    for (int q = 0; q < 8; q++) {
        int n = i + q*4096;
        float2 d = D[n], c = C[n];
        xx[q] = make_float2(d.x*c.x - d.y*c.y, -(d.x*c.y + d.y*c.x));
    }
    radix8_bf(xx, yy);
    tw_store(g_fftA + (size_t)arr * FFT_M, (size_t)8*i, 1, i, 0, yy);
}

__global__ void fft8_inv_last_kernel(const int* __restrict__ lengths)
{
    int i = blockIdx.x*blockDim.x + threadIdx.x;   // 0..4095
    int arr = blockIdx.y;
    int K = lengths[arr] / 2 + 1;
    const float2* src = g_fftB + (size_t)arr * FFT_M;
    float2 xx[8], yy[8];
    #pragma unroll
    for (int q = 0; q < 8; q++) xx[q] = src[i + q*4096];
    radix8_bf(xx, yy);
    float* sp = g_spec + (size_t)arr * 8448;
    #pragma unroll
    for (int q = 0; q < 3; q++) {
        int j = i + q*4096;
        if (j < K)
            sp[j] = log1pf(sqrtf(yy[q].x*yy[q].x + yy[q].y*yy[q].y) * (1.0f/32768.0f));
    }
}

__global__ void apool_kernel(const int* __restrict__ lengths)
{
    int i = blockIdx.x, j = threadIdx.x;
    int K = lengths[i]/2 + 1;
    int s0 = (j*K) >> 8;
    int e0 = ((j+1)*K + 255) >> 8;
    const float* sp = g_spec + (size_t)i*8448;
    float s = 0.f;
    for (int t = s0; t < e0; t++) s += sp[t];
    g_spectrum[i*256 + j] = s / (float)(e0 - s0);
}

// =============== small GEMMs ===============
__global__ void freqlin_kernel(const float* __restrict__ fw, const float* __restrict__ fb)
{
    int i = blockIdx.x, h = threadIdx.x;
    __shared__ float sp[256];
    for (int f = h; f < 256; f += 128) sp[f] = g_spectrum[i*256 + f];
    __syncthreads();
    float acc = fb[h];
    const float* wr = fw + (size_t)h*256;
    for (int f = 0; f < 256; f++) acc = fmaf(sp[f], wr[f], acc);
    g_freqvec[i*128 + h] = fmaxf(acc, 0.f);
}

__global__ void head_kernel(const float* __restrict__ w0, const float* __restrict__ b0,
                            const float* __restrict__ w1, const float* __restrict__ b1,
                            float* __restrict__ out)
{
    int b = blockIdx.x, tid = threadIdx.x;
    __shared__ float fused[384];
    __shared__ float hid[128];
    for (int j = tid; j < 384; j += 128)
        fused[j] = (j < 256) ? g_timevec[b*256 + j] : g_freqvec[b*128 + (j - 256)];
    __syncthreads();
    float acc = b0[tid];
    const float* wr = w0 + (size_t)tid*384;
    for (int j = 0; j < 384; j++) acc = fmaf(fused[j], wr[j], acc);
    hid[tid] = fmaxf(acc, 0.f);
    __syncthreads();
    int wid = tid >> 5, lane = tid & 31;
    float s = 0.f;
    for (int t = lane; t < 128; t += 32) s += hid[t] * w1[wid*128 + t];
    #pragma unroll
    for (int off = 16; off; off >>= 1) s += __shfl_down_sync(0xffffffffu, s, off);
    if (lane == 0) out[b*4 + wid] = s + b1[wid];
}

// =============== launch ===============
extern "C" void kernel_launch(void* const* d_in, const int* in_sizes, int n_in,
                              void* d_out, int out_size)
{
    const float* x   = (const float*)d_in[0];
    const int*   len = (const int*)  d_in[1];
    const float *cw0 = (const float*)d_in[2],  *cb0 = (const float*)d_in[3];
    const float *g0  = (const float*)d_in[4],  *be0 = (const float*)d_in[5];
    const float *m0  = (const float*)d_in[6],  *v0  = (const float*)d_in[7];
    const float *cw1 = (const float*)d_in[8],  *cb1 = (const float*)d_in[9];
    const float *g1  = (const float*)d_in[10], *be1 = (const float*)d_in[11];
    const float *m1  = (const float*)d_in[12], *v1  = (const float*)d_in[13];
    const float *cw2 = (const float*)d_in[14], *cb2 = (const float*)d_in[15];
    const float *g2  = (const float*)d_in[16], *be2 = (const float*)d_in[17];
    const float *m2  = (const float*)d_in[18], *v2  = (const float*)d_in[19];
    const float *fw  = (const float*)d_in[20], *fb  = (const float*)d_in[21];
    const float *hw0 = (const float*)d_in[22], *hb0 = (const float*)d_in[23];
    const float *hw1 = (const float*)d_in[24], *hb1 = (const float*)d_in[25];
    float* out = (float*)d_out;

    const int SMEM2 = SB_OFF + 136 * 144;   // 64640
    const int SMEM3 = SB_OFF + 136 * 272;   // 82048
    cudaFuncSetAttribute(convmma_kernel<64,128,8192,0>, cudaFuncAttributeMaxDynamicSharedMemorySize, SMEM2);
    cudaFuncSetAttribute(convmma_kernel<128,256,4096,1>, cudaFuncAttributeMaxDynamicSharedMemorySize, SMEM3);

    __half *wa2, *wa3;
    cudaGetSymbolAddress((void**)&wa2, g_wA2);
    cudaGetSymbolAddress((void**)&wa3, g_wA3);
    prep_w_kernel<64, 1><<<(1*4*128*80  + 255)/256, 256>>>(cw1, wa2);
    prep_w_kernel<128,2><<<(2*8*128*80 + 255)/256, 256>>>(cw2, wa3);

    // time branch
    conv1_kernel<<<dim3(32,8,64), 256>>>(x, cw0, cb0, g0, be0, m0, v0);
    convmma_kernel<64,128,8192,0><<<dim3(64,1,64), 256, SMEM2>>>(cb1, g1, be1, m1, v1, len);
    convmma_kernel<128,256,4096,1><<<dim3(32,2,64), 256, SMEM3>>>(cb2, g2, be2, m2, v2, len);
    timered_kernel<<<64, 256>>>(len);

    // frequency branch
    fft_twiddle_kernel<<<64, 256>>>();
    fft_build_kernel<<<dim3(64,64), 256>>>(x, len);
    int sel = 0;
    for (int st = 0; st < 5; st++) {
        int n = FFT_M >> (3*st);
        fft8_stage_kernel<<<dim3(16,128), 256>>>(sel, 3*st, 32768 - n);
        sel ^= 1;
    }
    fft8_inv_first_kernel<<<dim3(16,64), 256>>>();
    sel = 0;
    for (int st = 1; st < 4; st++) {
        int n = FFT_M >> (3*st);
        fft8_stage_kernel<<<dim3(16,64), 256>>>(sel, 3*st, 32768 - n);
        sel ^= 1;
    }
    fft8_inv_last_kernel<<<dim3(16,64), 256>>>(len);
    apool_kernel<<<64, 256>>>(len);
    freqlin_kernel<<<64, 128>>>(fw, fb);

    head_kernel<<<64, 128>>>(hw0, hb0, hw1, hb1, out);
}

// round 17
// speedup vs baseline: 15.3090x; 1.0125x over previous
#include <cuda_runtime.h>
#include <cuda_fp16.h>
#include <cstdint>
#include <cstddef>

#define PI_F 3.14159265358979323846f
#define FFT_M 32768

// ---- static scratch ----
// position-major fp16 activations: x[b][row = 8+t (8 pad rows each end)][channel halves]
__device__ uint4  g_x1[4202496];     // conv1 out: [64][8208 rows][64 halves]
__device__ uint4  g_x2[4210688];     // conv2 out: [64][4112 rows][128 halves]
__device__ float  g_tpart[64u*256u*32u];
__device__ float2 g_fftA[128u*32768u];
__device__ float2 g_fftB[128u*32768u];
__device__ float2 g_tw[32768];
__device__ float  g_spec[64u*8448u];
__device__ float  g_spectrum[64u*256u];
__device__ float  g_timevec[64u*256u];
__device__ float  g_freqvec[64u*128u];
// prepped fp16 weights: [mt][ch16][m=128][88 padded cols, 80 used], k = j*16 + c
__device__ __half g_wA2[4u*128u*88u];
__device__ __half g_wA3[16u*128u*88u];

// ---- helpers ----
__device__ __forceinline__ uint32_t smem_u32(const void* p) {
    uint32_t a; asm("{ .reg .u64 t; cvta.to.shared.u64 t, %1; cvt.u32.u64 %0, t; }" : "=r"(a) : "l"(p));
    return a;
}
__device__ __forceinline__ void mma16816(float* c, const uint32_t* a, uint32_t b0, uint32_t b1) {
    asm volatile("mma.sync.aligned.m16n8k16.row.col.f32.f16.f16.f32 "
        "{%0,%1,%2,%3}, {%4,%5,%6,%7}, {%8,%9}, {%0,%1,%2,%3};"
        : "+f"(c[0]), "+f"(c[1]), "+f"(c[2]), "+f"(c[3])
        : "r"(a[0]), "r"(a[1]), "r"(a[2]), "r"(a[3]), "r"(b0), "r"(b1));
}
__device__ __forceinline__ void ldm4(uint32_t* a, uint32_t addr) {
    asm volatile("ldmatrix.sync.aligned.m8n8.x4.shared.b16 {%0,%1,%2,%3}, [%4];"
        : "=r"(a[0]), "=r"(a[1]), "=r"(a[2]), "=r"(a[3]) : "r"(addr));
}
__device__ __forceinline__ float2 cmul(float2 a, float2 b) {
    return make_float2(a.x*b.x - a.y*b.y, a.x*b.y + a.y*b.x);
}
#define CP_ASYNC16(dst, src) asm volatile("cp.async.cg.shared.global [%0], [%1], 16;" :: "r"(dst), "l"(src))
#define CP_COMMIT() asm volatile("cp.async.commit_group;")
#define CP_WAIT0()  asm volatile("cp.async.wait_group 0;" ::: "memory")

#define A_CHUNK_B 22528
#define SB_OFF3   45056          // conv3: B offset after 2 A buffers

// ---- weight prep: fp32 [COUT][CIN][5] -> [mt][ch16][m][88] fp16, k = j*16 + c ----
template<int CIN, int MT>
__global__ void prep_w_kernel(const float* __restrict__ w, __half* __restrict__ dst)
{
    const int NCH = CIN / 16;
    int total = MT * NCH * 128 * 80;
    int idx = blockIdx.x * 256 + threadIdx.x;
    if (idx >= total) return;
    int kl = idx % 80;
    int m  = (idx / 80) % 128;
    int ch = (idx / (80 * 128)) % NCH;
    int mt = idx / (80 * 128 * NCH);
    int j = kl >> 4, c = kl & 15;
    float wv = w[(((size_t)(mt * 128 + m)) * CIN + ch * 16 + c) * 5 + j];
    dst[((size_t)(mt * NCH + ch) * 128 + m) * 88 + kl] = __float2half_rn(wv);
}

// ================= conv2: persistent-A (all 4 chunks), 2 position tiles per CTA =================
// smem: A @0 (90112 B, 4 chunks), B @90112 (136 rows x 144 B = 19584) -> 109696 B. 2 CTA/SM.
__global__ void __launch_bounds__(256, 2)
conv2mma_kernel(const float* __restrict__ cb, const float* __restrict__ g,
                const float* __restrict__ be, const float* __restrict__ bm,
                const float* __restrict__ bv)
{
    const int SROWB = 144;                 // B row bytes (72 halves)
    extern __shared__ __align__(16) char smem[];
    uint32_t sbase = smem_u32(smem);
    int tid = threadIdx.x, wid = tid >> 5, lane = tid & 31;
    int bxp = blockIdx.x, b = blockIdx.z;
    int warp_m = wid & 1, warp_n = wid >> 1;
    int lrow = lane >> 2;

    uint32_t aoff[4];
    #pragma unroll
    for (int m2 = 0; m2 < 4; m2++)
        aoff[m2] = (uint32_t)(((warp_m * 64 + m2 * 16 + (lane & 7) + ((lane >> 3) & 1) * 8) * 88
                              + (lane >> 4) * 8) * 2);
    uint32_t bbase = (uint32_t)((warp_n * 32 + (lane >> 4) * 8 + (lane & 7)) * SROWB
                               + ((lane >> 3) & 1) * 16);

    // stage ALL A chunks once (contiguous 90112 B)
    {
        const uint4* as = (const uint4*)g_wA2;
        for (int i = tid; i < 5632; i += 256) CP_ASYNC16(sbase + i * 16, as + i);
        CP_COMMIT();
    }

    #pragma unroll 1
    for (int t = 0; t < 2; t++) {
        int pt = bxp * 2 + t;
        int tb = pt * 128 - 2;
        // stage B tile (136 rows x 64 halves)
        {
            const __half* inh = (const __half*)g_x1;
            for (int i = tid; i < 136 * 8; i += 256) {
                int row = i >> 3, op = i & 7;
                const __half* gsrc = inh + ((size_t)b * 8208 + 8 + tb + row) * 64 + op * 8;
                CP_ASYNC16(sbase + 90112u + row * SROWB + op * 16, gsrc);
            }
            CP_COMMIT(); CP_WAIT0();
        }
        __syncthreads();

        float acc[4][4][4];
        #pragma unroll
        for (int i = 0; i < 4; i++)
            #pragma unroll
            for (int n = 0; n < 4; n++)
                #pragma unroll
                for (int q = 0; q < 4; q++) acc[i][n][q] = 0.f;

        // sync-free mainloop: 4 chunks x 5 ks, A and B both persistent
        #pragma unroll
        for (int ch = 0; ch < 4; ch++) {
            uint32_t Aaddr = sbase + ch * (uint32_t)A_CHUNK_B;
            uint32_t Baddr = sbase + 90112u + bbase + ch * 32;
            #pragma unroll
            for (int ks = 0; ks < 5; ks++) {
                uint32_t afr[4][4];
                #pragma unroll
                for (int m2 = 0; m2 < 4; m2++) ldm4(afr[m2], Aaddr + aoff[m2] + ks * 32);
                #pragma unroll
                for (int ntp = 0; ntp < 2; ntp++) {
                    uint32_t bb[4];
                    ldm4(bb, Baddr + (ks + ntp * 16) * SROWB);
                    #pragma unroll
                    for (int m2 = 0; m2 < 4; m2++) {
                        mma16816(acc[m2][2*ntp],     afr[m2], bb[0], bb[1]);
                        mma16816(acc[m2][2*ntp + 1], afr[m2], bb[2], bb[3]);
                    }
                }
            }
        }
        __syncthreads();                    // all B reads done before reuse as transpose buffer

        // epilogue: BN+relu+maxpool2 -> smem transpose -> coalesced rows of g_x2
        int pcol = warp_n * 16 + (lane & 3);
        __half* sOut = (__half*)(smem + 90112);   // [64 pos][136 halves stride]
        #pragma unroll
        for (int m2 = 0; m2 < 4; m2++) {
            #pragma unroll
            for (int h = 0; h < 2; h++) {
                int mg = warp_m * 64 + m2 * 16 + h * 8 + lrow;
                float scv = g[mg] * rsqrtf(bv[mg] + 1e-5f);
                float shv = be[mg] - bm[mg] * scv + cb[mg] * scv;
                #pragma unroll
                for (int nt = 0; nt < 4; nt++) {
                    float v0 = acc[m2][nt][2 * h]     * scv + shv;
                    float v1 = acc[m2][nt][2 * h + 1] * scv + shv;
                    float r = fmaxf(fmaxf(v0, v1), 0.f);
                    sOut[(pcol + nt * 4) * 136 + mg] = __float2half_rn(r);
                }
            }
        }
        __syncthreads();
        uint4* x2u = (uint4*)g_x2;
        const uint4* s4 = (const uint4*)(smem + 90112);
        for (int i = tid; i < 1024; i += 256) {
            int row = i >> 4, u = i & 15;
            x2u[((size_t)b * 4112 + 8 + pt * 64 + row) * 16 + u] = s4[row * 17 + u];
        }
        __syncthreads();                    // transpose reads done before next tile's B staging
    }

    // pad rows of g_x2
    if (bxp == 0) {
        uint4* x2u = (uint4*)g_x2;
        for (int i = tid; i < 256; i += 256) {
            int row = (i >> 4) < 8 ? (i >> 4) : 4096 + (i >> 4);
            x2u[((size_t)b * 4112 + row) * 16 + (i & 15)] = make_uint4(0,0,0,0);
        }
    }
}

// ================= conv3 (unchanged structure): double-buffered A, B staged once =================
__global__ void __launch_bounds__(256, 2)
conv3mma_kernel(const float* __restrict__ cb, const float* __restrict__ g,
                const float* __restrict__ be, const float* __restrict__ bm,
                const float* __restrict__ bv, const int* __restrict__ lengths)
{
    const int NCH = 8, SROWB = 272;
    const __half* wA = g_wA3;
    extern __shared__ __align__(16) char smem[];
    uint32_t sbase = smem_u32(smem);
    int tid = threadIdx.x, wid = tid >> 5, lane = tid & 31;
    int pt = blockIdx.x, mt = blockIdx.y, b = blockIdx.z;
    int warp_m = wid & 1, warp_n = wid >> 1;
    int lrow = lane >> 2;
    int tb = pt * 128 - 2;

    uint32_t aoff[4];
    #pragma unroll
    for (int m2 = 0; m2 < 4; m2++)
        aoff[m2] = (uint32_t)(((warp_m * 64 + m2 * 16 + (lane & 7) + ((lane >> 3) & 1) * 8) * 88
                              + (lane >> 4) * 8) * 2);
    uint32_t bbase = (uint32_t)((warp_n * 32 + (lane >> 4) * 8 + (lane & 7)) * SROWB
                               + ((lane >> 3) & 1) * 16);

    float acc[4][4][4];
    #pragma unroll
    for (int i = 0; i < 4; i++)
        #pragma unroll
        for (int n = 0; n < 4; n++)
            #pragma unroll
            for (int q = 0; q < 4; q++) acc[i][n][q] = 0.f;

    #define STAGE_A(CH) do {                                                             \
        const uint4* _as = (const uint4*)(wA + (size_t)(mt * NCH + (CH)) * 128 * 88);    \
        uint32_t _ad = sbase + (((CH) & 1) ? (uint32_t)A_CHUNK_B : 0u);                  \
        for (int _i = tid; _i < 1408; _i += 256) CP_ASYNC16(_ad + _i * 16, _as + _i);    \
    } while (0)

    {
        const __half* inh = (const __half*)g_x2;
        for (int i = tid; i < 136 * 16; i += 256) {
            int row = i >> 4, op = i & 15;
            const __half* gsrc = inh + ((size_t)b * 4112 + 8 + tb + row) * 128 + op * 8;
            CP_ASYNC16(sbase + (uint32_t)SB_OFF3 + row * SROWB + op * 16, gsrc);
        }
    }
    STAGE_A(0); CP_COMMIT();
    CP_WAIT0();
    __syncthreads();

    for (int ch = 0; ch < NCH; ch++) {
        int cur = ch & 1;
        if (ch + 1 < NCH) { STAGE_A(ch + 1); CP_COMMIT(); }
        {
            uint32_t Aaddr = sbase + (cur ? (uint32_t)A_CHUNK_B : 0u);
            uint32_t Baddr = sbase + (uint32_t)SB_OFF3 + bbase + ch * 32;
            #pragma unroll
            for (int ks = 0; ks < 5; ks++) {
                uint32_t afr[4][4];
                #pragma unroll
                for (int m2 = 0; m2 < 4; m2++) ldm4(afr[m2], Aaddr + aoff[m2] + ks * 32);
                #pragma unroll
                for (int ntp = 0; ntp < 2; ntp++) {
                    uint32_t bb[4];
                    ldm4(bb, Baddr + (ks + ntp * 16) * SROWB);
                    #pragma unroll
                    for (int m2 = 0; m2 < 4; m2++) {
                        mma16816(acc[m2][2*ntp],     afr[m2], bb[0], bb[1]);
                        mma16816(acc[m2][2*ntp + 1], afr[m2], bb[2], bb[3]);
                    }
                }
            }
        }
        if (ch + 1 < NCH) CP_WAIT0();
        __syncthreads();
    }
    #undef STAGE_A

    // BN+relu+maxpool2 + masked time-pool partial sum
    int pcol = warp_n * 16 + (lane & 3);
    int plen = lengths[b] >> 3;
    float* tbuf = (float*)smem;
    #pragma unroll
    for (int m2 = 0; m2 < 4; m2++) {
        #pragma unroll
        for (int h = 0; h < 2; h++) {
            int c_loc = warp_m * 64 + m2 * 16 + h * 8 + lrow;
            int mg = mt * 128 + c_loc;
            float scv = g[mg] * rsqrtf(bv[mg] + 1e-5f);
            float shv = be[mg] - bm[mg] * scv + cb[mg] * scv;
            float s = 0.f;
            #pragma unroll
            for (int nt = 0; nt < 4; nt++) {
                float v0 = acc[m2][nt][2 * h]     * scv + shv;
                float v1 = acc[m2][nt][2 * h + 1] * scv + shv;
                float r = fmaxf(fmaxf(v0, v1), 0.f);
                int P = pt * 64 + pcol + nt * 4;
                if (P < plen) s += r;
            }
            s += __shfl_xor_sync(0xffffffffu, s, 1);
            s += __shfl_xor_sync(0xffffffffu, s, 2);
            if ((lane & 3) == 0) tbuf[warp_n * 128 + c_loc] = s;
        }
    }
    __syncthreads();
    if (tid < 128) {
        float s = tbuf[tid] + tbuf[128 + tid] + tbuf[256 + tid] + tbuf[384 + tid];
        g_tpart[((size_t)b * 256 + mt * 128 + tid) * 32 + pt] = s;
    }
}

__global__ void timered_kernel(const int* __restrict__ lengths)
{
    int idx = blockIdx.x * 256 + threadIdx.x;
    int b = idx >> 8;
    const float* p = g_tpart + (size_t)idx * 32;
    float s = 0.f;
    #pragma unroll
    for (int i = 0; i < 32; i++) s += p[i];
    g_timevec[idx] = s / (float)(lengths[b] >> 3);
}

// =============== conv1: 1->64, k=7, +BN+relu+pool2, position-major fp16 out ===============
__global__ void conv1_kernel(const float* __restrict__ x, const float* __restrict__ w,
                             const float* __restrict__ cb, const float* __restrict__ g,
                             const float* __restrict__ be, const float* __restrict__ m,
                             const float* __restrict__ v)
{
    __shared__ float sx[519];
    __shared__ float swv[56];
    __shared__ float sbn[16];
    int tid = threadIdx.x;
    int pb  = blockIdx.x * 256;
    int c8  = blockIdx.y * 8;
    int b   = blockIdx.z;
    const float* xb = x + (size_t)b * 16384;
    for (int idx = tid; idx < 519; idx += 256) {
        int t = 2*pb - 3 + idx;
        sx[idx] = (t >= 0 && t < 16384) ? xb[t] : 0.f;
    }
    if (tid < 56) swv[tid] = w[c8*7 + tid];
    if (tid < 8) {
        int c = c8 + tid;
        float sc = g[c] * rsqrtf(v[c] + 1e-5f);
        sbn[tid] = sc;
        sbn[8 + tid] = be[c] - m[c]*sc + cb[c]*sc;
    }
    __syncthreads();
    float xv[8];
    #pragma unroll
    for (int j = 0; j < 8; j++) xv[j] = sx[2*tid + j];
    int P = pb + tid;
    uint32_t wv2[4];
    #pragma unroll
    for (int c2 = 0; c2 < 4; c2++) {
        float r2[2];
        #pragma unroll
        for (int u = 0; u < 2; u++) {
            int c = 2*c2 + u;
            float y0 = 0.f, y1 = 0.f;
            #pragma unroll
            for (int j = 0; j < 7; j++) {
                float wc = swv[c*7 + j];
                y0 = fmaf(wc, xv[j],   y0);
                y1 = fmaf(wc, xv[j+1], y1);
            }
            float sc = sbn[c], sh = sbn[8 + c];
            r2[u] = fmaxf(fmaxf(y0*sc + sh, y1*sc + sh), 0.f);
        }
        __half2 h2 = __halves2half2(__float2half_rn(r2[0]), __float2half_rn(r2[1]));
        wv2[c2] = *(uint32_t*)&h2;
    }
    g_x1[((size_t)b * 8208 + 8 + P) * 8 + blockIdx.y] = make_uint4(wv2[0], wv2[1], wv2[2], wv2[3]);
    if (blockIdx.x == 0 && blockIdx.y == 0) {
        for (int i = tid; i < 128; i += 256) {
            int row = (i >> 3) < 8 ? (i >> 3) : 8192 + (i >> 3);
            g_x1[((size_t)b * 8208 + row) * 8 + (i & 7)] = make_uint4(0,0,0,0);
        }
    }
}

// =============== FFT: Bluestein, M=32768 = 8^5, fused radix-64 Stockham ===============
__global__ void fft_twiddle_kernel()
{
    int p = blockIdx.x*blockDim.x + threadIdx.x;
    int off = 0;
    #pragma unroll
    for (int st = 0; st < 15; st++) {
        int n = FFT_M >> st, mm = n >> 1;
        if (p < mm) {
            float sv, cv; sincosf(-2.f*PI_F*(float)p/(float)n, &sv, &cv);
            g_tw[off + p] = make_float2(cv, sv);
        }
        off += mm;
    }
}

__global__ void fft_build_kernel(const float* __restrict__ x, const int* __restrict__ lengths)
{
    int n = blockIdx.x*blockDim.x + threadIdx.x;   // 0..16383
    int i = blockIdx.y;
    int L = lengths[i];
    float2 a  = make_float2(0.f, 0.f);
    float2 bb = make_float2(0.f, 0.f);
    if (n < L) {
        unsigned r = ((unsigned)n * (unsigned)n) % (unsigned)(2*L);
        float sv, cv; sincosf(PI_F * (float)r / (float)L, &sv, &cv);
        bb = make_float2(cv, sv);
        float xv = x[(size_t)i*16384 + n];
        a = make_float2(xv*cv, -xv*sv);
    }
    size_t dbase = (size_t)i*FFT_M, cbase = (size_t)(64+i)*FFT_M;
    g_fftA[dbase + n] = a;
    g_fftA[cbase + n] = bb;
    if (n > 0) {
        g_fftA[dbase + FFT_M - n] = make_float2(0.f, 0.f);
        g_fftA[cbase + FFT_M - n] = bb;
    } else {
        g_fftA[dbase + 16384] = make_float2(0.f, 0.f);
        g_fftA[cbase + 16384] = make_float2(0.f, 0.f);
    }
}

__device__ __forceinline__ void radix8_bf(const float2* xx, float2* yy)
{
    float2 x0=xx[0],x1=xx[1],x2=xx[2],x3=xx[3],x4=xx[4],x5=xx[5],x6=xx[6],x7=xx[7];
    float2 t0 = make_float2(x0.x + x4.x, x0.y + x4.y);
    float2 t1 = make_float2(x0.x - x4.x, x0.y - x4.y);
    float2 t2 = make_float2(x2.x + x6.x, x2.y + x6.y);
    float2 t3 = make_float2(x2.y - x6.y, -(x2.x - x6.x));
    float2 E0 = make_float2(t0.x + t2.x, t0.y + t2.y);
    float2 E1 = make_float2(t1.x + t3.x, t1.y + t3.y);
    float2 E2 = make_float2(t0.x - t2.x, t0.y - t2.y);
    float2 E3 = make_float2(t1.x - t3.x, t1.y - t3.y);
    float2 u0 = make_float2(x1.x + x5.x, x1.y + x5.y);
    float2 u1 = make_float2(x1.x - x5.x, x1.y - x5.y);
    float2 u2 = make_float2(x3.x + x7.x, x3.y + x7.y);
    float2 u3 = make_float2(x3.y - x7.y, -(x3.x - x7.x));
    float2 O0 = make_float2(u0.x + u2.x, u0.y + u2.y);
    float2 O1 = make_float2(u1.x + u3.x, u1.y + u3.y);
    float2 O2 = make_float2(u0.x - u2.x, u0.y - u2.y);
    float2 O3 = make_float2(u1.x - u3.x, u1.y - u3.y);
    const float r = 0.70710678118654752f;
    float2 P1 = make_float2(r*(O1.x + O1.y), r*(O1.y - O1.x));
    float2 P2 = make_float2(O2.y, -O2.x);
    float2 P3 = make_float2(r*(O3.y - O3.x), -r*(O3.x + O3.y));
    yy[0] = make_float2(E0.x + O0.x, E0.y + O0.y);
    yy[1] = make_float2(E1.x + P1.x, E1.y + P1.y);
    yy[2] = make_float2(E2.x + P2.x, E2.y + P2.y);
    yy[3] = make_float2(E3.x + P3.x, E3.y + P3.y);
    yy[4] = make_float2(E0.x - O0.x, E0.y - O0.y);
    yy[5] = make_float2(E1.x - P1.x, E1.y - P1.y);
    yy[6] = make_float2(E2.x - P2.x, E2.y - P2.y);
    yy[7] = make_float2(E3.x - P3.x, E3.y - P3.y);
}

__device__ __forceinline__ void tw_store(float2* __restrict__ dst, size_t jb, int s,
                                         int p, int twOff, const float2* yy)
{
    float2 w1 = g_tw[twOff + p];
    float2 w2 = g_tw[twOff + 2*p];
    float2 w4 = g_tw[twOff + 4*p];
    float2 w3 = cmul(w1, w2);
    float2 w5 = cmul(w1, w4);
    float2 w6 = cmul(w2, w4);
    float2 w7 = cmul(w3, w4);
    dst[jb]       = yy[0];
    dst[jb + s]   = cmul(yy[1], w1);
    dst[jb + 2*s] = cmul(yy[2], w2);
    dst[jb + 3*s] = cmul(yy[3], w3);
    dst[jb + 4*s] = cmul(yy[4], w4);
    dst[jb + 5*s] = cmul(yy[5], w5);
    dst[jb + 6*s] = cmul(yy[6], w6);
    dst[jb + 7*s] = cmul(yy[7], w7);
}

// second half of a fused radix-64: exchange + radix8 + twiddled store
__device__ __forceinline__ void fft64_tail(float2* __restrict__ dst, size_t base,
                                           float2* ex, int grp, int m, int i0, int shA,
                                           const float2* yyin, int pA, int twA)
{
    // twiddle stage A results and write exchange slots [grp][q*9... padded 73][m]
    {
        float2 w1 = g_tw[twA + pA];
        float2 w2 = g_tw[twA + 2*pA];
        float2 w4 = g_tw[twA + 4*pA];
        float2 w3 = cmul(w1, w2);
        float2 w5 = cmul(w1, w4);
        float2 w6 = cmul(w2, w4);
        float2 w7 = cmul(w3, w4);
        float2* slot = ex + grp * 73 + m;
        slot[0]  = yyin[0];
        slot[9]  = cmul(yyin[1], w1);
        slot[18] = cmul(yyin[2], w2);
        slot[27] = cmul(yyin[3], w3);
        slot[36] = cmul(yyin[4], w4);
        slot[45] = cmul(yyin[5], w5);
        slot[54] = cmul(yyin[6], w6);
        slot[63] = cmul(yyin[7], w7);
    }
    __syncwarp();
    float2 xx[8], yy[8];
    const float2* rb = ex + grp * 73 + m * 9;
    #pragma unroll
    for (int q = 0; q < 8; q++) xx[q] = rb[q];
    radix8_bf(xx, yy);
    int sB = 1 << (shA + 3);
    int twB = FFT_M - (FFT_M >> (shA + 3));
    int p0 = i0 >> shA;
    int rA = i0 & ((1 << shA) - 1);
    int iB = (p0 << (shA + 3)) + rA + (m << shA);
    tw_store(dst, base + iB + (size_t)7 * p0 * sB, sB, p0, twB, yy);
    __syncwarp();                    // exchange buffer safe for any reuse
}

// fused stages (stA, stA+1), stA in {0, 2}
__global__ void fft64_stage_kernel(int sel, int stA)
{
    __shared__ float2 ex[32 * 73];
    const float2* __restrict__ src = sel ? g_fftB : g_fftA;
    float2* __restrict__ dst       = sel ? g_fftA : g_fftB;
    int tid = threadIdx.x;
    int grp = tid >> 3, m = tid & 7;
    int i0 = blockIdx.x * 32 + grp;
    size_t base = (size_t)blockIdx.y * FFT_M;
    int shA = 3 * stA;
    int twA = FFT_M - (FFT_M >> shA == 0 ? 0 : (FFT_M >> shA));
    twA = FFT_M - (FFT_M >> shA);
    int i = i0 + (m << 9);
    int pA = i >> shA;
    float2 xx[8], yy[8];
    #pragma unroll
    for (int q = 0; q < 8; q++) xx[q] = src[base + i + (q << 12)];
    radix8_bf(xx, yy);
    fft64_tail(dst, base, ex, grp, m, i0, shA, yy, pA, twA);
}

// fused (st0, st1) with Bluestein conjugate pointwise product on load: g_fftB -> g_fftA
__global__ void fft64_pw_kernel()
{
    __shared__ float2 ex[32 * 73];
    int tid = threadIdx.x;
    int grp = tid >> 3, m = tid & 7;
    int i0 = blockIdx.x * 32 + grp;
    int arr = blockIdx.y;
    const float2* D = g_fftB + (size_t)arr * FFT_M;
    const float2* C = g_fftB + (size_t)(64 + arr) * FFT_M;
    int i = i0 + (m << 9);
    float2 xx[8], yy[8];
    #pragma unroll
    for (int q = 0; q < 8; q++) {
        int n = i + (q << 12);
        float2 d = D[n], c = C[n];
        xx[q] = make_float2(d.x*c.x - d.y*c.y, -(d.x*c.y + d.y*c.x));
    }
    radix8_bf(xx, yy);
    fft64_tail(g_fftA + (size_t)arr * FFT_M, 0, ex, grp, m, i0, 0, yy, i, 0);
}

// standalone radix-8 stage (used for st4 forward; p=0 there but general form kept)
__global__ void fft8_stage_kernel(int sel, int sShift, int twOff)
{
    const float2* __restrict__ src = sel ? g_fftB : g_fftA;
    float2* __restrict__ dst       = sel ? g_fftA : g_fftB;
    int i = blockIdx.x*blockDim.x + threadIdx.x;
    size_t base = (size_t)blockIdx.y * FFT_M;
    int p = i >> sShift;
    int s = 1 << sShift;
    float2 xx[8], yy[8];
    #pragma unroll
    for (int q = 0; q < 8; q++) xx[q] = src[base + i + q*4096];
    radix8_bf(xx, yy);
    tw_store(dst, base + i + (size_t)7*p*s, s, p, twOff, yy);
}

// inverse LAST stage (st4: p=0, twiddles=1) fused with magnitude/log1p -> g_spec
__global__ void fft8_inv_last_kernel(const int* __restrict__ lengths)
{
    int i = blockIdx.x*blockDim.x + threadIdx.x;   // 0..4095
    int arr = blockIdx.y;
    int K = lengths[arr] / 2 + 1;
    const float2* src = g_fftB + (size_t)arr * FFT_M;
    float2 xx[8], yy[8];
    #pragma unroll
    for (int q = 0; q < 8; q++) xx[q] = src[i + q*4096];
    radix8_bf(xx, yy);
    float* sp = g_spec + (size_t)arr * 8448;
    #pragma unroll
    for (int q = 0; q < 3; q++) {
        int j = i + q*4096;
        if (j < K)
            sp[j] = log1pf(sqrtf(yy[q].x*yy[q].x + yy[q].y*yy[q].y) * (1.0f/32768.0f));
    }
}

__global__ void apool_kernel(const int* __restrict__ lengths)
{
    int i = blockIdx.x, j = threadIdx.x;
    int K = lengths[i]/2 + 1;
    int s0 = (j*K) >> 8;
    int e0 = ((j+1)*K + 255) >> 8;
    const float* sp = g_spec + (size_t)i*8448;
    float s = 0.f;
    for (int t = s0; t < e0; t++) s += sp[t];
    g_spectrum[i*256 + j] = s / (float)(e0 - s0);
}

// =============== small GEMMs ===============
__global__ void freqlin_kernel(const float* __restrict__ fw, const float* __restrict__ fb)
{
    int i = blockIdx.x, h = threadIdx.x;
    __shared__ float sp[256];
    for (int f = h; f < 256; f += 128) sp[f] = g_spectrum[i*256 + f];
    __syncthreads();
    float acc = fb[h];
    const float* wr = fw + (size_t)h*256;
    for (int f = 0; f < 256; f++) acc = fmaf(sp[f], wr[f], acc);
    g_freqvec[i*128 + h] = fmaxf(acc, 0.f);
}

__global__ void head_kernel(const float* __restrict__ w0, const float* __restrict__ b0,
                            const float* __restrict__ w1, const float* __restrict__ b1,
                            float* __restrict__ out)
{
    int b = blockIdx.x, tid = threadIdx.x;
    __shared__ float fused[384];
    __shared__ float hid[128];
    for (int j = tid; j < 384; j += 128)
        fused[j] = (j < 256) ? g_timevec[b*256 + j] : g_freqvec[b*128 + (j - 256)];
    __syncthreads();
    float acc = b0[tid];
    const float* wr = w0 + (size_t)tid*384;
    for (int j = 0; j < 384; j++) acc = fmaf(fused[j], wr[j], acc);
    hid[tid] = fmaxf(acc, 0.f);
    __syncthreads();
    int wid = tid >> 5, lane = tid & 31;
    float s = 0.f;
    for (int t = lane; t < 128; t += 32) s += hid[t] * w1[wid*128 + t];
    #pragma unroll
    for (int off = 16; off; off >>= 1) s += __shfl_down_sync(0xffffffffu, s, off);
    if (lane == 0) out[b*4 + wid] = s + b1[wid];
}

// =============== launch ===============
extern "C" void kernel_launch(void* const* d_in, const int* in_sizes, int n_in,
                              void* d_out, int out_size)
{
    const float* x   = (const float*)d_in[0];
    const int*   len = (const int*)  d_in[1];
    const float *cw0 = (const float*)d_in[2],  *cb0 = (const float*)d_in[3];
    const float *g0  = (const float*)d_in[4],  *be0 = (const float*)d_in[5];
    const float *m0  = (const float*)d_in[6],  *v0  = (const float*)d_in[7];
    const float *cw1 = (const float*)d_in[8],  *cb1 = (const float*)d_in[9];
    const float *g1  = (const float*)d_in[10], *be1 = (const float*)d_in[11];
    const float *m1  = (const float*)d_in[12], *v1  = (const float*)d_in[13];
    const float *cw2 = (const float*)d_in[14], *cb2 = (const float*)d_in[15];
    const float *g2  = (const float*)d_in[16], *be2 = (const float*)d_in[17];
    const float *m2  = (const float*)d_in[18], *v2  = (const float*)d_in[19];
    const float *fw  = (const float*)d_in[20], *fb  = (const float*)d_in[21];
    const float *hw0 = (const float*)d_in[22], *hb0 = (const float*)d_in[23];
    const float *hw1 = (const float*)d_in[24], *hb1 = (const float*)d_in[25];
    float* out = (float*)d_out;

    const int SMEM2 = 90112 + 19584;        // 109696
    const int SMEM3 = SB_OFF3 + 136 * 272;  // 82048
    cudaFuncSetAttribute(conv2mma_kernel, cudaFuncAttributeMaxDynamicSharedMemorySize, SMEM2);
    cudaFuncSetAttribute(conv3mma_kernel, cudaFuncAttributeMaxDynamicSharedMemorySize, SMEM3);

    __half *wa2, *wa3;
    cudaGetSymbolAddress((void**)&wa2, g_wA2);
    cudaGetSymbolAddress((void**)&wa3, g_wA3);
    prep_w_kernel<64, 1><<<(1*4*128*80  + 255)/256, 256>>>(cw1, wa2);
    prep_w_kernel<128,2><<<(2*8*128*80 + 255)/256, 256>>>(cw2, wa3);

    // time branch
    conv1_kernel<<<dim3(32,8,64), 256>>>(x, cw0, cb0, g0, be0, m0, v0);
    conv2mma_kernel<<<dim3(32,1,64), 256, SMEM2>>>(cb1, g1, be1, m1, v1);
    conv3mma_kernel<<<dim3(32,2,64), 256, SMEM3>>>(cb2, g2, be2, m2, v2, len);
    timered_kernel<<<64, 256>>>(len);

    // frequency branch: fused radix-64 passes (3 fwd + 3 inv)
    fft_twiddle_kernel<<<64, 256>>>();
    fft_build_kernel<<<dim3(64,64), 256>>>(x, len);
    fft64_stage_kernel<<<dim3(16,128), 256>>>(0, 0);         // st0+st1: A->B
    fft64_stage_kernel<<<dim3(16,128), 256>>>(1, 2);         // st2+st3: B->A
    fft8_stage_kernel<<<dim3(16,128), 256>>>(0, 12, 32760);  // st4: A->B
    fft64_pw_kernel<<<dim3(16,64), 256>>>();                 // pointwise + st0+st1: B->A
    fft64_stage_kernel<<<dim3(16,64), 256>>>(0, 2);          // st2+st3: A->B
    fft8_inv_last_kernel<<<dim3(16,64), 256>>>(len);         // st4 + |.| + log1p -> g_spec
    apool_kernel<<<64, 256>>>(len);
    freqlin_kernel<<<64, 128>>>(fw, fb);

    head_kernel<<<64, 128>>>(hw0, hb0, hw1, hb1, out);
}